// round 7
// baseline (speedup 1.0000x reference)
#include <cuda_runtime.h>
#include <cuda_bf16.h>
#include <cstdint>
#include <math.h>

// ---------------------------------------------------------------------------
// Attention block, bf16 mma.sync pipeline.
// R7: CTA tile 128x64, warp tile 32x32, 3 CTAs/SM (occupancy experiment).
// B=16, C=512, HW=1024, 32 groups, eps=1e-6
// ---------------------------------------------------------------------------

#define B_ 16
#define C_ 512
#define HW_ 1024
#define NG_ 32

__device__ __nv_bfloat16 g_xnt[(long long)B_ * HW_ * C_];
__device__ __nv_bfloat16 g_qt [(long long)B_ * HW_ * C_];
__device__ __nv_bfloat16 g_kt [(long long)B_ * HW_ * C_];
__device__ __nv_bfloat16 g_v  [(long long)B_ * C_ * HW_];
__device__ float         g_e  [(long long)B_ * HW_ * HW_];
__device__ __nv_bfloat16 g_at [(long long)B_ * HW_ * HW_];
__device__ __nv_bfloat16 g_ot [(long long)B_ * HW_ * C_];
__device__ __nv_bfloat16 g_wq[C_ * C_], g_wk[C_ * C_], g_wv[C_ * C_], g_wp[C_ * C_];

__inline__ __device__ float warp_sum(float v) {
    #pragma unroll
    for (int o = 16; o > 0; o >>= 1) v += __shfl_xor_sync(0xffffffffu, v, o);
    return v;
}
__inline__ __device__ float warp_max(float v) {
    #pragma unroll
    for (int o = 16; o > 0; o >>= 1) v = fmaxf(v, __shfl_xor_sync(0xffffffffu, v, o));
    return v;
}
__device__ __forceinline__ uint32_t smem_u32(const void* p) {
    uint32_t a;
    asm("{ .reg .u64 t; cvta.to.shared.u64 t, %1; cvt.u32.u64 %0, t; }"
        : "=r"(a) : "l"(p));
    return a;
}

#define CPA16(dst, src) \
    asm volatile("cp.async.cg.shared.global [%0], [%1], 16;" :: "r"(dst), "l"(src))
#define CPA_COMMIT() asm volatile("cp.async.commit_group;" ::: "memory")

#define LDSM4(R0, R1, R2, R3, addr) \
    asm volatile("ldmatrix.sync.aligned.m8n8.x4.shared.b16 {%0,%1,%2,%3}, [%4];" \
                 : "=r"(R0), "=r"(R1), "=r"(R2), "=r"(R3) : "r"(addr))

__device__ __forceinline__ void mma_bf16(float c[4], const uint32_t a[4],
                                         uint32_t b0, uint32_t b1) {
    asm volatile(
        "mma.sync.aligned.m16n8k16.row.col.f32.bf16.bf16.f32 "
        "{%0,%1,%2,%3}, {%4,%5,%6,%7}, {%8,%9}, {%0,%1,%2,%3};"
        : "+f"(c[0]), "+f"(c[1]), "+f"(c[2]), "+f"(c[3])
        : "r"(a[0]), "r"(a[1]), "r"(a[2]), "r"(a[3]), "r"(b0), "r"(b1));
}

// ---------------------------------------------------------------------------
// Weight conversion fp32 -> bf16
// ---------------------------------------------------------------------------
__global__ void convert_w(const float* __restrict__ wq, const float* __restrict__ wk,
                          const float* __restrict__ wv, const float* __restrict__ wp)
{
    int i = (blockIdx.x * 256 + threadIdx.x) * 4;
    if (i >= C_ * C_) return;
    #pragma unroll
    for (int j = 0; j < 4; j++) {
        g_wq[i + j] = __float2bfloat16_rn(wq[i + j]);
        g_wk[i + j] = __float2bfloat16_rn(wk[i + j]);
        g_wv[i + j] = __float2bfloat16_rn(wv[i + j]);
        g_wp[i + j] = __float2bfloat16_rn(wp[i + j]);
    }
}

// ---------------------------------------------------------------------------
// GroupNorm + transpose: x (B,C,HW) fp32 -> xn_t (B,HW,C) bf16
// ---------------------------------------------------------------------------
__global__ void gn_t_kernel(const float* __restrict__ x,
                            const float* __restrict__ gamma,
                            const float* __restrict__ beta)
{
    const int GSZ = 16 * HW_;
    int bg = blockIdx.x;
    int b = bg >> 5, g = bg & 31;
    long long base = (long long)bg * GSZ;
    int tid = threadIdx.x;

    float s = 0.f, sq = 0.f;
    for (int e = tid * 4; e < GSZ; e += 256 * 4) {
        float4 v4 = *reinterpret_cast<const float4*>(&x[base + e]);
        s  += v4.x + v4.y + v4.z + v4.w;
        sq += v4.x * v4.x + v4.y * v4.y + v4.z * v4.z + v4.w * v4.w;
    }
    __shared__ float shs[8], shq[8];
    s = warp_sum(s); sq = warp_sum(sq);
    int wid = tid >> 5, lid = tid & 31;
    if (lid == 0) { shs[wid] = s; shq[wid] = sq; }
    __syncthreads();
    if (wid == 0) {
        float a = (lid < 8) ? shs[lid] : 0.f;
        float bb = (lid < 8) ? shq[lid] : 0.f;
        a = warp_sum(a); bb = warp_sum(bb);
        if (lid == 0) { shs[0] = a; shq[0] = bb; }
    }
    __syncthreads();
    float mean = shs[0] / (float)GSZ;
    float var  = shq[0] / (float)GSZ - mean * mean;
    float inv  = rsqrtf(var + 1e-6f);

    float ga[16], be[16];
    #pragma unroll
    for (int c = 0; c < 16; c++) {
        ga[c] = gamma[g * 16 + c] * inv;
        be[c] = beta[g * 16 + c] - mean * ga[c];
    }

    __shared__ float tile[16][256];
    for (int s0 = 0; s0 < HW_; s0 += 256) {
        __syncthreads();
        #pragma unroll
        for (int i = 0; i < 16; i++) {
            int task = tid + i * 256;
            int c = task >> 8, sl = task & 255;
            tile[c][sl] = x[base + (long long)c * HW_ + s0 + sl];
        }
        __syncthreads();
        int sp = s0 + tid;
        union { __nv_bfloat16 h[16]; uint4 u[2]; } o;
        #pragma unroll
        for (int c = 0; c < 16; c++)
            o.h[c] = __float2bfloat16_rn(tile[c][tid] * ga[c] + be[c]);
        uint4* dst = reinterpret_cast<uint4*>(
            &g_xnt[((long long)b * HW_ + sp) * C_ + g * 16]);
        dst[0] = o.u[0];
        dst[1] = o.u[1];
    }
}

// ---------------------------------------------------------------------------
// bf16 GEMM: CTA tile 128(M) x 64(N), BK=32, 8 warps (4M x 2N), warp 32x32.
// 4-stage cp.async ring, 1 sync/iter, pipelined ldmatrix, 3 CTAs/SM.
// ---------------------------------------------------------------------------
#define BK 32
#define ROWE 40                   // padded row in bf16 elems (80B)
#define STGA (128 * ROWE)         // A elems per stage
#define STGB (64 * ROWE)          // B elems per stage
#define NSTAGE 4
#define SMEM_BYTES (NSTAGE * (STGA + STGB) * 2)

__device__ __forceinline__ void fill_stage(
    uint32_t abase, uint32_t bbase,
    const __nv_bfloat16* Ap, const __nv_bfloat16* Bp,
    int m0, int n0, int ldA, int ldB, int k0, int tid)
{
    // A: 128 rows x 4 chunks = 512 tasks (2/thread)
    #pragma unroll
    for (int i = 0; i < 2; i++) {
        int task = tid + i * 256;
        int row = task >> 2, kc = task & 3;
        CPA16(abase + (row * ROWE + kc * 8) * 2,
              Ap + (long long)(m0 + row) * ldA + k0 + kc * 8);
    }
    // B: 64 rows x 4 chunks = 256 tasks (1/thread)
    {
        int row = tid >> 2, kc = tid & 3;
        CPA16(bbase + (row * ROWE + kc * 8) * 2,
              Bp + (long long)(n0 + row) * ldB + k0 + kc * 8);
    }
}

template<int BIAS_MODE, bool HAS_RES, bool OUT_BF16, bool DUAL>
__global__ __launch_bounds__(256, 3) void bf_gemm(
    const __nv_bfloat16* __restrict__ A, const __nv_bfloat16* __restrict__ Bm,
    void* __restrict__ Cv, const float* __restrict__ bias,
    const float* __restrict__ resid,
    const __nv_bfloat16* __restrict__ Bm2, const float* __restrict__ bias2,
    void* __restrict__ Cv2,
    int K, int ldA, int ldB, int N, float alpha,
    long long sA, long long sB, long long sC)
{
    extern __shared__ __nv_bfloat16 dsm[];

    int tid = threadIdx.x, wid = tid >> 5, lane = tid & 31;
    int g = lane >> 2, t = lane & 3;
    int wm = (wid & 3) * 32;          // 4 warps along M
    int wn = (wid >> 2) * 32;         // 2 warps along N
    int n0 = blockIdx.x * 64;
    int m0 = blockIdx.y * 128;
    int bz = blockIdx.z;
    if (DUAL) {
        if (bz >> 4) { Bm = Bm2; bias = bias2; Cv = Cv2; }
        bz &= 15;
    }
    const __nv_bfloat16* Ap = A  + (long long)bz * sA;
    const __nv_bfloat16* Bp = Bm + (long long)bz * sB;

    uint32_t as_base = smem_u32(dsm);
    uint32_t bs_base = as_base + NSTAGE * STGA * 2;

    int a_row = wm + (lane & 15);
    int a_koff = (lane >> 4) * 8;
    int b_row = wn + ((lane >> 4) << 3) + (lane & 7);
    int b_koff = ((lane >> 3) & 1) * 8;

    float acc[2][4][4];
    #pragma unroll
    for (int a = 0; a < 2; a++)
        #pragma unroll
        for (int b = 0; b < 4; b++)
            #pragma unroll
            for (int c = 0; c < 4; c++) acc[a][b][c] = 0.f;

    int nt = K / BK;

    #pragma unroll
    for (int s = 0; s < NSTAGE - 1; s++) {
        fill_stage(as_base + s * STGA * 2, bs_base + s * STGB * 2,
                   Ap, Bp, m0, n0, ldA, ldB, s * BK, tid);
        CPA_COMMIT();
    }
    asm volatile("cp.async.wait_group %0;" :: "n"(NSTAGE - 2) : "memory");
    __syncthreads();

    for (int tt = 0; tt < nt; tt++) {
        int fs = tt + NSTAGE - 1;
        if (fs < nt) {
            int st = fs & (NSTAGE - 1);
            fill_stage(as_base + st * STGA * 2, bs_base + st * STGB * 2,
                       Ap, Bp, m0, n0, ldA, ldB, fs * BK, tid);
        }
        CPA_COMMIT();

        int cs = tt & (NSTAGE - 1);
        uint32_t ab = as_base + cs * STGA * 2;
        uint32_t bb = bs_base + cs * STGB * 2;

        #pragma unroll
        for (int ks = 0; ks < BK; ks += 16) {
            uint32_t afr[2][4];
            #pragma unroll
            for (int mi = 0; mi < 2; mi++) {
                uint32_t addr = ab + (((a_row + mi * 16) * ROWE) + ks + a_koff) * 2;
                LDSM4(afr[mi][0], afr[mi][1], afr[mi][2], afr[mi][3], addr);
            }
            uint32_t bcur[4], bnxt[4];
            {
                uint32_t addr = bb + ((b_row * ROWE) + ks + b_koff) * 2;
                LDSM4(bcur[0], bcur[1], bcur[2], bcur[3], addr);
            }
            #pragma unroll
            for (int np = 0; np < 2; np++) {
                if (np < 1) {
                    uint32_t addr = bb + (((b_row + 16) * ROWE) + ks + b_koff) * 2;
                    LDSM4(bnxt[0], bnxt[1], bnxt[2], bnxt[3], addr);
                }
                mma_bf16(acc[0][np * 2],     afr[0], bcur[0], bcur[1]);
                mma_bf16(acc[1][np * 2],     afr[1], bcur[0], bcur[1]);
                mma_bf16(acc[0][np * 2 + 1], afr[0], bcur[2], bcur[3]);
                mma_bf16(acc[1][np * 2 + 1], afr[1], bcur[2], bcur[3]);
                #pragma unroll
                for (int j = 0; j < 4; j++) bcur[j] = bnxt[j];
            }
        }

        asm volatile("cp.async.wait_group %0;" :: "n"(NSTAGE - 2) : "memory");
        __syncthreads();
    }

    // epilogue
    const float* Rp = HAS_RES ? (resid + (long long)bz * sC) : nullptr;
    float* Cf = OUT_BF16 ? nullptr : ((float*)Cv + (long long)bz * sC);
    __nv_bfloat16* Ch = OUT_BF16 ? ((__nv_bfloat16*)Cv + (long long)bz * sC) : nullptr;

    #pragma unroll
    for (int mi = 0; mi < 2; mi++) {
        int mlo = m0 + wm + mi * 16 + g;
        int mhi = mlo + 8;
        float bmlo = (BIAS_MODE == 1) ? bias[mlo] : 0.f;
        float bmhi = (BIAS_MODE == 1) ? bias[mhi] : 0.f;
        #pragma unroll
        for (int ni = 0; ni < 4; ni++) {
            int col = n0 + wn + ni * 8 + 2 * t;
            float bn0 = (BIAS_MODE == 2) ? bias[col] : 0.f;
            float bn1 = (BIAS_MODE == 2) ? bias[col + 1] : 0.f;
            float v00 = acc[mi][ni][0] * alpha + bmlo + bn0;
            float v01 = acc[mi][ni][1] * alpha + bmlo + bn1;
            float v10 = acc[mi][ni][2] * alpha + bmhi + bn0;
            float v11 = acc[mi][ni][3] * alpha + bmhi + bn1;
            long long olo = (long long)mlo * N + col;
            long long ohi = (long long)mhi * N + col;
            if (HAS_RES) {
                float2 r0 = *reinterpret_cast<const float2*>(&Rp[olo]);
                float2 r1 = *reinterpret_cast<const float2*>(&Rp[ohi]);
                v00 += r0.x; v01 += r0.y; v10 += r1.x; v11 += r1.y;
            }
            if (OUT_BF16) {
                __nv_bfloat162 plo(__float2bfloat16_rn(v00), __float2bfloat16_rn(v01));
                __nv_bfloat162 phi(__float2bfloat16_rn(v10), __float2bfloat16_rn(v11));
                *reinterpret_cast<__nv_bfloat162*>(&Ch[olo]) = plo;
                *reinterpret_cast<__nv_bfloat162*>(&Ch[ohi]) = phi;
            } else {
                *reinterpret_cast<float2*>(&Cf[olo]) = make_float2(v00, v01);
                *reinterpret_cast<float2*>(&Cf[ohi]) = make_float2(v10, v11);
            }
        }
    }
}

// ---------------------------------------------------------------------------
// Row softmax: e fp32 -> attn bf16
// ---------------------------------------------------------------------------
__global__ void softmax_kernel(const float* __restrict__ e,
                               __nv_bfloat16* __restrict__ at)
{
    long long row = (long long)blockIdx.x * HW_;
    const float* p = e + row;
    int t = threadIdx.x;

    float4 v4 = *reinterpret_cast<const float4*>(&p[t * 4]);
    float m = fmaxf(fmaxf(v4.x, v4.y), fmaxf(v4.z, v4.w));
    __shared__ float sh[8];
    m = warp_max(m);
    int wid = t >> 5, lid = t & 31;
    if (lid == 0) sh[wid] = m;
    __syncthreads();
    if (wid == 0) {
        float a = (lid < 8) ? sh[lid] : -3.4e38f;
        a = warp_max(a);
        if (lid == 0) sh[0] = a;
    }
    __syncthreads();
    m = sh[0];
    __syncthreads();

    v4.x = __expf(v4.x - m);
    v4.y = __expf(v4.y - m);
    v4.z = __expf(v4.z - m);
    v4.w = __expf(v4.w - m);
    float s = v4.x + v4.y + v4.z + v4.w;
    s = warp_sum(s);
    if (lid == 0) sh[wid] = s;
    __syncthreads();
    if (wid == 0) {
        float a = (lid < 8) ? sh[lid] : 0.f;
        a = warp_sum(a);
        if (lid == 0) sh[0] = a;
    }
    __syncthreads();
    float inv = 1.0f / sh[0];

    __nv_bfloat162 p0(__float2bfloat16_rn(v4.x * inv), __float2bfloat16_rn(v4.y * inv));
    __nv_bfloat162 p1(__float2bfloat16_rn(v4.z * inv), __float2bfloat16_rn(v4.w * inv));
    __nv_bfloat162* dst = reinterpret_cast<__nv_bfloat162*>(&at[row + t * 4]);
    dst[0] = p0;
    dst[1] = p1;
}

// ---------------------------------------------------------------------------
// Launch
// ---------------------------------------------------------------------------
extern "C" void kernel_launch(void* const* d_in, const int* in_sizes, int n_in,
                              void* d_out, int out_size)
{
    const float* x     = (const float*)d_in[0];
    const float* gamma = (const float*)d_in[1];
    const float* beta  = (const float*)d_in[2];
    const float* wq    = (const float*)d_in[3];
    const float* bq    = (const float*)d_in[4];
    const float* wk    = (const float*)d_in[5];
    const float* bk    = (const float*)d_in[6];
    const float* wv    = (const float*)d_in[7];
    const float* bv    = (const float*)d_in[8];
    const float* wp    = (const float*)d_in[9];
    const float* bp    = (const float*)d_in[10];
    float* out = (float*)d_out;

    __nv_bfloat16 *xnt, *qt, *kt, *v, *at, *ot, *bwq, *bwk, *bwv, *bwp;
    float* e;
    cudaGetSymbolAddress((void**)&xnt, g_xnt);
    cudaGetSymbolAddress((void**)&qt,  g_qt);
    cudaGetSymbolAddress((void**)&kt,  g_kt);
    cudaGetSymbolAddress((void**)&v,   g_v);
    cudaGetSymbolAddress((void**)&e,   g_e);
    cudaGetSymbolAddress((void**)&at,  g_at);
    cudaGetSymbolAddress((void**)&ot,  g_ot);
    cudaGetSymbolAddress((void**)&bwq, g_wq);
    cudaGetSymbolAddress((void**)&bwk, g_wk);
    cudaGetSymbolAddress((void**)&bwv, g_wv);
    cudaGetSymbolAddress((void**)&bwp, g_wp);

    const long long sSC = (long long)HW_ * C_;
    const long long sHH = (long long)HW_ * HW_;
    const float scale = 1.0f / sqrtf((float)C_);

    cudaFuncSetAttribute(bf_gemm<2, false, true, true>,
                         cudaFuncAttributeMaxDynamicSharedMemorySize, SMEM_BYTES);
    cudaFuncSetAttribute(bf_gemm<1, false, true, false>,
                         cudaFuncAttributeMaxDynamicSharedMemorySize, SMEM_BYTES);
    cudaFuncSetAttribute(bf_gemm<0, false, false, false>,
                         cudaFuncAttributeMaxDynamicSharedMemorySize, SMEM_BYTES);
    cudaFuncSetAttribute(bf_gemm<0, false, true, false>,
                         cudaFuncAttributeMaxDynamicSharedMemorySize, SMEM_BYTES);
    cudaFuncSetAttribute(bf_gemm<1, true, false, false>,
                         cudaFuncAttributeMaxDynamicSharedMemorySize, SMEM_BYTES);

    convert_w<<<256, 256>>>(wq, wk, wv, wp);
    gn_t_kernel<<<B_ * NG_, 256>>>(x, gamma, beta);

    // q_t and k_t fused: M=1024(s), N=512(o), K=512; z<16 -> q, z>=16 -> k
    dim3 gqk(C_ / 64, HW_ / 128, 2 * B_);
    bf_gemm<2, false, true, true><<<gqk, 256, SMEM_BYTES>>>(
        xnt, bwq, qt, bq, nullptr, bwk, bk, kt,
        C_, C_, C_, C_, 1.0f, sSC, 0, sSC);

    // v[o,s]: M=512, N=1024, K=512
    dim3 gv(HW_ / 64, C_ / 128, B_);
    bf_gemm<1, false, true, false><<<gv, 256, SMEM_BYTES>>>(
        bwv, xnt, v, bv, nullptr, nullptr, nullptr, nullptr,
        C_, C_, C_, HW_, 1.0f, 0, sSC, sSC);

    // e[i,j]: M=N=1024, K=512
    dim3 ge(HW_ / 64, HW_ / 128, B_);
    bf_gemm<0, false, false, false><<<ge, 256, SMEM_BYTES>>>(
        qt, kt, e, nullptr, nullptr, nullptr, nullptr, nullptr,
        C_, C_, C_, HW_, scale, sSC, sSC, sHH);

    softmax_kernel<<<B_ * HW_, 256>>>(e, at);

    // o_t[i,c]: M=1024, N=512, K=1024
    dim3 go(C_ / 64, HW_ / 128, B_);
    bf_gemm<0, false, true, false><<<go, 256, SMEM_BYTES>>>(
        at, v, ot, nullptr, nullptr, nullptr, nullptr, nullptr,
        HW_, HW_, HW_, C_, 1.0f, sHH, sSC, sSC);

    // out[o,s]: M=512, N=1024, K=512, bias m, residual
    dim3 gp(HW_ / 64, C_ / 128, B_);
    bf_gemm<1, true, false, false><<<gp, 256, SMEM_BYTES>>>(
        bwp, ot, out, bp, x, nullptr, nullptr, nullptr,
        C_, C_, C_, HW_, 1.0f, 0, sSC, sSC);
}

// round 8
// speedup vs baseline: 1.0388x; 1.0388x over previous
#include <cuda_runtime.h>
#include <cuda_bf16.h>
#include <cstdint>
#include <math.h>

// ---------------------------------------------------------------------------
// Attention block, bf16 mma.sync pipeline.
// R8: tile 128x128 (R6 config) + cross-k-step register double buffering.
// B=16, C=512, HW=1024, 32 groups, eps=1e-6
// ---------------------------------------------------------------------------

#define B_ 16
#define C_ 512
#define HW_ 1024
#define NG_ 32

__device__ __nv_bfloat16 g_xnt[(long long)B_ * HW_ * C_];
__device__ __nv_bfloat16 g_qt [(long long)B_ * HW_ * C_];
__device__ __nv_bfloat16 g_kt [(long long)B_ * HW_ * C_];
__device__ __nv_bfloat16 g_v  [(long long)B_ * C_ * HW_];
__device__ float         g_e  [(long long)B_ * HW_ * HW_];
__device__ __nv_bfloat16 g_at [(long long)B_ * HW_ * HW_];
__device__ __nv_bfloat16 g_ot [(long long)B_ * HW_ * C_];
__device__ __nv_bfloat16 g_wq[C_ * C_], g_wk[C_ * C_], g_wv[C_ * C_], g_wp[C_ * C_];

__inline__ __device__ float warp_sum(float v) {
    #pragma unroll
    for (int o = 16; o > 0; o >>= 1) v += __shfl_xor_sync(0xffffffffu, v, o);
    return v;
}
__inline__ __device__ float warp_max(float v) {
    #pragma unroll
    for (int o = 16; o > 0; o >>= 1) v = fmaxf(v, __shfl_xor_sync(0xffffffffu, v, o));
    return v;
}
__device__ __forceinline__ uint32_t smem_u32(const void* p) {
    uint32_t a;
    asm("{ .reg .u64 t; cvta.to.shared.u64 t, %1; cvt.u32.u64 %0, t; }"
        : "=r"(a) : "l"(p));
    return a;
}

#define CPA16(dst, src) \
    asm volatile("cp.async.cg.shared.global [%0], [%1], 16;" :: "r"(dst), "l"(src))
#define CPA_COMMIT() asm volatile("cp.async.commit_group;" ::: "memory")

#define LDSM4(R0, R1, R2, R3, addr) \
    asm volatile("ldmatrix.sync.aligned.m8n8.x4.shared.b16 {%0,%1,%2,%3}, [%4];" \
                 : "=r"(R0), "=r"(R1), "=r"(R2), "=r"(R3) : "r"(addr))

__device__ __forceinline__ void mma_bf16(float c[4], const uint32_t a[4],
                                         uint32_t b0, uint32_t b1) {
    asm volatile(
        "mma.sync.aligned.m16n8k16.row.col.f32.bf16.bf16.f32 "
        "{%0,%1,%2,%3}, {%4,%5,%6,%7}, {%8,%9}, {%0,%1,%2,%3};"
        : "+f"(c[0]), "+f"(c[1]), "+f"(c[2]), "+f"(c[3])
        : "r"(a[0]), "r"(a[1]), "r"(a[2]), "r"(a[3]), "r"(b0), "r"(b1));
}

// ---------------------------------------------------------------------------
// Weight conversion fp32 -> bf16
// ---------------------------------------------------------------------------
__global__ void convert_w(const float* __restrict__ wq, const float* __restrict__ wk,
                          const float* __restrict__ wv, const float* __restrict__ wp)
{
    int i = (blockIdx.x * 256 + threadIdx.x) * 4;
    if (i >= C_ * C_) return;
    #pragma unroll
    for (int j = 0; j < 4; j++) {
        g_wq[i + j] = __float2bfloat16_rn(wq[i + j]);
        g_wk[i + j] = __float2bfloat16_rn(wk[i + j]);
        g_wv[i + j] = __float2bfloat16_rn(wv[i + j]);
        g_wp[i + j] = __float2bfloat16_rn(wp[i + j]);
    }
}

// ---------------------------------------------------------------------------
// GroupNorm + transpose: x (B,C,HW) fp32 -> xn_t (B,HW,C) bf16
// ---------------------------------------------------------------------------
__global__ void gn_t_kernel(const float* __restrict__ x,
                            const float* __restrict__ gamma,
                            const float* __restrict__ beta)
{
    const int GSZ = 16 * HW_;
    int bg = blockIdx.x;
    int b = bg >> 5, g = bg & 31;
    long long base = (long long)bg * GSZ;
    int tid = threadIdx.x;

    float s = 0.f, sq = 0.f;
    for (int e = tid * 4; e < GSZ; e += 256 * 4) {
        float4 v4 = *reinterpret_cast<const float4*>(&x[base + e]);
        s  += v4.x + v4.y + v4.z + v4.w;
        sq += v4.x * v4.x + v4.y * v4.y + v4.z * v4.z + v4.w * v4.w;
    }
    __shared__ float shs[8], shq[8];
    s = warp_sum(s); sq = warp_sum(sq);
    int wid = tid >> 5, lid = tid & 31;
    if (lid == 0) { shs[wid] = s; shq[wid] = sq; }
    __syncthreads();
    if (wid == 0) {
        float a = (lid < 8) ? shs[lid] : 0.f;
        float bb = (lid < 8) ? shq[lid] : 0.f;
        a = warp_sum(a); bb = warp_sum(bb);
        if (lid == 0) { shs[0] = a; shq[0] = bb; }
    }
    __syncthreads();
    float mean = shs[0] / (float)GSZ;
    float var  = shq[0] / (float)GSZ - mean * mean;
    float inv  = rsqrtf(var + 1e-6f);

    float ga[16], be[16];
    #pragma unroll
    for (int c = 0; c < 16; c++) {
        ga[c] = gamma[g * 16 + c] * inv;
        be[c] = beta[g * 16 + c] - mean * ga[c];
    }

    __shared__ float tile[16][256];
    for (int s0 = 0; s0 < HW_; s0 += 256) {
        __syncthreads();
        #pragma unroll
        for (int i = 0; i < 16; i++) {
            int task = tid + i * 256;
            int c = task >> 8, sl = task & 255;
            tile[c][sl] = x[base + (long long)c * HW_ + s0 + sl];
        }
        __syncthreads();
        int sp = s0 + tid;
        union { __nv_bfloat16 h[16]; uint4 u[2]; } o;
        #pragma unroll
        for (int c = 0; c < 16; c++)
            o.h[c] = __float2bfloat16_rn(tile[c][tid] * ga[c] + be[c]);
        uint4* dst = reinterpret_cast<uint4*>(
            &g_xnt[((long long)b * HW_ + sp) * C_ + g * 16]);
        dst[0] = o.u[0];
        dst[1] = o.u[1];
    }
}

// ---------------------------------------------------------------------------
// bf16 GEMM: CTA 128x128, BK=32, 8 warps (4M x 2N), warp 32x64.
// 5-stage cp.async ring + full cross-k-step fragment double buffering.
// ---------------------------------------------------------------------------
#define BK 32
#define ROWE 40                   // padded row in bf16 elems (80B)
#define STGE (128 * ROWE)
#define NSTAGE 5
#define SMEM_BYTES (2 * NSTAGE * STGE * 2)

struct Frag {
    uint32_t a[2][4];
    uint32_t b[4][4];
};

__device__ __forceinline__ void fill_stage(
    uint32_t abase, uint32_t bbase,
    const __nv_bfloat16* Ap, const __nv_bfloat16* Bp,
    int m0, int n0, int ldA, int ldB, int k0, int tid)
{
    #pragma unroll
    for (int i = 0; i < 2; i++) {
        int task = tid + i * 256;
        int row = task >> 2, kc = task & 3;
        CPA16(abase + (row * ROWE + kc * 8) * 2,
              Ap + (long long)(m0 + row) * ldA + k0 + kc * 8);
        CPA16(bbase + (row * ROWE + kc * 8) * 2,
              Bp + (long long)(n0 + row) * ldB + k0 + kc * 8);
    }
}

__device__ __forceinline__ void load_frag(
    Frag& f, uint32_t ab, uint32_t bb, int ks,
    int a_row, int a_koff, int b_row, int b_koff)
{
    #pragma unroll
    for (int mi = 0; mi < 2; mi++) {
        uint32_t addr = ab + (((a_row + mi * 16) * ROWE) + ks + a_koff) * 2;
        LDSM4(f.a[mi][0], f.a[mi][1], f.a[mi][2], f.a[mi][3], addr);
    }
    #pragma unroll
    for (int np = 0; np < 4; np++) {
        uint32_t addr = bb + (((b_row + np * 16) * ROWE) + ks + b_koff) * 2;
        LDSM4(f.b[np][0], f.b[np][1], f.b[np][2], f.b[np][3], addr);
    }
}

__device__ __forceinline__ void do_mmas(float acc[2][8][4], const Frag& f)
{
    #pragma unroll
    for (int np = 0; np < 4; np++) {
        mma_bf16(acc[0][np * 2],     f.a[0], f.b[np][0], f.b[np][1]);
        mma_bf16(acc[1][np * 2],     f.a[1], f.b[np][0], f.b[np][1]);
        mma_bf16(acc[0][np * 2 + 1], f.a[0], f.b[np][2], f.b[np][3]);
        mma_bf16(acc[1][np * 2 + 1], f.a[1], f.b[np][2], f.b[np][3]);
    }
}

template<int BIAS_MODE, bool HAS_RES, bool OUT_BF16, bool DUAL>
__global__ __launch_bounds__(256, 2) void bf_gemm(
    const __nv_bfloat16* __restrict__ A, const __nv_bfloat16* __restrict__ Bm,
    void* __restrict__ Cv, const float* __restrict__ bias,
    const float* __restrict__ resid,
    const __nv_bfloat16* __restrict__ Bm2, const float* __restrict__ bias2,
    void* __restrict__ Cv2,
    int K, int ldA, int ldB, int N, float alpha,
    long long sA, long long sB, long long sC)
{
    extern __shared__ __nv_bfloat16 dsm[];

    int tid = threadIdx.x, wid = tid >> 5, lane = tid & 31;
    int g = lane >> 2, t = lane & 3;
    int wm = (wid & 3) * 32;
    int wn = (wid >> 2) * 64;
    int n0 = blockIdx.x * 128;
    int m0 = blockIdx.y * 128;
    int bz = blockIdx.z;
    if (DUAL) {
        if (bz >> 4) { Bm = Bm2; bias = bias2; Cv = Cv2; }
        bz &= 15;
    }
    const __nv_bfloat16* Ap = A  + (long long)bz * sA;
    const __nv_bfloat16* Bp = Bm + (long long)bz * sB;

    uint32_t as_base = smem_u32(dsm);
    uint32_t bs_base = as_base + NSTAGE * STGE * 2;

    int a_row = wm + (lane & 15);
    int a_koff = (lane >> 4) * 8;
    int b_row = wn + ((lane >> 4) << 3) + (lane & 7);
    int b_koff = ((lane >> 3) & 1) * 8;

    float acc[2][8][4];
    #pragma unroll
    for (int a = 0; a < 2; a++)
        #pragma unroll
        for (int b = 0; b < 8; b++)
            #pragma unroll
            for (int c = 0; c < 4; c++) acc[a][b][c] = 0.f;

    int nt = K / BK;

    // prologue: fill stages 0..NSTAGE-2
    #pragma unroll
    for (int s = 0; s < NSTAGE - 1; s++) {
        fill_stage(as_base + s * STGE * 2, bs_base + s * STGE * 2,
                   Ap, Bp, m0, n0, ldA, ldB, s * BK, tid);
        CPA_COMMIT();
    }
    asm volatile("cp.async.wait_group %0;" :: "n"(NSTAGE - 2) : "memory");
    __syncthreads();

    Frag fr0, fr1;
    // fragments for (chunk 0, ks=0)
    load_frag(fr0, as_base, bs_base, 0, a_row, a_koff, b_row, b_koff);

    for (int tt = 0; tt < nt; tt++) {
        int cs = tt % NSTAGE;
        uint32_t ab = as_base + cs * STGE * 2;
        uint32_t bb = bs_base + cs * STGE * 2;

        // prefetch (tt, ks=16) fragments, then MMAs for (tt, ks=0)
        load_frag(fr1, ab, bb, 16, a_row, a_koff, b_row, b_koff);
        do_mmas(acc, fr0);

        // stage the fill for chunk tt+NSTAGE-1, ensure stage tt+1 is resident
        int fs = tt + NSTAGE - 1;
        if (fs < nt) {
            int st = fs % NSTAGE;
            fill_stage(as_base + st * STGE * 2, bs_base + st * STGE * 2,
                       Ap, Bp, m0, n0, ldA, ldB, fs * BK, tid);
        }
        CPA_COMMIT();
        asm volatile("cp.async.wait_group %0;" :: "n"(NSTAGE - 2) : "memory");
        __syncthreads();

        // prefetch (tt+1, ks=0), then MMAs for (tt, ks=16)
        if (tt + 1 < nt) {
            int ns = (tt + 1) % NSTAGE;
            load_frag(fr0, as_base + ns * STGE * 2, bs_base + ns * STGE * 2, 0,
                      a_row, a_koff, b_row, b_koff);
        }
        do_mmas(acc, fr1);
    }

    // epilogue
    const float* Rp = HAS_RES ? (resid + (long long)bz * sC) : nullptr;
    float* Cf = OUT_BF16 ? nullptr : ((float*)Cv + (long long)bz * sC);
    __nv_bfloat16* Ch = OUT_BF16 ? ((__nv_bfloat16*)Cv + (long long)bz * sC) : nullptr;

    #pragma unroll
    for (int mi = 0; mi < 2; mi++) {
        int mlo = m0 + wm + mi * 16 + g;
        int mhi = mlo + 8;
        float bmlo = (BIAS_MODE == 1) ? bias[mlo] : 0.f;
        float bmhi = (BIAS_MODE == 1) ? bias[mhi] : 0.f;
        #pragma unroll
        for (int ni = 0; ni < 8; ni++) {
            int col = n0 + wn + ni * 8 + 2 * t;
            float bn0 = (BIAS_MODE == 2) ? bias[col] : 0.f;
            float bn1 = (BIAS_MODE == 2) ? bias[col + 1] : 0.f;
            float v00 = acc[mi][ni][0] * alpha + bmlo + bn0;
            float v01 = acc[mi][ni][1] * alpha + bmlo + bn1;
            float v10 = acc[mi][ni][2] * alpha + bmhi + bn0;
            float v11 = acc[mi][ni][3] * alpha + bmhi + bn1;
            long long olo = (long long)mlo * N + col;
            long long ohi = (long long)mhi * N + col;
            if (HAS_RES) {
                float2 r0 = *reinterpret_cast<const float2*>(&Rp[olo]);
                float2 r1 = *reinterpret_cast<const float2*>(&Rp[ohi]);
                v00 += r0.x; v01 += r0.y; v10 += r1.x; v11 += r1.y;
            }
            if (OUT_BF16) {
                __nv_bfloat162 plo(__float2bfloat16_rn(v00), __float2bfloat16_rn(v01));
                __nv_bfloat162 phi(__float2bfloat16_rn(v10), __float2bfloat16_rn(v11));
                *reinterpret_cast<__nv_bfloat162*>(&Ch[olo]) = plo;
                *reinterpret_cast<__nv_bfloat162*>(&Ch[ohi]) = phi;
            } else {
                *reinterpret_cast<float2*>(&Cf[olo]) = make_float2(v00, v01);
                *reinterpret_cast<float2*>(&Cf[ohi]) = make_float2(v10, v11);
            }
        }
    }
}

// ---------------------------------------------------------------------------
// Row softmax: e fp32 -> attn bf16
// ---------------------------------------------------------------------------
__global__ void softmax_kernel(const float* __restrict__ e,
                               __nv_bfloat16* __restrict__ at)
{
    long long row = (long long)blockIdx.x * HW_;
    const float* p = e + row;
    int t = threadIdx.x;

    float4 v4 = *reinterpret_cast<const float4*>(&p[t * 4]);
    float m = fmaxf(fmaxf(v4.x, v4.y), fmaxf(v4.z, v4.w));
    __shared__ float sh[8];
    m = warp_max(m);
    int wid = t >> 5, lid = t & 31;
    if (lid == 0) sh[wid] = m;
    __syncthreads();
    if (wid == 0) {
        float a = (lid < 8) ? sh[lid] : -3.4e38f;
        a = warp_max(a);
        if (lid == 0) sh[0] = a;
    }
    __syncthreads();
    m = sh[0];
    __syncthreads();

    v4.x = __expf(v4.x - m);
    v4.y = __expf(v4.y - m);
    v4.z = __expf(v4.z - m);
    v4.w = __expf(v4.w - m);
    float s = v4.x + v4.y + v4.z + v4.w;
    s = warp_sum(s);
    if (lid == 0) sh[wid] = s;
    __syncthreads();
    if (wid == 0) {
        float a = (lid < 8) ? sh[lid] : 0.f;
        a = warp_sum(a);
        if (lid == 0) sh[0] = a;
    }
    __syncthreads();
    float inv = 1.0f / sh[0];

    __nv_bfloat162 p0(__float2bfloat16_rn(v4.x * inv), __float2bfloat16_rn(v4.y * inv));
    __nv_bfloat162 p1(__float2bfloat16_rn(v4.z * inv), __float2bfloat16_rn(v4.w * inv));
    __nv_bfloat162* dst = reinterpret_cast<__nv_bfloat162*>(&at[row + t * 4]);
    dst[0] = p0;
    dst[1] = p1;
}

// ---------------------------------------------------------------------------
// Launch
// ---------------------------------------------------------------------------
extern "C" void kernel_launch(void* const* d_in, const int* in_sizes, int n_in,
                              void* d_out, int out_size)
{
    const float* x     = (const float*)d_in[0];
    const float* gamma = (const float*)d_in[1];
    const float* beta  = (const float*)d_in[2];
    const float* wq    = (const float*)d_in[3];
    const float* bq    = (const float*)d_in[4];
    const float* wk    = (const float*)d_in[5];
    const float* bk    = (const float*)d_in[6];
    const float* wv    = (const float*)d_in[7];
    const float* bv    = (const float*)d_in[8];
    const float* wp    = (const float*)d_in[9];
    const float* bp    = (const float*)d_in[10];
    float* out = (float*)d_out;

    __nv_bfloat16 *xnt, *qt, *kt, *v, *at, *ot, *bwq, *bwk, *bwv, *bwp;
    float* e;
    cudaGetSymbolAddress((void**)&xnt, g_xnt);
    cudaGetSymbolAddress((void**)&qt,  g_qt);
    cudaGetSymbolAddress((void**)&kt,  g_kt);
    cudaGetSymbolAddress((void**)&v,   g_v);
    cudaGetSymbolAddress((void**)&e,   g_e);
    cudaGetSymbolAddress((void**)&at,  g_at);
    cudaGetSymbolAddress((void**)&ot,  g_ot);
    cudaGetSymbolAddress((void**)&bwq, g_wq);
    cudaGetSymbolAddress((void**)&bwk, g_wk);
    cudaGetSymbolAddress((void**)&bwv, g_wv);
    cudaGetSymbolAddress((void**)&bwp, g_wp);

    const long long sSC = (long long)HW_ * C_;
    const long long sHH = (long long)HW_ * HW_;
    const float scale = 1.0f / sqrtf((float)C_);

    cudaFuncSetAttribute(bf_gemm<2, false, true, true>,
                         cudaFuncAttributeMaxDynamicSharedMemorySize, SMEM_BYTES);
    cudaFuncSetAttribute(bf_gemm<1, false, true, false>,
                         cudaFuncAttributeMaxDynamicSharedMemorySize, SMEM_BYTES);
    cudaFuncSetAttribute(bf_gemm<0, false, false, false>,
                         cudaFuncAttributeMaxDynamicSharedMemorySize, SMEM_BYTES);
    cudaFuncSetAttribute(bf_gemm<0, false, true, false>,
                         cudaFuncAttributeMaxDynamicSharedMemorySize, SMEM_BYTES);
    cudaFuncSetAttribute(bf_gemm<1, true, false, false>,
                         cudaFuncAttributeMaxDynamicSharedMemorySize, SMEM_BYTES);

    convert_w<<<256, 256>>>(wq, wk, wv, wp);
    gn_t_kernel<<<B_ * NG_, 256>>>(x, gamma, beta);

    // q_t and k_t fused: M=1024(s), N=512(o), K=512; z<16 -> q, z>=16 -> k
    dim3 gqk(C_ / 128, HW_ / 128, 2 * B_);
    bf_gemm<2, false, true, true><<<gqk, 256, SMEM_BYTES>>>(
        xnt, bwq, qt, bq, nullptr, bwk, bk, kt,
        C_, C_, C_, C_, 1.0f, sSC, 0, sSC);

    // v[o,s]: M=512, N=1024, K=512
    dim3 gv(HW_ / 128, C_ / 128, B_);
    bf_gemm<1, false, true, false><<<gv, 256, SMEM_BYTES>>>(
        bwv, xnt, v, bv, nullptr, nullptr, nullptr, nullptr,
        C_, C_, C_, HW_, 1.0f, 0, sSC, sSC);

    // e[i,j]: M=N=1024, K=512
    dim3 ge(HW_ / 128, HW_ / 128, B_);
    bf_gemm<0, false, false, false><<<ge, 256, SMEM_BYTES>>>(
        qt, kt, e, nullptr, nullptr, nullptr, nullptr, nullptr,
        C_, C_, C_, HW_, scale, sSC, sSC, sHH);

    softmax_kernel<<<B_ * HW_, 256>>>(e, at);

    // o_t[i,c]: M=1024, N=512, K=1024
    dim3 go(C_ / 128, HW_ / 128, B_);
    bf_gemm<0, false, true, false><<<go, 256, SMEM_BYTES>>>(
        at, v, ot, nullptr, nullptr, nullptr, nullptr, nullptr,
        HW_, HW_, HW_, C_, 1.0f, sHH, sSC, sSC);

    // out[o,s]: M=512, N=1024, K=512, bias m, residual
    dim3 gp(HW_ / 128, C_ / 128, B_);
    bf_gemm<1, true, false, false><<<gp, 256, SMEM_BYTES>>>(
        bwp, ot, out, bp, x, nullptr, nullptr, nullptr,
        C_, C_, C_, HW_, 1.0f, 0, sSC, sSC);
}

// round 9
// speedup vs baseline: 1.1324x; 1.0901x over previous
#include <cuda_runtime.h>
#include <cuda_bf16.h>
#include <cstdint>
#include <math.h>

// ---------------------------------------------------------------------------
// Attention block, bf16 mma.sync pipeline.
// R9: R6 core schedule, BK=64 / NSTAGE=3 (fewer barriers), fused QKV launch,
// weight conversion folded into GroupNorm.
// B=16, C=512, HW=1024, 32 groups, eps=1e-6
// ---------------------------------------------------------------------------

#define B_ 16
#define C_ 512
#define HW_ 1024
#define NG_ 32

__device__ __nv_bfloat16 g_xnt[(long long)B_ * HW_ * C_];
__device__ __nv_bfloat16 g_qt [(long long)B_ * HW_ * C_];
__device__ __nv_bfloat16 g_kt [(long long)B_ * HW_ * C_];
__device__ __nv_bfloat16 g_v  [(long long)B_ * C_ * HW_];
__device__ float         g_e  [(long long)B_ * HW_ * HW_];
__device__ __nv_bfloat16 g_at [(long long)B_ * HW_ * HW_];
__device__ __nv_bfloat16 g_ot [(long long)B_ * HW_ * C_];
__device__ __nv_bfloat16 g_wq[C_ * C_], g_wk[C_ * C_], g_wv[C_ * C_], g_wp[C_ * C_];

__inline__ __device__ float warp_sum(float v) {
    #pragma unroll
    for (int o = 16; o > 0; o >>= 1) v += __shfl_xor_sync(0xffffffffu, v, o);
    return v;
}
__inline__ __device__ float warp_max(float v) {
    #pragma unroll
    for (int o = 16; o > 0; o >>= 1) v = fmaxf(v, __shfl_xor_sync(0xffffffffu, v, o));
    return v;
}
__device__ __forceinline__ uint32_t smem_u32(const void* p) {
    uint32_t a;
    asm("{ .reg .u64 t; cvta.to.shared.u64 t, %1; cvt.u32.u64 %0, t; }"
        : "=r"(a) : "l"(p));
    return a;
}

#define CPA16(dst, src) \
    asm volatile("cp.async.cg.shared.global [%0], [%1], 16;" :: "r"(dst), "l"(src))
#define CPA_COMMIT() asm volatile("cp.async.commit_group;" ::: "memory")

#define LDSM4(R0, R1, R2, R3, addr) \
    asm volatile("ldmatrix.sync.aligned.m8n8.x4.shared.b16 {%0,%1,%2,%3}, [%4];" \
                 : "=r"(R0), "=r"(R1), "=r"(R2), "=r"(R3) : "r"(addr))

__device__ __forceinline__ void mma_bf16(float c[4], const uint32_t a[4],
                                         uint32_t b0, uint32_t b1) {
    asm volatile(
        "mma.sync.aligned.m16n8k16.row.col.f32.bf16.bf16.f32 "
        "{%0,%1,%2,%3}, {%4,%5,%6,%7}, {%8,%9}, {%0,%1,%2,%3};"
        : "+f"(c[0]), "+f"(c[1]), "+f"(c[2]), "+f"(c[3])
        : "r"(a[0]), "r"(a[1]), "r"(a[2]), "r"(a[3]), "r"(b0), "r"(b1));
}

// ---------------------------------------------------------------------------
// GEMM tiling constants
// ---------------------------------------------------------------------------
#define BK 64
#define ROWE 72                   // 64 elems + 8 pad (144B rows)
#define STGE (128 * ROWE)         // elems per operand per stage
#define NSTAGE 3
#define SMEM_BYTES (2 * NSTAGE * STGE * 2)

__device__ __forceinline__ void fill_stage(
    uint32_t abase, uint32_t bbase,
    const __nv_bfloat16* Ap, const __nv_bfloat16* Bp,
    int m0, int n0, int ldA, int ldB, int k0, int tid)
{
    #pragma unroll
    for (int i = 0; i < 4; i++) {
        int task = tid + i * 256;
        int row = task >> 3, kc = task & 7;
        CPA16(abase + (row * ROWE + kc * 8) * 2,
              Ap + (long long)(m0 + row) * ldA + k0 + kc * 8);
        CPA16(bbase + (row * ROWE + kc * 8) * 2,
              Bp + (long long)(n0 + row) * ldB + k0 + kc * 8);
    }
}

// R6-proven compute body for one BK=64 chunk (4 k-steps of 16).
__device__ __forceinline__ void compute_chunk(
    float acc[2][8][4], uint32_t ab, uint32_t bb,
    int a_row, int a_koff, int b_row, int b_koff)
{
    #pragma unroll
    for (int ks = 0; ks < BK; ks += 16) {
        uint32_t afr[2][4];
        #pragma unroll
        for (int mi = 0; mi < 2; mi++) {
            uint32_t addr = ab + (((a_row + mi * 16) * ROWE) + ks + a_koff) * 2;
            LDSM4(afr[mi][0], afr[mi][1], afr[mi][2], afr[mi][3], addr);
        }
        uint32_t bcur[4], bnxt[4];
        {
            uint32_t addr = bb + ((b_row * ROWE) + ks + b_koff) * 2;
            LDSM4(bcur[0], bcur[1], bcur[2], bcur[3], addr);
        }
        #pragma unroll
        for (int np = 0; np < 4; np++) {
            if (np < 3) {
                uint32_t addr = bb +
                    (((b_row + (np + 1) * 16) * ROWE) + ks + b_koff) * 2;
                LDSM4(bnxt[0], bnxt[1], bnxt[2], bnxt[3], addr);
            }
            mma_bf16(acc[0][np * 2],     afr[0], bcur[0], bcur[1]);
            mma_bf16(acc[1][np * 2],     afr[1], bcur[0], bcur[1]);
            mma_bf16(acc[0][np * 2 + 1], afr[0], bcur[2], bcur[3]);
            mma_bf16(acc[1][np * 2 + 1], afr[1], bcur[2], bcur[3]);
            #pragma unroll
            for (int j = 0; j < 4; j++) bcur[j] = bnxt[j];
        }
    }
}

// ---------------------------------------------------------------------------
// GroupNorm + transpose (+ folded weight conversion)
// x (B,C,HW) fp32 -> xn_t (B,HW,C) bf16 ; w* fp32 -> bf16
// ---------------------------------------------------------------------------
__global__ void gn_t_kernel(const float* __restrict__ x,
                            const float* __restrict__ gamma,
                            const float* __restrict__ beta,
                            const float* __restrict__ wq,
                            const float* __restrict__ wk,
                            const float* __restrict__ wv,
                            const float* __restrict__ wp)
{
    const int GSZ = 16 * HW_;
    int bg = blockIdx.x;
    int b = bg >> 5, g = bg & 31;
    long long base = (long long)bg * GSZ;
    int tid = threadIdx.x;

    // folded weight conversion: 512 blocks x 2048 elems covers 4 x 512x512
    {
        int idx0 = bg * 2048 + tid * 4;
        #pragma unroll
        for (int h = 0; h < 2; h++) {
            int idx = idx0 + h * 1024;
            int m = idx >> 18;            // which matrix
            int off = idx & 0x3FFFF;
            const float* src = (m == 0) ? wq : (m == 1) ? wk : (m == 2) ? wv : wp;
            __nv_bfloat16* dst = (m == 0) ? g_wq : (m == 1) ? g_wk : (m == 2) ? g_wv : g_wp;
            float4 v4 = *reinterpret_cast<const float4*>(&src[off]);
            __nv_bfloat162 p0(__float2bfloat16_rn(v4.x), __float2bfloat16_rn(v4.y));
            __nv_bfloat162 p1(__float2bfloat16_rn(v4.z), __float2bfloat16_rn(v4.w));
            *reinterpret_cast<__nv_bfloat162*>(&dst[off])     = p0;
            *reinterpret_cast<__nv_bfloat162*>(&dst[off + 2]) = p1;
        }
    }

    float s = 0.f, sq = 0.f;
    for (int e = tid * 4; e < GSZ; e += 256 * 4) {
        float4 v4 = *reinterpret_cast<const float4*>(&x[base + e]);
        s  += v4.x + v4.y + v4.z + v4.w;
        sq += v4.x * v4.x + v4.y * v4.y + v4.z * v4.z + v4.w * v4.w;
    }
    __shared__ float shs[8], shq[8];
    s = warp_sum(s); sq = warp_sum(sq);
    int wid = tid >> 5, lid = tid & 31;
    if (lid == 0) { shs[wid] = s; shq[wid] = sq; }
    __syncthreads();
    if (wid == 0) {
        float a = (lid < 8) ? shs[lid] : 0.f;
        float bb = (lid < 8) ? shq[lid] : 0.f;
        a = warp_sum(a); bb = warp_sum(bb);
        if (lid == 0) { shs[0] = a; shq[0] = bb; }
    }
    __syncthreads();
    float mean = shs[0] / (float)GSZ;
    float var  = shq[0] / (float)GSZ - mean * mean;
    float inv  = rsqrtf(var + 1e-6f);

    float ga[16], be[16];
    #pragma unroll
    for (int c = 0; c < 16; c++) {
        ga[c] = gamma[g * 16 + c] * inv;
        be[c] = beta[g * 16 + c] - mean * ga[c];
    }

    __shared__ float tile[16][256];
    for (int s0 = 0; s0 < HW_; s0 += 256) {
        __syncthreads();
        #pragma unroll
        for (int i = 0; i < 16; i++) {
            int task = tid + i * 256;
            int c = task >> 8, sl = task & 255;
            tile[c][sl] = x[base + (long long)c * HW_ + s0 + sl];
        }
        __syncthreads();
        int sp = s0 + tid;
        union { __nv_bfloat16 h[16]; uint4 u[2]; } o;
        #pragma unroll
        for (int c = 0; c < 16; c++)
            o.h[c] = __float2bfloat16_rn(tile[c][tid] * ga[c] + be[c]);
        uint4* dst = reinterpret_cast<uint4*>(
            &g_xnt[((long long)b * HW_ + sp) * C_ + g * 16]);
        dst[0] = o.u[0];
        dst[1] = o.u[1];
    }
}

// ---------------------------------------------------------------------------
// Fused QKV GEMM. grid (32, 1, 48), 256 threads.
//   z in [0,16):  q_t[b]  = xnt[b] * wq^T + bq   (M=1024, N=512, bias col? no:)
//     here: A = xnt (rows s, k contig), B = wq (rows o, k contig)
//     out q_t[s, o], bias over o (columns).
//   z in [16,32): same with wk -> k_t
//   z in [32,48): v[b][c,j] = wv (rows c) * xnt[b] (rows j) -> out v[c, j],
//     M=512, N=1024, bias over c (rows).
// ---------------------------------------------------------------------------
__global__ __launch_bounds__(256, 2) void qkv_gemm(
    const float* __restrict__ bq, const float* __restrict__ bk,
    const float* __restrict__ bv)
{
    extern __shared__ __nv_bfloat16 dsm[];

    int tid = threadIdx.x, wid = tid >> 5, lane = tid & 31;
    int g = lane >> 2, t = lane & 3;
    int wm = (wid & 3) * 32;
    int wn = (wid >> 2) * 64;

    const long long sSC = (long long)HW_ * C_;
    int zz = blockIdx.z;
    int xx = blockIdx.x;

    const __nv_bfloat16 *Ap, *Bp;
    __nv_bfloat16* Co;
    const float* bi;
    int m0, n0, Nn;
    bool bias_col;
    if (zz < 32) {
        int b = zz & 15;
        Ap = g_xnt + (long long)b * sSC;
        Bp = (zz < 16) ? g_wq : g_wk;
        Co = ((zz < 16) ? g_qt : g_kt) + (long long)b * sSC;
        bi = (zz < 16) ? bq : bk;
        m0 = (xx >> 2) * 128;          // 8 m-tiles (s)
        n0 = (xx & 3) * 128;           // 4 n-tiles (o)
        Nn = C_;
        bias_col = true;
    } else {
        int b = zz - 32;
        Ap = g_wv;
        Bp = g_xnt + (long long)b * sSC;
        Co = g_v + (long long)b * sSC;
        bi = bv;
        m0 = (xx >> 3) * 128;          // 4 m-tiles (c)
        n0 = (xx & 7) * 128;           // 8 n-tiles (j)
        Nn = HW_;
        bias_col = false;
    }

    uint32_t as_base = smem_u32(dsm);
    uint32_t bs_base = as_base + NSTAGE * STGE * 2;

    int a_row = wm + (lane & 15);
    int a_koff = (lane >> 4) * 8;
    int b_row = wn + ((lane >> 4) << 3) + (lane & 7);
    int b_koff = ((lane >> 3) & 1) * 8;

    float acc[2][8][4];
    #pragma unroll
    for (int a = 0; a < 2; a++)
        #pragma unroll
        for (int b2 = 0; b2 < 8; b2++)
            #pragma unroll
            for (int c = 0; c < 4; c++) acc[a][b2][c] = 0.f;

    const int nt = C_ / BK;   // 8

    #pragma unroll
    for (int s = 0; s < NSTAGE - 1; s++) {
        fill_stage(as_base + s * STGE * 2, bs_base + s * STGE * 2,
                   Ap, Bp, m0, n0, C_, C_, s * BK, tid);
        CPA_COMMIT();
    }
    asm volatile("cp.async.wait_group %0;" :: "n"(NSTAGE - 2) : "memory");
    __syncthreads();

    for (int tt = 0; tt < nt; tt++) {
        int fs = tt + NSTAGE - 1;
        if (fs < nt) {
            int st = fs % NSTAGE;
            fill_stage(as_base + st * STGE * 2, bs_base + st * STGE * 2,
                       Ap, Bp, m0, n0, C_, C_, fs * BK, tid);
        }
        CPA_COMMIT();

        int cs = tt % NSTAGE;
        compute_chunk(acc, as_base + cs * STGE * 2, bs_base + cs * STGE * 2,
                      a_row, a_koff, b_row, b_koff);

        asm volatile("cp.async.wait_group %0;" :: "n"(NSTAGE - 2) : "memory");
        __syncthreads();
    }

    #pragma unroll
    for (int mi = 0; mi < 2; mi++) {
        int mlo = m0 + wm + mi * 16 + g;
        int mhi = mlo + 8;
        float bmlo = bias_col ? 0.f : bi[mlo];
        float bmhi = bias_col ? 0.f : bi[mhi];
        #pragma unroll
        for (int ni = 0; ni < 8; ni++) {
            int col = n0 + wn + ni * 8 + 2 * t;
            float bn0 = bias_col ? bi[col] : 0.f;
            float bn1 = bias_col ? bi[col + 1] : 0.f;
            float v00 = acc[mi][ni][0] + bmlo + bn0;
            float v01 = acc[mi][ni][1] + bmlo + bn1;
            float v10 = acc[mi][ni][2] + bmhi + bn0;
            float v11 = acc[mi][ni][3] + bmhi + bn1;
            long long olo = (long long)mlo * Nn + col;
            long long ohi = (long long)mhi * Nn + col;
            __nv_bfloat162 plo(__float2bfloat16_rn(v00), __float2bfloat16_rn(v01));
            __nv_bfloat162 phi(__float2bfloat16_rn(v10), __float2bfloat16_rn(v11));
            *reinterpret_cast<__nv_bfloat162*>(&Co[olo]) = plo;
            *reinterpret_cast<__nv_bfloat162*>(&Co[ohi]) = phi;
        }
    }
}

// ---------------------------------------------------------------------------
// Generic bf16 GEMM (e / ot / proj).  D = alpha*A*B^T (+bias[m]) (+res)
// ---------------------------------------------------------------------------
template<int BIAS_MODE, bool HAS_RES, bool OUT_BF16>
__global__ __launch_bounds__(256, 2) void bf_gemm(
    const __nv_bfloat16* __restrict__ A, const __nv_bfloat16* __restrict__ Bm,
    void* __restrict__ Cv, const float* __restrict__ bias,
    const float* __restrict__ resid,
    int K, int ldA, int ldB, int N, float alpha,
    long long sA, long long sB, long long sC)
{
    extern __shared__ __nv_bfloat16 dsm[];

    int tid = threadIdx.x, wid = tid >> 5, lane = tid & 31;
    int g = lane >> 2, t = lane & 3;
    int wm = (wid & 3) * 32;
    int wn = (wid >> 2) * 64;
    int n0 = blockIdx.x * 128;
    int m0 = blockIdx.y * 128;
    int bz = blockIdx.z;
    const __nv_bfloat16* Ap = A  + (long long)bz * sA;
    const __nv_bfloat16* Bp = Bm + (long long)bz * sB;

    uint32_t as_base = smem_u32(dsm);
    uint32_t bs_base = as_base + NSTAGE * STGE * 2;

    int a_row = wm + (lane & 15);
    int a_koff = (lane >> 4) * 8;
    int b_row = wn + ((lane >> 4) << 3) + (lane & 7);
    int b_koff = ((lane >> 3) & 1) * 8;

    float acc[2][8][4];
    #pragma unroll
    for (int a = 0; a < 2; a++)
        #pragma unroll
        for (int b = 0; b < 8; b++)
            #pragma unroll
            for (int c = 0; c < 4; c++) acc[a][b][c] = 0.f;

    int nt = K / BK;

    #pragma unroll
    for (int s = 0; s < NSTAGE - 1; s++) {
        fill_stage(as_base + s * STGE * 2, bs_base + s * STGE * 2,
                   Ap, Bp, m0, n0, ldA, ldB, s * BK, tid);
        CPA_COMMIT();
    }
    asm volatile("cp.async.wait_group %0;" :: "n"(NSTAGE - 2) : "memory");
    __syncthreads();

    for (int tt = 0; tt < nt; tt++) {
        int fs = tt + NSTAGE - 1;
        if (fs < nt) {
            int st = fs % NSTAGE;
            fill_stage(as_base + st * STGE * 2, bs_base + st * STGE * 2,
                       Ap, Bp, m0, n0, ldA, ldB, fs * BK, tid);
        }
        CPA_COMMIT();

        int cs = tt % NSTAGE;
        compute_chunk(acc, as_base + cs * STGE * 2, bs_base + cs * STGE * 2,
                      a_row, a_koff, b_row, b_koff);

        asm volatile("cp.async.wait_group %0;" :: "n"(NSTAGE - 2) : "memory");
        __syncthreads();
    }

    const float* Rp = HAS_RES ? (resid + (long long)bz * sC) : nullptr;
    float* Cf = OUT_BF16 ? nullptr : ((float*)Cv + (long long)bz * sC);
    __nv_bfloat16* Ch = OUT_BF16 ? ((__nv_bfloat16*)Cv + (long long)bz * sC) : nullptr;

    #pragma unroll
    for (int mi = 0; mi < 2; mi++) {
        int mlo = m0 + wm + mi * 16 + g;
        int mhi = mlo + 8;
        float bmlo = (BIAS_MODE == 1) ? bias[mlo] : 0.f;
        float bmhi = (BIAS_MODE == 1) ? bias[mhi] : 0.f;
        #pragma unroll
        for (int ni = 0; ni < 8; ni++) {
            int col = n0 + wn + ni * 8 + 2 * t;
            float v00 = acc[mi][ni][0] * alpha + bmlo;
            float v01 = acc[mi][ni][1] * alpha + bmlo;
            float v10 = acc[mi][ni][2] * alpha + bmhi;
            float v11 = acc[mi][ni][3] * alpha + bmhi;
            long long olo = (long long)mlo * N + col;
            long long ohi = (long long)mhi * N + col;
            if (HAS_RES) {
                float2 r0 = *reinterpret_cast<const float2*>(&Rp[olo]);
                float2 r1 = *reinterpret_cast<const float2*>(&Rp[ohi]);
                v00 += r0.x; v01 += r0.y; v10 += r1.x; v11 += r1.y;
            }
            if (OUT_BF16) {
                __nv_bfloat162 plo(__float2bfloat16_rn(v00), __float2bfloat16_rn(v01));
                __nv_bfloat162 phi(__float2bfloat16_rn(v10), __float2bfloat16_rn(v11));
                *reinterpret_cast<__nv_bfloat162*>(&Ch[olo]) = plo;
                *reinterpret_cast<__nv_bfloat162*>(&Ch[ohi]) = phi;
            } else {
                *reinterpret_cast<float2*>(&Cf[olo]) = make_float2(v00, v01);
                *reinterpret_cast<float2*>(&Cf[ohi]) = make_float2(v10, v11);
            }
        }
    }
}

// ---------------------------------------------------------------------------
// Row softmax: e fp32 -> attn bf16
// ---------------------------------------------------------------------------
__global__ void softmax_kernel(const float* __restrict__ e,
                               __nv_bfloat16* __restrict__ at)
{
    long long row = (long long)blockIdx.x * HW_;
    const float* p = e + row;
    int t = threadIdx.x;

    float4 v4 = *reinterpret_cast<const float4*>(&p[t * 4]);
    float m = fmaxf(fmaxf(v4.x, v4.y), fmaxf(v4.z, v4.w));
    __shared__ float sh[8];
    m = warp_max(m);
    int wid = t >> 5, lid = t & 31;
    if (lid == 0) sh[wid] = m;
    __syncthreads();
    if (wid == 0) {
        float a = (lid < 8) ? sh[lid] : -3.4e38f;
        a = warp_max(a);
        if (lid == 0) sh[0] = a;
    }
    __syncthreads();
    m = sh[0];
    __syncthreads();

    v4.x = __expf(v4.x - m);
    v4.y = __expf(v4.y - m);
    v4.z = __expf(v4.z - m);
    v4.w = __expf(v4.w - m);
    float s = v4.x + v4.y + v4.z + v4.w;
    s = warp_sum(s);
    if (lid == 0) sh[wid] = s;
    __syncthreads();
    if (wid == 0) {
        float a = (lid < 8) ? sh[lid] : 0.f;
        a = warp_sum(a);
        if (lid == 0) sh[0] = a;
    }
    __syncthreads();
    float inv = 1.0f / sh[0];

    __nv_bfloat162 p0(__float2bfloat16_rn(v4.x * inv), __float2bfloat16_rn(v4.y * inv));
    __nv_bfloat162 p1(__float2bfloat16_rn(v4.z * inv), __float2bfloat16_rn(v4.w * inv));
    __nv_bfloat162* dst = reinterpret_cast<__nv_bfloat162*>(&at[row + t * 4]);
    dst[0] = p0;
    dst[1] = p1;
}

// ---------------------------------------------------------------------------
// Launch
// ---------------------------------------------------------------------------
extern "C" void kernel_launch(void* const* d_in, const int* in_sizes, int n_in,
                              void* d_out, int out_size)
{
    const float* x     = (const float*)d_in[0];
    const float* gamma = (const float*)d_in[1];
    const float* beta  = (const float*)d_in[2];
    const float* wq    = (const float*)d_in[3];
    const float* bq    = (const float*)d_in[4];
    const float* wk    = (const float*)d_in[5];
    const float* bk    = (const float*)d_in[6];
    const float* wv    = (const float*)d_in[7];
    const float* bv    = (const float*)d_in[8];
    const float* wp    = (const float*)d_in[9];
    const float* bp    = (const float*)d_in[10];
    float* out = (float*)d_out;

    __nv_bfloat16 *qt, *kt, *v, *at, *ot, *bwp;
    float* e;
    cudaGetSymbolAddress((void**)&qt,  g_qt);
    cudaGetSymbolAddress((void**)&kt,  g_kt);
    cudaGetSymbolAddress((void**)&v,   g_v);
    cudaGetSymbolAddress((void**)&e,   g_e);
    cudaGetSymbolAddress((void**)&at,  g_at);
    cudaGetSymbolAddress((void**)&ot,  g_ot);
    cudaGetSymbolAddress((void**)&bwp, g_wp);

    const long long sSC = (long long)HW_ * C_;
    const long long sHH = (long long)HW_ * HW_;
    const float scale = 1.0f / sqrtf((float)C_);

    cudaFuncSetAttribute(qkv_gemm,
                         cudaFuncAttributeMaxDynamicSharedMemorySize, SMEM_BYTES);
    cudaFuncSetAttribute(bf_gemm<0, false, false>,
                         cudaFuncAttributeMaxDynamicSharedMemorySize, SMEM_BYTES);
    cudaFuncSetAttribute(bf_gemm<0, false, true>,
                         cudaFuncAttributeMaxDynamicSharedMemorySize, SMEM_BYTES);
    cudaFuncSetAttribute(bf_gemm<1, true, false>,
                         cudaFuncAttributeMaxDynamicSharedMemorySize, SMEM_BYTES);

    // 1) GroupNorm + transpose (+ weight bf16 conversion folded in)
    gn_t_kernel<<<B_ * NG_, 256>>>(x, gamma, beta, wq, wk, wv, wp);

    // 2) fused q_t / k_t / v
    dim3 gqkv(32, 1, 48);
    qkv_gemm<<<gqkv, 256, SMEM_BYTES>>>(bq, bk, bv);

    // 3) e[i,j] = scale * q_t . k_t
    dim3 ge(HW_ / 128, HW_ / 128, B_);
    bf_gemm<0, false, false><<<ge, 256, SMEM_BYTES>>>(
        qt, kt, e, nullptr, nullptr,
        C_, C_, C_, HW_, scale, sSC, sSC, sHH);

    // 4) softmax rows -> at bf16
    softmax_kernel<<<B_ * HW_, 256>>>(e, at);

    // 5) o_t[i,c] = at . v  (M=1024, N=512, K=1024)
    dim3 go(C_ / 128, HW_ / 128, B_);
    bf_gemm<0, false, true><<<go, 256, SMEM_BYTES>>>(
        at, v, ot, nullptr, nullptr,
        HW_, HW_, HW_, C_, 1.0f, sHH, sSC, sSC);

    // 6) out[o,s] = wp . o_t + bp + x
    dim3 gp(HW_ / 128, C_ / 128, B_);
    bf_gemm<1, true, false><<<gp, 256, SMEM_BYTES>>>(
        bwp, ot, out, bp, x,
        C_, C_, C_, HW_, 1.0f, 0, sSC, sSC);
}

// round 10
// speedup vs baseline: 1.1685x; 1.0318x over previous
#include <cuda_runtime.h>
#include <cuda_bf16.h>
#include <cstdint>
#include <math.h>

// ---------------------------------------------------------------------------
// Attention block, bf16 mma.sync pipeline.
// R10: R9 frozen (BK=64/NSTAGE=3, fused QKV) + warp-per-row softmax.
// B=16, C=512, HW=1024, 32 groups, eps=1e-6
// ---------------------------------------------------------------------------

#define B_ 16
#define C_ 512
#define HW_ 1024
#define NG_ 32

__device__ __nv_bfloat16 g_xnt[(long long)B_ * HW_ * C_];
__device__ __nv_bfloat16 g_qt [(long long)B_ * HW_ * C_];
__device__ __nv_bfloat16 g_kt [(long long)B_ * HW_ * C_];
__device__ __nv_bfloat16 g_v  [(long long)B_ * C_ * HW_];
__device__ float         g_e  [(long long)B_ * HW_ * HW_];
__device__ __nv_bfloat16 g_at [(long long)B_ * HW_ * HW_];
__device__ __nv_bfloat16 g_ot [(long long)B_ * HW_ * C_];
__device__ __nv_bfloat16 g_wq[C_ * C_], g_wk[C_ * C_], g_wv[C_ * C_], g_wp[C_ * C_];

__inline__ __device__ float warp_sum(float v) {
    #pragma unroll
    for (int o = 16; o > 0; o >>= 1) v += __shfl_xor_sync(0xffffffffu, v, o);
    return v;
}
__inline__ __device__ float warp_max(float v) {
    #pragma unroll
    for (int o = 16; o > 0; o >>= 1) v = fmaxf(v, __shfl_xor_sync(0xffffffffu, v, o));
    return v;
}
__device__ __forceinline__ uint32_t smem_u32(const void* p) {
    uint32_t a;
    asm("{ .reg .u64 t; cvta.to.shared.u64 t, %1; cvt.u32.u64 %0, t; }"
        : "=r"(a) : "l"(p));
    return a;
}

#define CPA16(dst, src) \
    asm volatile("cp.async.cg.shared.global [%0], [%1], 16;" :: "r"(dst), "l"(src))
#define CPA_COMMIT() asm volatile("cp.async.commit_group;" ::: "memory")

#define LDSM4(R0, R1, R2, R3, addr) \
    asm volatile("ldmatrix.sync.aligned.m8n8.x4.shared.b16 {%0,%1,%2,%3}, [%4];" \
                 : "=r"(R0), "=r"(R1), "=r"(R2), "=r"(R3) : "r"(addr))

__device__ __forceinline__ void mma_bf16(float c[4], const uint32_t a[4],
                                         uint32_t b0, uint32_t b1) {
    asm volatile(
        "mma.sync.aligned.m16n8k16.row.col.f32.bf16.bf16.f32 "
        "{%0,%1,%2,%3}, {%4,%5,%6,%7}, {%8,%9}, {%0,%1,%2,%3};"
        : "+f"(c[0]), "+f"(c[1]), "+f"(c[2]), "+f"(c[3])
        : "r"(a[0]), "r"(a[1]), "r"(a[2]), "r"(a[3]), "r"(b0), "r"(b1));
}

// ---------------------------------------------------------------------------
// GEMM tiling constants
// ---------------------------------------------------------------------------
#define BK 64
#define ROWE 72                   // 64 elems + 8 pad (144B rows)
#define STGE (128 * ROWE)
#define NSTAGE 3
#define SMEM_BYTES (2 * NSTAGE * STGE * 2)

__device__ __forceinline__ void fill_stage(
    uint32_t abase, uint32_t bbase,
    const __nv_bfloat16* Ap, const __nv_bfloat16* Bp,
    int m0, int n0, int ldA, int ldB, int k0, int tid)
{
    #pragma unroll
    for (int i = 0; i < 4; i++) {
        int task = tid + i * 256;
        int row = task >> 3, kc = task & 7;
        CPA16(abase + (row * ROWE + kc * 8) * 2,
              Ap + (long long)(m0 + row) * ldA + k0 + kc * 8);
        CPA16(bbase + (row * ROWE + kc * 8) * 2,
              Bp + (long long)(n0 + row) * ldB + k0 + kc * 8);
    }
}

__device__ __forceinline__ void compute_chunk(
    float acc[2][8][4], uint32_t ab, uint32_t bb,
    int a_row, int a_koff, int b_row, int b_koff)
{
    #pragma unroll
    for (int ks = 0; ks < BK; ks += 16) {
        uint32_t afr[2][4];
        #pragma unroll
        for (int mi = 0; mi < 2; mi++) {
            uint32_t addr = ab + (((a_row + mi * 16) * ROWE) + ks + a_koff) * 2;
            LDSM4(afr[mi][0], afr[mi][1], afr[mi][2], afr[mi][3], addr);
        }
        uint32_t bcur[4], bnxt[4];
        {
            uint32_t addr = bb + ((b_row * ROWE) + ks + b_koff) * 2;
            LDSM4(bcur[0], bcur[1], bcur[2], bcur[3], addr);
        }
        #pragma unroll
        for (int np = 0; np < 4; np++) {
            if (np < 3) {
                uint32_t addr = bb +
                    (((b_row + (np + 1) * 16) * ROWE) + ks + b_koff) * 2;
                LDSM4(bnxt[0], bnxt[1], bnxt[2], bnxt[3], addr);
            }
            mma_bf16(acc[0][np * 2],     afr[0], bcur[0], bcur[1]);
            mma_bf16(acc[1][np * 2],     afr[1], bcur[0], bcur[1]);
            mma_bf16(acc[0][np * 2 + 1], afr[0], bcur[2], bcur[3]);
            mma_bf16(acc[1][np * 2 + 1], afr[1], bcur[2], bcur[3]);
            #pragma unroll
            for (int j = 0; j < 4; j++) bcur[j] = bnxt[j];
        }
    }
}

// ---------------------------------------------------------------------------
// GroupNorm + transpose (+ folded weight conversion)
// ---------------------------------------------------------------------------
__global__ void gn_t_kernel(const float* __restrict__ x,
                            const float* __restrict__ gamma,
                            const float* __restrict__ beta,
                            const float* __restrict__ wq,
                            const float* __restrict__ wk,
                            const float* __restrict__ wv,
                            const float* __restrict__ wp)
{
    const int GSZ = 16 * HW_;
    int bg = blockIdx.x;
    int b = bg >> 5, g = bg & 31;
    long long base = (long long)bg * GSZ;
    int tid = threadIdx.x;

    {
        int idx0 = bg * 2048 + tid * 4;
        #pragma unroll
        for (int h = 0; h < 2; h++) {
            int idx = idx0 + h * 1024;
            int m = idx >> 18;
            int off = idx & 0x3FFFF;
            const float* src = (m == 0) ? wq : (m == 1) ? wk : (m == 2) ? wv : wp;
            __nv_bfloat16* dst = (m == 0) ? g_wq : (m == 1) ? g_wk : (m == 2) ? g_wv : g_wp;
            float4 v4 = *reinterpret_cast<const float4*>(&src[off]);
            __nv_bfloat162 p0(__float2bfloat16_rn(v4.x), __float2bfloat16_rn(v4.y));
            __nv_bfloat162 p1(__float2bfloat16_rn(v4.z), __float2bfloat16_rn(v4.w));
            *reinterpret_cast<__nv_bfloat162*>(&dst[off])     = p0;
            *reinterpret_cast<__nv_bfloat162*>(&dst[off + 2]) = p1;
        }
    }

    float s = 0.f, sq = 0.f;
    for (int e = tid * 4; e < GSZ; e += 256 * 4) {
        float4 v4 = *reinterpret_cast<const float4*>(&x[base + e]);
        s  += v4.x + v4.y + v4.z + v4.w;
        sq += v4.x * v4.x + v4.y * v4.y + v4.z * v4.z + v4.w * v4.w;
    }
    __shared__ float shs[8], shq[8];
    s = warp_sum(s); sq = warp_sum(sq);
    int wid = tid >> 5, lid = tid & 31;
    if (lid == 0) { shs[wid] = s; shq[wid] = sq; }
    __syncthreads();
    if (wid == 0) {
        float a = (lid < 8) ? shs[lid] : 0.f;
        float bb = (lid < 8) ? shq[lid] : 0.f;
        a = warp_sum(a); bb = warp_sum(bb);
        if (lid == 0) { shs[0] = a; shq[0] = bb; }
    }
    __syncthreads();
    float mean = shs[0] / (float)GSZ;
    float var  = shq[0] / (float)GSZ - mean * mean;
    float inv  = rsqrtf(var + 1e-6f);

    float ga[16], be[16];
    #pragma unroll
    for (int c = 0; c < 16; c++) {
        ga[c] = gamma[g * 16 + c] * inv;
        be[c] = beta[g * 16 + c] - mean * ga[c];
    }

    __shared__ float tile[16][256];
    for (int s0 = 0; s0 < HW_; s0 += 256) {
        __syncthreads();
        #pragma unroll
        for (int i = 0; i < 16; i++) {
            int task = tid + i * 256;
            int c = task >> 8, sl = task & 255;
            tile[c][sl] = x[base + (long long)c * HW_ + s0 + sl];
        }
        __syncthreads();
        int sp = s0 + tid;
        union { __nv_bfloat16 h[16]; uint4 u[2]; } o;
        #pragma unroll
        for (int c = 0; c < 16; c++)
            o.h[c] = __float2bfloat16_rn(tile[c][tid] * ga[c] + be[c]);
        uint4* dst = reinterpret_cast<uint4*>(
            &g_xnt[((long long)b * HW_ + sp) * C_ + g * 16]);
        dst[0] = o.u[0];
        dst[1] = o.u[1];
    }
}

// ---------------------------------------------------------------------------
// Fused QKV GEMM (unchanged from R9)
// ---------------------------------------------------------------------------
__global__ __launch_bounds__(256, 2) void qkv_gemm(
    const float* __restrict__ bq, const float* __restrict__ bk,
    const float* __restrict__ bv)
{
    extern __shared__ __nv_bfloat16 dsm[];

    int tid = threadIdx.x, wid = tid >> 5, lane = tid & 31;
    int g = lane >> 2, t = lane & 3;
    int wm = (wid & 3) * 32;
    int wn = (wid >> 2) * 64;

    const long long sSC = (long long)HW_ * C_;
    int zz = blockIdx.z;
    int xx = blockIdx.x;

    const __nv_bfloat16 *Ap, *Bp;
    __nv_bfloat16* Co;
    const float* bi;
    int m0, n0, Nn;
    bool bias_col;
    if (zz < 32) {
        int b = zz & 15;
        Ap = g_xnt + (long long)b * sSC;
        Bp = (zz < 16) ? g_wq : g_wk;
        Co = ((zz < 16) ? g_qt : g_kt) + (long long)b * sSC;
        bi = (zz < 16) ? bq : bk;
        m0 = (xx >> 2) * 128;
        n0 = (xx & 3) * 128;
        Nn = C_;
        bias_col = true;
    } else {
        int b = zz - 32;
        Ap = g_wv;
        Bp = g_xnt + (long long)b * sSC;
        Co = g_v + (long long)b * sSC;
        bi = bv;
        m0 = (xx >> 3) * 128;
        n0 = (xx & 7) * 128;
        Nn = HW_;
        bias_col = false;
    }

    uint32_t as_base = smem_u32(dsm);
    uint32_t bs_base = as_base + NSTAGE * STGE * 2;

    int a_row = wm + (lane & 15);
    int a_koff = (lane >> 4) * 8;
    int b_row = wn + ((lane >> 4) << 3) + (lane & 7);
    int b_koff = ((lane >> 3) & 1) * 8;

    float acc[2][8][4];
    #pragma unroll
    for (int a = 0; a < 2; a++)
        #pragma unroll
        for (int b2 = 0; b2 < 8; b2++)
            #pragma unroll
            for (int c = 0; c < 4; c++) acc[a][b2][c] = 0.f;

    const int nt = C_ / BK;

    #pragma unroll
    for (int s = 0; s < NSTAGE - 1; s++) {
        fill_stage(as_base + s * STGE * 2, bs_base + s * STGE * 2,
                   Ap, Bp, m0, n0, C_, C_, s * BK, tid);
        CPA_COMMIT();
    }
    asm volatile("cp.async.wait_group %0;" :: "n"(NSTAGE - 2) : "memory");
    __syncthreads();

    for (int tt = 0; tt < nt; tt++) {
        int fs = tt + NSTAGE - 1;
        if (fs < nt) {
            int st = fs % NSTAGE;
            fill_stage(as_base + st * STGE * 2, bs_base + st * STGE * 2,
                       Ap, Bp, m0, n0, C_, C_, fs * BK, tid);
        }
        CPA_COMMIT();

        int cs = tt % NSTAGE;
        compute_chunk(acc, as_base + cs * STGE * 2, bs_base + cs * STGE * 2,
                      a_row, a_koff, b_row, b_koff);

        asm volatile("cp.async.wait_group %0;" :: "n"(NSTAGE - 2) : "memory");
        __syncthreads();
    }

    #pragma unroll
    for (int mi = 0; mi < 2; mi++) {
        int mlo = m0 + wm + mi * 16 + g;
        int mhi = mlo + 8;
        float bmlo = bias_col ? 0.f : bi[mlo];
        float bmhi = bias_col ? 0.f : bi[mhi];
        #pragma unroll
        for (int ni = 0; ni < 8; ni++) {
            int col = n0 + wn + ni * 8 + 2 * t;
            float bn0 = bias_col ? bi[col] : 0.f;
            float bn1 = bias_col ? bi[col + 1] : 0.f;
            float v00 = acc[mi][ni][0] + bmlo + bn0;
            float v01 = acc[mi][ni][1] + bmlo + bn1;
            float v10 = acc[mi][ni][2] + bmhi + bn0;
            float v11 = acc[mi][ni][3] + bmhi + bn1;
            long long olo = (long long)mlo * Nn + col;
            long long ohi = (long long)mhi * Nn + col;
            __nv_bfloat162 plo(__float2bfloat16_rn(v00), __float2bfloat16_rn(v01));
            __nv_bfloat162 phi(__float2bfloat16_rn(v10), __float2bfloat16_rn(v11));
            *reinterpret_cast<__nv_bfloat162*>(&Co[olo]) = plo;
            *reinterpret_cast<__nv_bfloat162*>(&Co[ohi]) = phi;
        }
    }
}

// ---------------------------------------------------------------------------
// Generic bf16 GEMM (e / ot / proj) — unchanged from R9
// ---------------------------------------------------------------------------
template<int BIAS_MODE, bool HAS_RES, bool OUT_BF16>
__global__ __launch_bounds__(256, 2) void bf_gemm(
    const __nv_bfloat16* __restrict__ A, const __nv_bfloat16* __restrict__ Bm,
    void* __restrict__ Cv, const float* __restrict__ bias,
    const float* __restrict__ resid,
    int K, int ldA, int ldB, int N, float alpha,
    long long sA, long long sB, long long sC)
{
    extern __shared__ __nv_bfloat16 dsm[];

    int tid = threadIdx.x, wid = tid >> 5, lane = tid & 31;
    int g = lane >> 2, t = lane & 3;
    int wm = (wid & 3) * 32;
    int wn = (wid >> 2) * 64;
    int n0 = blockIdx.x * 128;
    int m0 = blockIdx.y * 128;
    int bz = blockIdx.z;
    const __nv_bfloat16* Ap = A  + (long long)bz * sA;
    const __nv_bfloat16* Bp = Bm + (long long)bz * sB;

    uint32_t as_base = smem_u32(dsm);
    uint32_t bs_base = as_base + NSTAGE * STGE * 2;

    int a_row = wm + (lane & 15);
    int a_koff = (lane >> 4) * 8;
    int b_row = wn + ((lane >> 4) << 3) + (lane & 7);
    int b_koff = ((lane >> 3) & 1) * 8;

    float acc[2][8][4];
    #pragma unroll
    for (int a = 0; a < 2; a++)
        #pragma unroll
        for (int b = 0; b < 8; b++)
            #pragma unroll
            for (int c = 0; c < 4; c++) acc[a][b][c] = 0.f;

    int nt = K / BK;

    #pragma unroll
    for (int s = 0; s < NSTAGE - 1; s++) {
        fill_stage(as_base + s * STGE * 2, bs_base + s * STGE * 2,
                   Ap, Bp, m0, n0, ldA, ldB, s * BK, tid);
        CPA_COMMIT();
    }
    asm volatile("cp.async.wait_group %0;" :: "n"(NSTAGE - 2) : "memory");
    __syncthreads();

    for (int tt = 0; tt < nt; tt++) {
        int fs = tt + NSTAGE - 1;
        if (fs < nt) {
            int st = fs % NSTAGE;
            fill_stage(as_base + st * STGE * 2, bs_base + st * STGE * 2,
                       Ap, Bp, m0, n0, ldA, ldB, fs * BK, tid);
        }
        CPA_COMMIT();

        int cs = tt % NSTAGE;
        compute_chunk(acc, as_base + cs * STGE * 2, bs_base + cs * STGE * 2,
                      a_row, a_koff, b_row, b_koff);

        asm volatile("cp.async.wait_group %0;" :: "n"(NSTAGE - 2) : "memory");
        __syncthreads();
    }

    const float* Rp = HAS_RES ? (resid + (long long)bz * sC) : nullptr;
    float* Cf = OUT_BF16 ? nullptr : ((float*)Cv + (long long)bz * sC);
    __nv_bfloat16* Ch = OUT_BF16 ? ((__nv_bfloat16*)Cv + (long long)bz * sC) : nullptr;

    #pragma unroll
    for (int mi = 0; mi < 2; mi++) {
        int mlo = m0 + wm + mi * 16 + g;
        int mhi = mlo + 8;
        float bmlo = (BIAS_MODE == 1) ? bias[mlo] : 0.f;
        float bmhi = (BIAS_MODE == 1) ? bias[mhi] : 0.f;
        #pragma unroll
        for (int ni = 0; ni < 8; ni++) {
            int col = n0 + wn + ni * 8 + 2 * t;
            float v00 = acc[mi][ni][0] * alpha + bmlo;
            float v01 = acc[mi][ni][1] * alpha + bmlo;
            float v10 = acc[mi][ni][2] * alpha + bmhi;
            float v11 = acc[mi][ni][3] * alpha + bmhi;
            long long olo = (long long)mlo * N + col;
            long long ohi = (long long)mhi * N + col;
            if (HAS_RES) {
                float2 r0 = *reinterpret_cast<const float2*>(&Rp[olo]);
                float2 r1 = *reinterpret_cast<const float2*>(&Rp[ohi]);
                v00 += r0.x; v01 += r0.y; v10 += r1.x; v11 += r1.y;
            }
            if (OUT_BF16) {
                __nv_bfloat162 plo(__float2bfloat16_rn(v00), __float2bfloat16_rn(v01));
                __nv_bfloat162 phi(__float2bfloat16_rn(v10), __float2bfloat16_rn(v11));
                *reinterpret_cast<__nv_bfloat162*>(&Ch[olo]) = plo;
                *reinterpret_cast<__nv_bfloat162*>(&Ch[ohi]) = phi;
            } else {
                *reinterpret_cast<float2*>(&Cf[olo]) = make_float2(v00, v01);
                *reinterpret_cast<float2*>(&Cf[ohi]) = make_float2(v10, v11);
            }
        }
    }
}

// ---------------------------------------------------------------------------
// R10: warp-per-row softmax. Block = 256 threads = 8 warps = 8 rows.
// Each lane holds 32 elems (8 x float4) in registers; shuffle-only reductions.
// e fp32 -> at bf16.
// ---------------------------------------------------------------------------
__global__ __launch_bounds__(256) void softmax_kernel(
    const float* __restrict__ e, __nv_bfloat16* __restrict__ at)
{
    int wid = threadIdx.x >> 5, lane = threadIdx.x & 31;
    long long row = (long long)(blockIdx.x * 8 + wid) * HW_;
    const float4* p = reinterpret_cast<const float4*>(e + row) + lane;

    float4 v[8];
    #pragma unroll
    for (int i = 0; i < 8; i++) v[i] = p[i * 32];

    float m = -3.4e38f;
    #pragma unroll
    for (int i = 0; i < 8; i++) {
        m = fmaxf(m, fmaxf(fmaxf(v[i].x, v[i].y), fmaxf(v[i].z, v[i].w)));
    }
    m = warp_max(m);

    float s = 0.f;
    #pragma unroll
    for (int i = 0; i < 8; i++) {
        v[i].x = __expf(v[i].x - m);
        v[i].y = __expf(v[i].y - m);
        v[i].z = __expf(v[i].z - m);
        v[i].w = __expf(v[i].w - m);
        s += v[i].x + v[i].y + v[i].z + v[i].w;
    }
    s = warp_sum(s);
    float inv = 1.0f / s;

    __nv_bfloat162* dst = reinterpret_cast<__nv_bfloat162*>(at + row) + lane * 2;
    #pragma unroll
    for (int i = 0; i < 8; i++) {
        __nv_bfloat162 p0(__float2bfloat16_rn(v[i].x * inv),
                          __float2bfloat16_rn(v[i].y * inv));
        __nv_bfloat162 p1(__float2bfloat16_rn(v[i].z * inv),
                          __float2bfloat16_rn(v[i].w * inv));
        dst[i * 64]     = p0;
        dst[i * 64 + 1] = p1;
    }
}

// ---------------------------------------------------------------------------
// Launch
// ---------------------------------------------------------------------------
extern "C" void kernel_launch(void* const* d_in, const int* in_sizes, int n_in,
                              void* d_out, int out_size)
{
    const float* x     = (const float*)d_in[0];
    const float* gamma = (const float*)d_in[1];
    const float* beta  = (const float*)d_in[2];
    const float* wq    = (const float*)d_in[3];
    const float* bq    = (const float*)d_in[4];
    const float* wk    = (const float*)d_in[5];
    const float* bk    = (const float*)d_in[6];
    const float* wv    = (const float*)d_in[7];
    const float* bv    = (const float*)d_in[8];
    const float* wp    = (const float*)d_in[9];
    const float* bp    = (const float*)d_in[10];
    float* out = (float*)d_out;

    __nv_bfloat16 *qt, *kt, *v, *at, *ot, *bwp;
    float* e;
    cudaGetSymbolAddress((void**)&qt,  g_qt);
    cudaGetSymbolAddress((void**)&kt,  g_kt);
    cudaGetSymbolAddress((void**)&v,   g_v);
    cudaGetSymbolAddress((void**)&e,   g_e);
    cudaGetSymbolAddress((void**)&at,  g_at);
    cudaGetSymbolAddress((void**)&ot,  g_ot);
    cudaGetSymbolAddress((void**)&bwp, g_wp);

    const long long sSC = (long long)HW_ * C_;
    const long long sHH = (long long)HW_ * HW_;
    const float scale = 1.0f / sqrtf((float)C_);

    cudaFuncSetAttribute(qkv_gemm,
                         cudaFuncAttributeMaxDynamicSharedMemorySize, SMEM_BYTES);
    cudaFuncSetAttribute(bf_gemm<0, false, false>,
                         cudaFuncAttributeMaxDynamicSharedMemorySize, SMEM_BYTES);
    cudaFuncSetAttribute(bf_gemm<0, false, true>,
                         cudaFuncAttributeMaxDynamicSharedMemorySize, SMEM_BYTES);
    cudaFuncSetAttribute(bf_gemm<1, true, false>,
                         cudaFuncAttributeMaxDynamicSharedMemorySize, SMEM_BYTES);

    // 1) GroupNorm + transpose (+ weight bf16 conversion)
    gn_t_kernel<<<B_ * NG_, 256>>>(x, gamma, beta, wq, wk, wv, wp);

    // 2) fused q_t / k_t / v
    dim3 gqkv(32, 1, 48);
    qkv_gemm<<<gqkv, 256, SMEM_BYTES>>>(bq, bk, bv);

    // 3) e[i,j] = scale * q_t . k_t
    dim3 ge(HW_ / 128, HW_ / 128, B_);
    bf_gemm<0, false, false><<<ge, 256, SMEM_BYTES>>>(
        qt, kt, e, nullptr, nullptr,
        C_, C_, C_, HW_, scale, sSC, sSC, sHH);

    // 4) softmax rows -> at bf16 (warp per row, 8 rows per block)
    softmax_kernel<<<B_ * HW_ / 8, 256>>>(e, at);

    // 5) o_t[i,c] = at . v
    dim3 go(C_ / 128, HW_ / 128, B_);
    bf_gemm<0, false, true><<<go, 256, SMEM_BYTES>>>(
        at, v, ot, nullptr, nullptr,
        HW_, HW_, HW_, C_, 1.0f, sHH, sSC, sSC);

    // 6) out[o,s] = wp . o_t + bp + x
    dim3 gp(HW_ / 128, C_ / 128, B_);
    bf_gemm<1, true, false><<<gp, 256, SMEM_BYTES>>>(
        bwp, ot, out, bp, x,
        C_, C_, C_, HW_, 1.0f, 0, sSC, sSC);
}

// round 11
// speedup vs baseline: 1.1737x; 1.0045x over previous
#include <cuda_runtime.h>
#include <cuda_bf16.h>
#include <cstdint>
#include <math.h>

// ---------------------------------------------------------------------------
// Attention block, bf16 mma.sync pipeline.
// R11: R10 frozen + single-global-read GroupNorm (smem-resident group slab).
// B=16, C=512, HW=1024, 32 groups, eps=1e-6
// ---------------------------------------------------------------------------

#define B_ 16
#define C_ 512
#define HW_ 1024
#define NG_ 32

__device__ __nv_bfloat16 g_xnt[(long long)B_ * HW_ * C_];
__device__ __nv_bfloat16 g_qt [(long long)B_ * HW_ * C_];
__device__ __nv_bfloat16 g_kt [(long long)B_ * HW_ * C_];
__device__ __nv_bfloat16 g_v  [(long long)B_ * C_ * HW_];
__device__ float         g_e  [(long long)B_ * HW_ * HW_];
__device__ __nv_bfloat16 g_at [(long long)B_ * HW_ * HW_];
__device__ __nv_bfloat16 g_ot [(long long)B_ * HW_ * C_];
__device__ __nv_bfloat16 g_wq[C_ * C_], g_wk[C_ * C_], g_wv[C_ * C_], g_wp[C_ * C_];

__inline__ __device__ float warp_sum(float v) {
    #pragma unroll
    for (int o = 16; o > 0; o >>= 1) v += __shfl_xor_sync(0xffffffffu, v, o);
    return v;
}
__inline__ __device__ float warp_max(float v) {
    #pragma unroll
    for (int o = 16; o > 0; o >>= 1) v = fmaxf(v, __shfl_xor_sync(0xffffffffu, v, o));
    return v;
}
__device__ __forceinline__ uint32_t smem_u32(const void* p) {
    uint32_t a;
    asm("{ .reg .u64 t; cvta.to.shared.u64 t, %1; cvt.u32.u64 %0, t; }"
        : "=r"(a) : "l"(p));
    return a;
}

#define CPA16(dst, src) \
    asm volatile("cp.async.cg.shared.global [%0], [%1], 16;" :: "r"(dst), "l"(src))
#define CPA_COMMIT() asm volatile("cp.async.commit_group;" ::: "memory")

#define LDSM4(R0, R1, R2, R3, addr) \
    asm volatile("ldmatrix.sync.aligned.m8n8.x4.shared.b16 {%0,%1,%2,%3}, [%4];" \
                 : "=r"(R0), "=r"(R1), "=r"(R2), "=r"(R3) : "r"(addr))

__device__ __forceinline__ void mma_bf16(float c[4], const uint32_t a[4],
                                         uint32_t b0, uint32_t b1) {
    asm volatile(
        "mma.sync.aligned.m16n8k16.row.col.f32.bf16.bf16.f32 "
        "{%0,%1,%2,%3}, {%4,%5,%6,%7}, {%8,%9}, {%0,%1,%2,%3};"
        : "+f"(c[0]), "+f"(c[1]), "+f"(c[2]), "+f"(c[3])
        : "r"(a[0]), "r"(a[1]), "r"(a[2]), "r"(a[3]), "r"(b0), "r"(b1));
}

// ---------------------------------------------------------------------------
// GEMM tiling constants (frozen R9/R10 config)
// ---------------------------------------------------------------------------
#define BK 64
#define ROWE 72                   // 64 elems + 8 pad (144B rows)
#define STGE (128 * ROWE)
#define NSTAGE 3
#define SMEM_BYTES (2 * NSTAGE * STGE * 2)

__device__ __forceinline__ void fill_stage(
    uint32_t abase, uint32_t bbase,
    const __nv_bfloat16* Ap, const __nv_bfloat16* Bp,
    int m0, int n0, int ldA, int ldB, int k0, int tid)
{
    #pragma unroll
    for (int i = 0; i < 4; i++) {
        int task = tid + i * 256;
        int row = task >> 3, kc = task & 7;
        CPA16(abase + (row * ROWE + kc * 8) * 2,
              Ap + (long long)(m0 + row) * ldA + k0 + kc * 8);
        CPA16(bbase + (row * ROWE + kc * 8) * 2,
              Bp + (long long)(n0 + row) * ldB + k0 + kc * 8);
    }
}

__device__ __forceinline__ void compute_chunk(
    float acc[2][8][4], uint32_t ab, uint32_t bb,
    int a_row, int a_koff, int b_row, int b_koff)
{
    #pragma unroll
    for (int ks = 0; ks < BK; ks += 16) {
        uint32_t afr[2][4];
        #pragma unroll
        for (int mi = 0; mi < 2; mi++) {
            uint32_t addr = ab + (((a_row + mi * 16) * ROWE) + ks + a_koff) * 2;
            LDSM4(afr[mi][0], afr[mi][1], afr[mi][2], afr[mi][3], addr);
        }
        uint32_t bcur[4], bnxt[4];
        {
            uint32_t addr = bb + ((b_row * ROWE) + ks + b_koff) * 2;
            LDSM4(bcur[0], bcur[1], bcur[2], bcur[3], addr);
        }
        #pragma unroll
        for (int np = 0; np < 4; np++) {
            if (np < 3) {
                uint32_t addr = bb +
                    (((b_row + (np + 1) * 16) * ROWE) + ks + b_koff) * 2;
                LDSM4(bnxt[0], bnxt[1], bnxt[2], bnxt[3], addr);
            }
            mma_bf16(acc[0][np * 2],     afr[0], bcur[0], bcur[1]);
            mma_bf16(acc[1][np * 2],     afr[1], bcur[0], bcur[1]);
            mma_bf16(acc[0][np * 2 + 1], afr[0], bcur[2], bcur[3]);
            mma_bf16(acc[1][np * 2 + 1], afr[1], bcur[2], bcur[3]);
            #pragma unroll
            for (int j = 0; j < 4; j++) bcur[j] = bnxt[j];
        }
    }
}

// ---------------------------------------------------------------------------
// R11 GroupNorm: single global read. Group slab (16ch x 1024 = 64KB fp32)
// cached in dynamic smem; stats computed during load; normalize + transpose
// straight out of smem. (+ folded weight conversion, unchanged)
// ---------------------------------------------------------------------------
__global__ void gn_t_kernel(const float* __restrict__ x,
                            const float* __restrict__ gamma,
                            const float* __restrict__ beta,
                            const float* __restrict__ wq,
                            const float* __restrict__ wk,
                            const float* __restrict__ wv,
                            const float* __restrict__ wp)
{
    extern __shared__ float sd[];       // 16384 floats = 64KB
    const int GSZ = 16 * HW_;
    int bg = blockIdx.x;
    int b = bg >> 5, g = bg & 31;
    long long base = (long long)bg * GSZ;
    int tid = threadIdx.x;

    // folded weight conversion: 512 blocks x 2048 elems covers 4 x 512x512
    {
        int idx0 = bg * 2048 + tid * 4;
        #pragma unroll
        for (int h = 0; h < 2; h++) {
            int idx = idx0 + h * 1024;
            int m = idx >> 18;
            int off = idx & 0x3FFFF;
            const float* src = (m == 0) ? wq : (m == 1) ? wk : (m == 2) ? wv : wp;
            __nv_bfloat16* dst = (m == 0) ? g_wq : (m == 1) ? g_wk : (m == 2) ? g_wv : g_wp;
            float4 v4 = *reinterpret_cast<const float4*>(&src[off]);
            __nv_bfloat162 p0(__float2bfloat16_rn(v4.x), __float2bfloat16_rn(v4.y));
            __nv_bfloat162 p1(__float2bfloat16_rn(v4.z), __float2bfloat16_rn(v4.w));
            *reinterpret_cast<__nv_bfloat162*>(&dst[off])     = p0;
            *reinterpret_cast<__nv_bfloat162*>(&dst[off + 2]) = p1;
        }
    }

    // single pass: global -> smem, accumulating stats
    float s = 0.f, sq = 0.f;
    for (int e = tid * 4; e < GSZ; e += 256 * 4) {
        float4 v4 = *reinterpret_cast<const float4*>(&x[base + e]);
        *reinterpret_cast<float4*>(&sd[e]) = v4;
        s  += v4.x + v4.y + v4.z + v4.w;
        sq += v4.x * v4.x + v4.y * v4.y + v4.z * v4.z + v4.w * v4.w;
    }
    __shared__ float shs[8], shq[8];
    s = warp_sum(s); sq = warp_sum(sq);
    int wid = tid >> 5, lid = tid & 31;
    if (lid == 0) { shs[wid] = s; shq[wid] = sq; }
    __syncthreads();
    if (wid == 0) {
        float a = (lid < 8) ? shs[lid] : 0.f;
        float bb = (lid < 8) ? shq[lid] : 0.f;
        a = warp_sum(a); bb = warp_sum(bb);
        if (lid == 0) { shs[0] = a; shq[0] = bb; }
    }
    __syncthreads();
    float mean = shs[0] / (float)GSZ;
    float var  = shq[0] / (float)GSZ - mean * mean;
    float inv  = rsqrtf(var + 1e-6f);

    float ga[16], be[16];
    #pragma unroll
    for (int c = 0; c < 16; c++) {
        ga[c] = gamma[g * 16 + c] * inv;
        be[c] = beta[g * 16 + c] - mean * ga[c];
    }

    // normalize + transpose straight out of smem (conflict-free: lane-adjacent sp)
    #pragma unroll
    for (int s0 = 0; s0 < HW_; s0 += 256) {
        int sp = s0 + tid;
        union { __nv_bfloat16 h[16]; uint4 u[2]; } o;
        #pragma unroll
        for (int c = 0; c < 16; c++)
            o.h[c] = __float2bfloat16_rn(sd[c * HW_ + sp] * ga[c] + be[c]);
        uint4* dst = reinterpret_cast<uint4*>(
            &g_xnt[((long long)b * HW_ + sp) * C_ + g * 16]);
        dst[0] = o.u[0];
        dst[1] = o.u[1];
    }
}
#define GN_SMEM (16 * HW_ * 4)

// ---------------------------------------------------------------------------
// Fused QKV GEMM (unchanged)
// ---------------------------------------------------------------------------
__global__ __launch_bounds__(256, 2) void qkv_gemm(
    const float* __restrict__ bq, const float* __restrict__ bk,
    const float* __restrict__ bv)
{
    extern __shared__ __nv_bfloat16 dsm[];

    int tid = threadIdx.x, wid = tid >> 5, lane = tid & 31;
    int g = lane >> 2, t = lane & 3;
    int wm = (wid & 3) * 32;
    int wn = (wid >> 2) * 64;

    const long long sSC = (long long)HW_ * C_;
    int zz = blockIdx.z;
    int xx = blockIdx.x;

    const __nv_bfloat16 *Ap, *Bp;
    __nv_bfloat16* Co;
    const float* bi;
    int m0, n0, Nn;
    bool bias_col;
    if (zz < 32) {
        int b = zz & 15;
        Ap = g_xnt + (long long)b * sSC;
        Bp = (zz < 16) ? g_wq : g_wk;
        Co = ((zz < 16) ? g_qt : g_kt) + (long long)b * sSC;
        bi = (zz < 16) ? bq : bk;
        m0 = (xx >> 2) * 128;
        n0 = (xx & 3) * 128;
        Nn = C_;
        bias_col = true;
    } else {
        int b = zz - 32;
        Ap = g_wv;
        Bp = g_xnt + (long long)b * sSC;
        Co = g_v + (long long)b * sSC;
        bi = bv;
        m0 = (xx >> 3) * 128;
        n0 = (xx & 7) * 128;
        Nn = HW_;
        bias_col = false;
    }

    uint32_t as_base = smem_u32(dsm);
    uint32_t bs_base = as_base + NSTAGE * STGE * 2;

    int a_row = wm + (lane & 15);
    int a_koff = (lane >> 4) * 8;
    int b_row = wn + ((lane >> 4) << 3) + (lane & 7);
    int b_koff = ((lane >> 3) & 1) * 8;

    float acc[2][8][4];
    #pragma unroll
    for (int a = 0; a < 2; a++)
        #pragma unroll
        for (int b2 = 0; b2 < 8; b2++)
            #pragma unroll
            for (int c = 0; c < 4; c++) acc[a][b2][c] = 0.f;

    const int nt = C_ / BK;

    #pragma unroll
    for (int s = 0; s < NSTAGE - 1; s++) {
        fill_stage(as_base + s * STGE * 2, bs_base + s * STGE * 2,
                   Ap, Bp, m0, n0, C_, C_, s * BK, tid);
        CPA_COMMIT();
    }
    asm volatile("cp.async.wait_group %0;" :: "n"(NSTAGE - 2) : "memory");
    __syncthreads();

    for (int tt = 0; tt < nt; tt++) {
        int fs = tt + NSTAGE - 1;
        if (fs < nt) {
            int st = fs % NSTAGE;
            fill_stage(as_base + st * STGE * 2, bs_base + st * STGE * 2,
                       Ap, Bp, m0, n0, C_, C_, fs * BK, tid);
        }
        CPA_COMMIT();

        int cs = tt % NSTAGE;
        compute_chunk(acc, as_base + cs * STGE * 2, bs_base + cs * STGE * 2,
                      a_row, a_koff, b_row, b_koff);

        asm volatile("cp.async.wait_group %0;" :: "n"(NSTAGE - 2) : "memory");
        __syncthreads();
    }

    #pragma unroll
    for (int mi = 0; mi < 2; mi++) {
        int mlo = m0 + wm + mi * 16 + g;
        int mhi = mlo + 8;
        float bmlo = bias_col ? 0.f : bi[mlo];
        float bmhi = bias_col ? 0.f : bi[mhi];
        #pragma unroll
        for (int ni = 0; ni < 8; ni++) {
            int col = n0 + wn + ni * 8 + 2 * t;
            float bn0 = bias_col ? bi[col] : 0.f;
            float bn1 = bias_col ? bi[col + 1] : 0.f;
            float v00 = acc[mi][ni][0] + bmlo + bn0;
            float v01 = acc[mi][ni][1] + bmlo + bn1;
            float v10 = acc[mi][ni][2] + bmhi + bn0;
            float v11 = acc[mi][ni][3] + bmhi + bn1;
            long long olo = (long long)mlo * Nn + col;
            long long ohi = (long long)mhi * Nn + col;
            __nv_bfloat162 plo(__float2bfloat16_rn(v00), __float2bfloat16_rn(v01));
            __nv_bfloat162 phi(__float2bfloat16_rn(v10), __float2bfloat16_rn(v11));
            *reinterpret_cast<__nv_bfloat162*>(&Co[olo]) = plo;
            *reinterpret_cast<__nv_bfloat162*>(&Co[ohi]) = phi;
        }
    }
}

// ---------------------------------------------------------------------------
// Generic bf16 GEMM (e / ot / proj) — unchanged
// ---------------------------------------------------------------------------
template<int BIAS_MODE, bool HAS_RES, bool OUT_BF16>
__global__ __launch_bounds__(256, 2) void bf_gemm(
    const __nv_bfloat16* __restrict__ A, const __nv_bfloat16* __restrict__ Bm,
    void* __restrict__ Cv, const float* __restrict__ bias,
    const float* __restrict__ resid,
    int K, int ldA, int ldB, int N, float alpha,
    long long sA, long long sB, long long sC)
{
    extern __shared__ __nv_bfloat16 dsm[];

    int tid = threadIdx.x, wid = tid >> 5, lane = tid & 31;
    int g = lane >> 2, t = lane & 3;
    int wm = (wid & 3) * 32;
    int wn = (wid >> 2) * 64;
    int n0 = blockIdx.x * 128;
    int m0 = blockIdx.y * 128;
    int bz = blockIdx.z;
    const __nv_bfloat16* Ap = A  + (long long)bz * sA;
    const __nv_bfloat16* Bp = Bm + (long long)bz * sB;

    uint32_t as_base = smem_u32(dsm);
    uint32_t bs_base = as_base + NSTAGE * STGE * 2;

    int a_row = wm + (lane & 15);
    int a_koff = (lane >> 4) * 8;
    int b_row = wn + ((lane >> 4) << 3) + (lane & 7);
    int b_koff = ((lane >> 3) & 1) * 8;

    float acc[2][8][4];
    #pragma unroll
    for (int a = 0; a < 2; a++)
        #pragma unroll
        for (int b = 0; b < 8; b++)
            #pragma unroll
            for (int c = 0; c < 4; c++) acc[a][b][c] = 0.f;

    int nt = K / BK;

    #pragma unroll
    for (int s = 0; s < NSTAGE - 1; s++) {
        fill_stage(as_base + s * STGE * 2, bs_base + s * STGE * 2,
                   Ap, Bp, m0, n0, ldA, ldB, s * BK, tid);
        CPA_COMMIT();
    }
    asm volatile("cp.async.wait_group %0;" :: "n"(NSTAGE - 2) : "memory");
    __syncthreads();

    for (int tt = 0; tt < nt; tt++) {
        int fs = tt + NSTAGE - 1;
        if (fs < nt) {
            int st = fs % NSTAGE;
            fill_stage(as_base + st * STGE * 2, bs_base + st * STGE * 2,
                       Ap, Bp, m0, n0, ldA, ldB, fs * BK, tid);
        }
        CPA_COMMIT();

        int cs = tt % NSTAGE;
        compute_chunk(acc, as_base + cs * STGE * 2, bs_base + cs * STGE * 2,
                      a_row, a_koff, b_row, b_koff);

        asm volatile("cp.async.wait_group %0;" :: "n"(NSTAGE - 2) : "memory");
        __syncthreads();
    }

    const float* Rp = HAS_RES ? (resid + (long long)bz * sC) : nullptr;
    float* Cf = OUT_BF16 ? nullptr : ((float*)Cv + (long long)bz * sC);
    __nv_bfloat16* Ch = OUT_BF16 ? ((__nv_bfloat16*)Cv + (long long)bz * sC) : nullptr;

    #pragma unroll
    for (int mi = 0; mi < 2; mi++) {
        int mlo = m0 + wm + mi * 16 + g;
        int mhi = mlo + 8;
        float bmlo = (BIAS_MODE == 1) ? bias[mlo] : 0.f;
        float bmhi = (BIAS_MODE == 1) ? bias[mhi] : 0.f;
        #pragma unroll
        for (int ni = 0; ni < 8; ni++) {
            int col = n0 + wn + ni * 8 + 2 * t;
            float v00 = acc[mi][ni][0] * alpha + bmlo;
            float v01 = acc[mi][ni][1] * alpha + bmlo;
            float v10 = acc[mi][ni][2] * alpha + bmhi;
            float v11 = acc[mi][ni][3] * alpha + bmhi;
            long long olo = (long long)mlo * N + col;
            long long ohi = (long long)mhi * N + col;
            if (HAS_RES) {
                float2 r0 = *reinterpret_cast<const float2*>(&Rp[olo]);
                float2 r1 = *reinterpret_cast<const float2*>(&Rp[ohi]);
                v00 += r0.x; v01 += r0.y; v10 += r1.x; v11 += r1.y;
            }
            if (OUT_BF16) {
                __nv_bfloat162 plo(__float2bfloat16_rn(v00), __float2bfloat16_rn(v01));
                __nv_bfloat162 phi(__float2bfloat16_rn(v10), __float2bfloat16_rn(v11));
                *reinterpret_cast<__nv_bfloat162*>(&Ch[olo]) = plo;
                *reinterpret_cast<__nv_bfloat162*>(&Ch[ohi]) = phi;
            } else {
                *reinterpret_cast<float2*>(&Cf[olo]) = make_float2(v00, v01);
                *reinterpret_cast<float2*>(&Cf[ohi]) = make_float2(v10, v11);
            }
        }
    }
}

// ---------------------------------------------------------------------------
// Warp-per-row softmax (unchanged from R10)
// ---------------------------------------------------------------------------
__global__ __launch_bounds__(256) void softmax_kernel(
    const float* __restrict__ e, __nv_bfloat16* __restrict__ at)
{
    int wid = threadIdx.x >> 5, lane = threadIdx.x & 31;
    long long row = (long long)(blockIdx.x * 8 + wid) * HW_;
    const float4* p = reinterpret_cast<const float4*>(e + row) + lane;

    float4 v[8];
    #pragma unroll
    for (int i = 0; i < 8; i++) v[i] = p[i * 32];

    float m = -3.4e38f;
    #pragma unroll
    for (int i = 0; i < 8; i++) {
        m = fmaxf(m, fmaxf(fmaxf(v[i].x, v[i].y), fmaxf(v[i].z, v[i].w)));
    }
    m = warp_max(m);

    float s = 0.f;
    #pragma unroll
    for (int i = 0; i < 8; i++) {
        v[i].x = __expf(v[i].x - m);
        v[i].y = __expf(v[i].y - m);
        v[i].z = __expf(v[i].z - m);
        v[i].w = __expf(v[i].w - m);
        s += v[i].x + v[i].y + v[i].z + v[i].w;
    }
    s = warp_sum(s);
    float inv = 1.0f / s;

    __nv_bfloat162* dst = reinterpret_cast<__nv_bfloat162*>(at + row) + lane * 2;
    #pragma unroll
    for (int i = 0; i < 8; i++) {
        __nv_bfloat162 p0(__float2bfloat16_rn(v[i].x * inv),
                          __float2bfloat16_rn(v[i].y * inv));
        __nv_bfloat162 p1(__float2bfloat16_rn(v[i].z * inv),
                          __float2bfloat16_rn(v[i].w * inv));
        dst[i * 64]     = p0;
        dst[i * 64 + 1] = p1;
    }
}

// ---------------------------------------------------------------------------
// Launch
// ---------------------------------------------------------------------------
extern "C" void kernel_launch(void* const* d_in, const int* in_sizes, int n_in,
                              void* d_out, int out_size)
{
    const float* x     = (const float*)d_in[0];
    const float* gamma = (const float*)d_in[1];
    const float* beta  = (const float*)d_in[2];
    const float* wq    = (const float*)d_in[3];
    const float* bq    = (const float*)d_in[4];
    const float* wk    = (const float*)d_in[5];
    const float* bk    = (const float*)d_in[6];
    const float* wv    = (const float*)d_in[7];
    const float* bv    = (const float*)d_in[8];
    const float* wp    = (const float*)d_in[9];
    const float* bp    = (const float*)d_in[10];
    float* out = (float*)d_out;

    __nv_bfloat16 *qt, *kt, *v, *at, *ot, *bwp;
    float* e;
    cudaGetSymbolAddress((void**)&qt,  g_qt);
    cudaGetSymbolAddress((void**)&kt,  g_kt);
    cudaGetSymbolAddress((void**)&v,   g_v);
    cudaGetSymbolAddress((void**)&e,   g_e);
    cudaGetSymbolAddress((void**)&at,  g_at);
    cudaGetSymbolAddress((void**)&ot,  g_ot);
    cudaGetSymbolAddress((void**)&bwp, g_wp);

    const long long sSC = (long long)HW_ * C_;
    const long long sHH = (long long)HW_ * HW_;
    const float scale = 1.0f / sqrtf((float)C_);

    cudaFuncSetAttribute(gn_t_kernel,
                         cudaFuncAttributeMaxDynamicSharedMemorySize, GN_SMEM);
    cudaFuncSetAttribute(qkv_gemm,
                         cudaFuncAttributeMaxDynamicSharedMemorySize, SMEM_BYTES);
    cudaFuncSetAttribute(bf_gemm<0, false, false>,
                         cudaFuncAttributeMaxDynamicSharedMemorySize, SMEM_BYTES);
    cudaFuncSetAttribute(bf_gemm<0, false, true>,
                         cudaFuncAttributeMaxDynamicSharedMemorySize, SMEM_BYTES);
    cudaFuncSetAttribute(bf_gemm<1, true, false>,
                         cudaFuncAttributeMaxDynamicSharedMemorySize, SMEM_BYTES);

    // 1) GroupNorm + transpose (single global read) + weight conversion
    gn_t_kernel<<<B_ * NG_, 256, GN_SMEM>>>(x, gamma, beta, wq, wk, wv, wp);

    // 2) fused q_t / k_t / v
    dim3 gqkv(32, 1, 48);
    qkv_gemm<<<gqkv, 256, SMEM_BYTES>>>(bq, bk, bv);

    // 3) e[i,j] = scale * q_t . k_t
    dim3 ge(HW_ / 128, HW_ / 128, B_);
    bf_gemm<0, false, false><<<ge, 256, SMEM_BYTES>>>(
        qt, kt, e, nullptr, nullptr,
        C_, C_, C_, HW_, scale, sSC, sSC, sHH);

    // 4) softmax rows -> at bf16 (warp per row)
    softmax_kernel<<<B_ * HW_ / 8, 256>>>(e, at);

    // 5) o_t[i,c] = at . v
    dim3 go(C_ / 128, HW_ / 128, B_);
    bf_gemm<0, false, true><<<go, 256, SMEM_BYTES>>>(
        at, v, ot, nullptr, nullptr,
        HW_, HW_, HW_, C_, 1.0f, sHH, sSC, sSC);

    // 6) out[o,s] = wp . o_t + bp + x
    dim3 gp(HW_ / 128, C_ / 128, B_);
    bf_gemm<1, true, false><<<gp, 256, SMEM_BYTES>>>(
        bwp, ot, out, bp, x,
        C_, C_, C_, HW_, 1.0f, 0, sSC, sSC);
}

// round 12
// speedup vs baseline: 1.1851x; 1.0097x over previous
#include <cuda_runtime.h>
#include <cuda_bf16.h>
#include <cstdint>
#include <math.h>

// ---------------------------------------------------------------------------
// Attention block, bf16 mma.sync pipeline.
// R12: unnormalized-exp fusion — e GEMM writes exp(e) bf16 directly (no e
// buffer, no softmax pass); rowsum kernel computes 1/S; ot GEMM scales rows.
// B=16, C=512, HW=1024, 32 groups, eps=1e-6
// ---------------------------------------------------------------------------

#define B_ 16
#define C_ 512
#define HW_ 1024
#define NG_ 32

__device__ __nv_bfloat16 g_xnt[(long long)B_ * HW_ * C_];
__device__ __nv_bfloat16 g_qt [(long long)B_ * HW_ * C_];
__device__ __nv_bfloat16 g_kt [(long long)B_ * HW_ * C_];
__device__ __nv_bfloat16 g_v  [(long long)B_ * C_ * HW_];
__device__ __nv_bfloat16 g_at [(long long)B_ * HW_ * HW_];   // exp(e), unnormalized
__device__ float         g_s  [B_ * HW_];                    // 1/rowsum
__device__ __nv_bfloat16 g_ot [(long long)B_ * HW_ * C_];
__device__ __nv_bfloat16 g_wq[C_ * C_], g_wk[C_ * C_], g_wv[C_ * C_], g_wp[C_ * C_];

__inline__ __device__ float warp_sum(float v) {
    #pragma unroll
    for (int o = 16; o > 0; o >>= 1) v += __shfl_xor_sync(0xffffffffu, v, o);
    return v;
}
__device__ __forceinline__ uint32_t smem_u32(const void* p) {
    uint32_t a;
    asm("{ .reg .u64 t; cvta.to.shared.u64 t, %1; cvt.u32.u64 %0, t; }"
        : "=r"(a) : "l"(p));
    return a;
}

#define CPA16(dst, src) \
    asm volatile("cp.async.cg.shared.global [%0], [%1], 16;" :: "r"(dst), "l"(src))
#define CPA_COMMIT() asm volatile("cp.async.commit_group;" ::: "memory")

#define LDSM4(R0, R1, R2, R3, addr) \
    asm volatile("ldmatrix.sync.aligned.m8n8.x4.shared.b16 {%0,%1,%2,%3}, [%4];" \
                 : "=r"(R0), "=r"(R1), "=r"(R2), "=r"(R3) : "r"(addr))

__device__ __forceinline__ void mma_bf16(float c[4], const uint32_t a[4],
                                         uint32_t b0, uint32_t b1) {
    asm volatile(
        "mma.sync.aligned.m16n8k16.row.col.f32.bf16.bf16.f32 "
        "{%0,%1,%2,%3}, {%4,%5,%6,%7}, {%8,%9}, {%0,%1,%2,%3};"
        : "+f"(c[0]), "+f"(c[1]), "+f"(c[2]), "+f"(c[3])
        : "r"(a[0]), "r"(a[1]), "r"(a[2]), "r"(a[3]), "r"(b0), "r"(b1));
}

// ---------------------------------------------------------------------------
// GEMM tiling constants (frozen config)
// ---------------------------------------------------------------------------
#define BK 64
#define ROWE 72
#define STGE (128 * ROWE)
#define NSTAGE 3
#define SMEM_BYTES (2 * NSTAGE * STGE * 2)

__device__ __forceinline__ void fill_stage(
    uint32_t abase, uint32_t bbase,
    const __nv_bfloat16* Ap, const __nv_bfloat16* Bp,
    int m0, int n0, int ldA, int ldB, int k0, int tid)
{
    #pragma unroll
    for (int i = 0; i < 4; i++) {
        int task = tid + i * 256;
        int row = task >> 3, kc = task & 7;
        CPA16(abase + (row * ROWE + kc * 8) * 2,
              Ap + (long long)(m0 + row) * ldA + k0 + kc * 8);
        CPA16(bbase + (row * ROWE + kc * 8) * 2,
              Bp + (long long)(n0 + row) * ldB + k0 + kc * 8);
    }
}

__device__ __forceinline__ void compute_chunk(
    float acc[2][8][4], uint32_t ab, uint32_t bb,
    int a_row, int a_koff, int b_row, int b_koff)
{
    #pragma unroll
    for (int ks = 0; ks < BK; ks += 16) {
        uint32_t afr[2][4];
        #pragma unroll
        for (int mi = 0; mi < 2; mi++) {
            uint32_t addr = ab + (((a_row + mi * 16) * ROWE) + ks + a_koff) * 2;
            LDSM4(afr[mi][0], afr[mi][1], afr[mi][2], afr[mi][3], addr);
        }
        uint32_t bcur[4], bnxt[4];
        {
            uint32_t addr = bb + ((b_row * ROWE) + ks + b_koff) * 2;
            LDSM4(bcur[0], bcur[1], bcur[2], bcur[3], addr);
        }
        #pragma unroll
        for (int np = 0; np < 4; np++) {
            if (np < 3) {
                uint32_t addr = bb +
                    (((b_row + (np + 1) * 16) * ROWE) + ks + b_koff) * 2;
                LDSM4(bnxt[0], bnxt[1], bnxt[2], bnxt[3], addr);
            }
            mma_bf16(acc[0][np * 2],     afr[0], bcur[0], bcur[1]);
            mma_bf16(acc[1][np * 2],     afr[1], bcur[0], bcur[1]);
            mma_bf16(acc[0][np * 2 + 1], afr[0], bcur[2], bcur[3]);
            mma_bf16(acc[1][np * 2 + 1], afr[1], bcur[2], bcur[3]);
            #pragma unroll
            for (int j = 0; j < 4; j++) bcur[j] = bnxt[j];
        }
    }
}

// ---------------------------------------------------------------------------
// GroupNorm + transpose, single global read (+ folded weight conversion)
// ---------------------------------------------------------------------------
__global__ void gn_t_kernel(const float* __restrict__ x,
                            const float* __restrict__ gamma,
                            const float* __restrict__ beta,
                            const float* __restrict__ wq,
                            const float* __restrict__ wk,
                            const float* __restrict__ wv,
                            const float* __restrict__ wp)
{
    extern __shared__ float sd[];
    const int GSZ = 16 * HW_;
    int bg = blockIdx.x;
    int b = bg >> 5, g = bg & 31;
    long long base = (long long)bg * GSZ;
    int tid = threadIdx.x;

    {
        int idx0 = bg * 2048 + tid * 4;
        #pragma unroll
        for (int h = 0; h < 2; h++) {
            int idx = idx0 + h * 1024;
            int m = idx >> 18;
            int off = idx & 0x3FFFF;
            const float* src = (m == 0) ? wq : (m == 1) ? wk : (m == 2) ? wv : wp;
            __nv_bfloat16* dst = (m == 0) ? g_wq : (m == 1) ? g_wk : (m == 2) ? g_wv : g_wp;
            float4 v4 = *reinterpret_cast<const float4*>(&src[off]);
            __nv_bfloat162 p0(__float2bfloat16_rn(v4.x), __float2bfloat16_rn(v4.y));
            __nv_bfloat162 p1(__float2bfloat16_rn(v4.z), __float2bfloat16_rn(v4.w));
            *reinterpret_cast<__nv_bfloat162*>(&dst[off])     = p0;
            *reinterpret_cast<__nv_bfloat162*>(&dst[off + 2]) = p1;
        }
    }

    float s = 0.f, sq = 0.f;
    for (int e = tid * 4; e < GSZ; e += 256 * 4) {
        float4 v4 = *reinterpret_cast<const float4*>(&x[base + e]);
        *reinterpret_cast<float4*>(&sd[e]) = v4;
        s  += v4.x + v4.y + v4.z + v4.w;
        sq += v4.x * v4.x + v4.y * v4.y + v4.z * v4.z + v4.w * v4.w;
    }
    __shared__ float shs[8], shq[8];
    s = warp_sum(s); sq = warp_sum(sq);
    int wid = tid >> 5, lid = tid & 31;
    if (lid == 0) { shs[wid] = s; shq[wid] = sq; }
    __syncthreads();
    if (wid == 0) {
        float a = (lid < 8) ? shs[lid] : 0.f;
        float bb = (lid < 8) ? shq[lid] : 0.f;
        a = warp_sum(a); bb = warp_sum(bb);
        if (lid == 0) { shs[0] = a; shq[0] = bb; }
    }
    __syncthreads();
    float mean = shs[0] / (float)GSZ;
    float var  = shq[0] / (float)GSZ - mean * mean;
    float inv  = rsqrtf(var + 1e-6f);

    float ga[16], be[16];
    #pragma unroll
    for (int c = 0; c < 16; c++) {
        ga[c] = gamma[g * 16 + c] * inv;
        be[c] = beta[g * 16 + c] - mean * ga[c];
    }

    #pragma unroll
    for (int s0 = 0; s0 < HW_; s0 += 256) {
        int sp = s0 + tid;
        union { __nv_bfloat16 h[16]; uint4 u[2]; } o;
        #pragma unroll
        for (int c = 0; c < 16; c++)
            o.h[c] = __float2bfloat16_rn(sd[c * HW_ + sp] * ga[c] + be[c]);
        uint4* dst = reinterpret_cast<uint4*>(
            &g_xnt[((long long)b * HW_ + sp) * C_ + g * 16]);
        dst[0] = o.u[0];
        dst[1] = o.u[1];
    }
}
#define GN_SMEM (16 * HW_ * 4)

// ---------------------------------------------------------------------------
// Fused QKV GEMM (unchanged)
// ---------------------------------------------------------------------------
__global__ __launch_bounds__(256, 2) void qkv_gemm(
    const float* __restrict__ bq, const float* __restrict__ bk,
    const float* __restrict__ bv)
{
    extern __shared__ __nv_bfloat16 dsm[];

    int tid = threadIdx.x, wid = tid >> 5, lane = tid & 31;
    int g = lane >> 2, t = lane & 3;
    int wm = (wid & 3) * 32;
    int wn = (wid >> 2) * 64;

    const long long sSC = (long long)HW_ * C_;
    int zz = blockIdx.z;
    int xx = blockIdx.x;

    const __nv_bfloat16 *Ap, *Bp;
    __nv_bfloat16* Co;
    const float* bi;
    int m0, n0, Nn;
    bool bias_col;
    if (zz < 32) {
        int b = zz & 15;
        Ap = g_xnt + (long long)b * sSC;
        Bp = (zz < 16) ? g_wq : g_wk;
        Co = ((zz < 16) ? g_qt : g_kt) + (long long)b * sSC;
        bi = (zz < 16) ? bq : bk;
        m0 = (xx >> 2) * 128;
        n0 = (xx & 3) * 128;
        Nn = C_;
        bias_col = true;
    } else {
        int b = zz - 32;
        Ap = g_wv;
        Bp = g_xnt + (long long)b * sSC;
        Co = g_v + (long long)b * sSC;
        bi = bv;
        m0 = (xx >> 3) * 128;
        n0 = (xx & 7) * 128;
        Nn = HW_;
        bias_col = false;
    }

    uint32_t as_base = smem_u32(dsm);
    uint32_t bs_base = as_base + NSTAGE * STGE * 2;

    int a_row = wm + (lane & 15);
    int a_koff = (lane >> 4) * 8;
    int b_row = wn + ((lane >> 4) << 3) + (lane & 7);
    int b_koff = ((lane >> 3) & 1) * 8;

    float acc[2][8][4];
    #pragma unroll
    for (int a = 0; a < 2; a++)
        #pragma unroll
        for (int b2 = 0; b2 < 8; b2++)
            #pragma unroll
            for (int c = 0; c < 4; c++) acc[a][b2][c] = 0.f;

    const int nt = C_ / BK;

    #pragma unroll
    for (int s = 0; s < NSTAGE - 1; s++) {
        fill_stage(as_base + s * STGE * 2, bs_base + s * STGE * 2,
                   Ap, Bp, m0, n0, C_, C_, s * BK, tid);
        CPA_COMMIT();
    }
    asm volatile("cp.async.wait_group %0;" :: "n"(NSTAGE - 2) : "memory");
    __syncthreads();

    for (int tt = 0; tt < nt; tt++) {
        int fs = tt + NSTAGE - 1;
        if (fs < nt) {
            int st = fs % NSTAGE;
            fill_stage(as_base + st * STGE * 2, bs_base + st * STGE * 2,
                       Ap, Bp, m0, n0, C_, C_, fs * BK, tid);
        }
        CPA_COMMIT();

        int cs = tt % NSTAGE;
        compute_chunk(acc, as_base + cs * STGE * 2, bs_base + cs * STGE * 2,
                      a_row, a_koff, b_row, b_koff);

        asm volatile("cp.async.wait_group %0;" :: "n"(NSTAGE - 2) : "memory");
        __syncthreads();
    }

    #pragma unroll
    for (int mi = 0; mi < 2; mi++) {
        int mlo = m0 + wm + mi * 16 + g;
        int mhi = mlo + 8;
        float bmlo = bias_col ? 0.f : bi[mlo];
        float bmhi = bias_col ? 0.f : bi[mhi];
        #pragma unroll
        for (int ni = 0; ni < 8; ni++) {
            int col = n0 + wn + ni * 8 + 2 * t;
            float bn0 = bias_col ? bi[col] : 0.f;
            float bn1 = bias_col ? bi[col + 1] : 0.f;
            float v00 = acc[mi][ni][0] + bmlo + bn0;
            float v01 = acc[mi][ni][1] + bmlo + bn1;
            float v10 = acc[mi][ni][2] + bmhi + bn0;
            float v11 = acc[mi][ni][3] + bmhi + bn1;
            long long olo = (long long)mlo * Nn + col;
            long long ohi = (long long)mhi * Nn + col;
            __nv_bfloat162 plo(__float2bfloat16_rn(v00), __float2bfloat16_rn(v01));
            __nv_bfloat162 phi(__float2bfloat16_rn(v10), __float2bfloat16_rn(v11));
            *reinterpret_cast<__nv_bfloat162*>(&Co[olo]) = plo;
            *reinterpret_cast<__nv_bfloat162*>(&Co[ohi]) = phi;
        }
    }
}

// ---------------------------------------------------------------------------
// Generic bf16 GEMM.
// EPI modes: HAS_EXP -> val = __expf(acc*alpha), out bf16 (e GEMM)
//            HAS_RSC -> val = acc * rowsc[m],    out bf16 (ot GEMM)
//            BIAS_MODE=1 + HAS_RES -> fp32 out   (proj GEMM)
// ---------------------------------------------------------------------------
template<int BIAS_MODE, bool HAS_RES, bool OUT_BF16, bool HAS_EXP, bool HAS_RSC>
__global__ __launch_bounds__(256, 2) void bf_gemm(
    const __nv_bfloat16* __restrict__ A, const __nv_bfloat16* __restrict__ Bm,
    void* __restrict__ Cv, const float* __restrict__ bias,
    const float* __restrict__ resid, const float* __restrict__ rowsc,
    int K, int ldA, int ldB, int N, float alpha,
    long long sA, long long sB, long long sC, long long sR)
{
    extern __shared__ __nv_bfloat16 dsm[];

    int tid = threadIdx.x, wid = tid >> 5, lane = tid & 31;
    int g = lane >> 2, t = lane & 3;
    int wm = (wid & 3) * 32;
    int wn = (wid >> 2) * 64;
    int n0 = blockIdx.x * 128;
    int m0 = blockIdx.y * 128;
    int bz = blockIdx.z;
    const __nv_bfloat16* Ap = A  + (long long)bz * sA;
    const __nv_bfloat16* Bp = Bm + (long long)bz * sB;

    uint32_t as_base = smem_u32(dsm);
    uint32_t bs_base = as_base + NSTAGE * STGE * 2;

    int a_row = wm + (lane & 15);
    int a_koff = (lane >> 4) * 8;
    int b_row = wn + ((lane >> 4) << 3) + (lane & 7);
    int b_koff = ((lane >> 3) & 1) * 8;

    float acc[2][8][4];
    #pragma unroll
    for (int a = 0; a < 2; a++)
        #pragma unroll
        for (int b = 0; b < 8; b++)
            #pragma unroll
            for (int c = 0; c < 4; c++) acc[a][b][c] = 0.f;

    int nt = K / BK;

    #pragma unroll
    for (int s = 0; s < NSTAGE - 1; s++) {
        fill_stage(as_base + s * STGE * 2, bs_base + s * STGE * 2,
                   Ap, Bp, m0, n0, ldA, ldB, s * BK, tid);
        CPA_COMMIT();
    }
    asm volatile("cp.async.wait_group %0;" :: "n"(NSTAGE - 2) : "memory");
    __syncthreads();

    for (int tt = 0; tt < nt; tt++) {
        int fs = tt + NSTAGE - 1;
        if (fs < nt) {
            int st = fs % NSTAGE;
            fill_stage(as_base + st * STGE * 2, bs_base + st * STGE * 2,
                       Ap, Bp, m0, n0, ldA, ldB, fs * BK, tid);
        }
        CPA_COMMIT();

        int cs = tt % NSTAGE;
        compute_chunk(acc, as_base + cs * STGE * 2, bs_base + cs * STGE * 2,
                      a_row, a_koff, b_row, b_koff);

        asm volatile("cp.async.wait_group %0;" :: "n"(NSTAGE - 2) : "memory");
        __syncthreads();
    }

    const float* Rp = HAS_RES ? (resid + (long long)bz * sC) : nullptr;
    const float* Sp = HAS_RSC ? (rowsc + (long long)bz * sR) : nullptr;
    float* Cf = OUT_BF16 ? nullptr : ((float*)Cv + (long long)bz * sC);
    __nv_bfloat16* Ch = OUT_BF16 ? ((__nv_bfloat16*)Cv + (long long)bz * sC) : nullptr;

    #pragma unroll
    for (int mi = 0; mi < 2; mi++) {
        int mlo = m0 + wm + mi * 16 + g;
        int mhi = mlo + 8;
        float bmlo = (BIAS_MODE == 1) ? bias[mlo] : 0.f;
        float bmhi = (BIAS_MODE == 1) ? bias[mhi] : 0.f;
        float rlo = HAS_RSC ? Sp[mlo] : 1.f;
        float rhi = HAS_RSC ? Sp[mhi] : 1.f;
        #pragma unroll
        for (int ni = 0; ni < 8; ni++) {
            int col = n0 + wn + ni * 8 + 2 * t;
            float v00 = acc[mi][ni][0] * alpha + bmlo;
            float v01 = acc[mi][ni][1] * alpha + bmlo;
            float v10 = acc[mi][ni][2] * alpha + bmhi;
            float v11 = acc[mi][ni][3] * alpha + bmhi;
            if (HAS_EXP) {
                v00 = __expf(v00); v01 = __expf(v01);
                v10 = __expf(v10); v11 = __expf(v11);
            }
            if (HAS_RSC) {
                v00 *= rlo; v01 *= rlo;
                v10 *= rhi; v11 *= rhi;
            }
            long long olo = (long long)mlo * N + col;
            long long ohi = (long long)mhi * N + col;
            if (HAS_RES) {
                float2 r0 = *reinterpret_cast<const float2*>(&Rp[olo]);
                float2 r1 = *reinterpret_cast<const float2*>(&Rp[ohi]);
                v00 += r0.x; v01 += r0.y; v10 += r1.x; v11 += r1.y;
            }
            if (OUT_BF16) {
                __nv_bfloat162 plo(__float2bfloat16_rn(v00), __float2bfloat16_rn(v01));
                __nv_bfloat162 phi(__float2bfloat16_rn(v10), __float2bfloat16_rn(v11));
                *reinterpret_cast<__nv_bfloat162*>(&Ch[olo]) = plo;
                *reinterpret_cast<__nv_bfloat162*>(&Ch[ohi]) = phi;
            } else {
                *reinterpret_cast<float2*>(&Cf[olo]) = make_float2(v00, v01);
                *reinterpret_cast<float2*>(&Cf[ohi]) = make_float2(v10, v11);
            }
        }
    }
}

// ---------------------------------------------------------------------------
// Rowsum: warp per row over at (bf16, unnormalized exp); writes 1/sum fp32.
// ---------------------------------------------------------------------------
__global__ __launch_bounds__(256) void rowsum_kernel(
    const __nv_bfloat16* __restrict__ at, float* __restrict__ invs)
{
    int wid = threadIdx.x >> 5, lane = threadIdx.x & 31;
    int r = blockIdx.x * 8 + wid;
    const uint4* p = reinterpret_cast<const uint4*>(at + (long long)r * HW_) + lane;

    float s = 0.f;
    #pragma unroll
    for (int i = 0; i < 4; i++) {
        uint4 u = p[i * 32];
        const __nv_bfloat162* h = reinterpret_cast<const __nv_bfloat162*>(&u);
        #pragma unroll
        for (int j = 0; j < 4; j++) {
            float2 f = __bfloat1622float2(h[j]);
            s += f.x + f.y;
        }
    }
    s = warp_sum(s);
    if (lane == 0) invs[r] = 1.0f / s;
}

// ---------------------------------------------------------------------------
// Launch
// ---------------------------------------------------------------------------
extern "C" void kernel_launch(void* const* d_in, const int* in_sizes, int n_in,
                              void* d_out, int out_size)
{
    const float* x     = (const float*)d_in[0];
    const float* gamma = (const float*)d_in[1];
    const float* beta  = (const float*)d_in[2];
    const float* wq    = (const float*)d_in[3];
    const float* bq    = (const float*)d_in[4];
    const float* wk    = (const float*)d_in[5];
    const float* bk    = (const float*)d_in[6];
    const float* wv    = (const float*)d_in[7];
    const float* bv    = (const float*)d_in[8];
    const float* wp    = (const float*)d_in[9];
    const float* bp    = (const float*)d_in[10];
    float* out = (float*)d_out;

    __nv_bfloat16 *qt, *kt, *v, *at, *ot, *bwp;
    float* invs;
    cudaGetSymbolAddress((void**)&qt,   g_qt);
    cudaGetSymbolAddress((void**)&kt,   g_kt);
    cudaGetSymbolAddress((void**)&v,    g_v);
    cudaGetSymbolAddress((void**)&at,   g_at);
    cudaGetSymbolAddress((void**)&invs, g_s);
    cudaGetSymbolAddress((void**)&ot,   g_ot);
    cudaGetSymbolAddress((void**)&bwp,  g_wp);

    const long long sSC = (long long)HW_ * C_;
    const long long sHH = (long long)HW_ * HW_;
    const float scale = 1.0f / sqrtf((float)C_);

    cudaFuncSetAttribute(gn_t_kernel,
                         cudaFuncAttributeMaxDynamicSharedMemorySize, GN_SMEM);
    cudaFuncSetAttribute(qkv_gemm,
                         cudaFuncAttributeMaxDynamicSharedMemorySize, SMEM_BYTES);
    cudaFuncSetAttribute(bf_gemm<0, false, true, true, false>,
                         cudaFuncAttributeMaxDynamicSharedMemorySize, SMEM_BYTES);
    cudaFuncSetAttribute(bf_gemm<0, false, true, false, true>,
                         cudaFuncAttributeMaxDynamicSharedMemorySize, SMEM_BYTES);
    cudaFuncSetAttribute(bf_gemm<1, true, false, false, false>,
                         cudaFuncAttributeMaxDynamicSharedMemorySize, SMEM_BYTES);

    // 1) GroupNorm + transpose + weight conversion
    gn_t_kernel<<<B_ * NG_, 256, GN_SMEM>>>(x, gamma, beta, wq, wk, wv, wp);

    // 2) fused q_t / k_t / v
    dim3 gqkv(32, 1, 48);
    qkv_gemm<<<gqkv, 256, SMEM_BYTES>>>(bq, bk, bv);

    // 3) at[i,j] = exp(scale * q_t[i] . k_t[j])  (unnormalized, bf16)
    dim3 ge(HW_ / 128, HW_ / 128, B_);
    bf_gemm<0, false, true, true, false><<<ge, 256, SMEM_BYTES>>>(
        qt, kt, at, nullptr, nullptr, nullptr,
        C_, C_, C_, HW_, scale, sSC, sSC, sHH, 0);

    // 4) 1/rowsum
    rowsum_kernel<<<B_ * HW_ / 8, 256>>>(at, invs);

    // 5) o_t[i,c] = (at[i] . v[c]) * invs[i]
    dim3 go(C_ / 128, HW_ / 128, B_);
    bf_gemm<0, false, true, false, true><<<go, 256, SMEM_BYTES>>>(
        at, v, ot, nullptr, nullptr, invs,
        HW_, HW_, HW_, C_, 1.0f, sHH, sSC, sSC, HW_);

    // 6) out[o,s] = wp . o_t + bp + x
    dim3 gp(HW_ / 128, C_ / 128, B_);
    bf_gemm<1, true, false, false, false><<<gp, 256, SMEM_BYTES>>>(
        bwp, ot, out, bp, x, nullptr,
        C_, C_, C_, HW_, 1.0f, 0, sSC, sSC, 0);
}

// round 13
// speedup vs baseline: 1.1924x; 1.0062x over previous
#include <cuda_runtime.h>
#include <cuda_bf16.h>
#include <cstdint>
#include <math.h>

// ---------------------------------------------------------------------------
// Attention block, bf16 mma.sync pipeline.
// R13: rowsum folded into e-GEMM epilogue (atomicAdd per row); no rowsum pass.
// B=16, C=512, HW=1024, 32 groups, eps=1e-6
// ---------------------------------------------------------------------------

#define B_ 16
#define C_ 512
#define HW_ 1024
#define NG_ 32

__device__ __nv_bfloat16 g_xnt[(long long)B_ * HW_ * C_];
__device__ __nv_bfloat16 g_qt [(long long)B_ * HW_ * C_];
__device__ __nv_bfloat16 g_kt [(long long)B_ * HW_ * C_];
__device__ __nv_bfloat16 g_v  [(long long)B_ * C_ * HW_];
__device__ __nv_bfloat16 g_at [(long long)B_ * HW_ * HW_];   // exp(e), unnormalized
__device__ float         g_s  [B_ * HW_];                    // rowsum (atomic)
__device__ __nv_bfloat16 g_ot [(long long)B_ * HW_ * C_];
__device__ __nv_bfloat16 g_wq[C_ * C_], g_wk[C_ * C_], g_wv[C_ * C_], g_wp[C_ * C_];

__inline__ __device__ float warp_sum(float v) {
    #pragma unroll
    for (int o = 16; o > 0; o >>= 1) v += __shfl_xor_sync(0xffffffffu, v, o);
    return v;
}
__device__ __forceinline__ uint32_t smem_u32(const void* p) {
    uint32_t a;
    asm("{ .reg .u64 t; cvta.to.shared.u64 t, %1; cvt.u32.u64 %0, t; }"
        : "=r"(a) : "l"(p));
    return a;
}

#define CPA16(dst, src) \
    asm volatile("cp.async.cg.shared.global [%0], [%1], 16;" :: "r"(dst), "l"(src))
#define CPA_COMMIT() asm volatile("cp.async.commit_group;" ::: "memory")

#define LDSM4(R0, R1, R2, R3, addr) \
    asm volatile("ldmatrix.sync.aligned.m8n8.x4.shared.b16 {%0,%1,%2,%3}, [%4];" \
                 : "=r"(R0), "=r"(R1), "=r"(R2), "=r"(R3) : "r"(addr))

__device__ __forceinline__ void mma_bf16(float c[4], const uint32_t a[4],
                                         uint32_t b0, uint32_t b1) {
    asm volatile(
        "mma.sync.aligned.m16n8k16.row.col.f32.bf16.bf16.f32 "
        "{%0,%1,%2,%3}, {%4,%5,%6,%7}, {%8,%9}, {%0,%1,%2,%3};"
        : "+f"(c[0]), "+f"(c[1]), "+f"(c[2]), "+f"(c[3])
        : "r"(a[0]), "r"(a[1]), "r"(a[2]), "r"(a[3]), "r"(b0), "r"(b1));
}

// ---------------------------------------------------------------------------
// GEMM tiling constants (frozen config)
// ---------------------------------------------------------------------------
#define BK 64
#define ROWE 72
#define STGE (128 * ROWE)
#define NSTAGE 3
#define SMEM_BYTES (2 * NSTAGE * STGE * 2)

__device__ __forceinline__ void fill_stage(
    uint32_t abase, uint32_t bbase,
    const __nv_bfloat16* Ap, const __nv_bfloat16* Bp,
    int m0, int n0, int ldA, int ldB, int k0, int tid)
{
    #pragma unroll
    for (int i = 0; i < 4; i++) {
        int task = tid + i * 256;
        int row = task >> 3, kc = task & 7;
        CPA16(abase + (row * ROWE + kc * 8) * 2,
              Ap + (long long)(m0 + row) * ldA + k0 + kc * 8);
        CPA16(bbase + (row * ROWE + kc * 8) * 2,
              Bp + (long long)(n0 + row) * ldB + k0 + kc * 8);
    }
}

__device__ __forceinline__ void compute_chunk(
    float acc[2][8][4], uint32_t ab, uint32_t bb,
    int a_row, int a_koff, int b_row, int b_koff)
{
    #pragma unroll
    for (int ks = 0; ks < BK; ks += 16) {
        uint32_t afr[2][4];
        #pragma unroll
        for (int mi = 0; mi < 2; mi++) {
            uint32_t addr = ab + (((a_row + mi * 16) * ROWE) + ks + a_koff) * 2;
            LDSM4(afr[mi][0], afr[mi][1], afr[mi][2], afr[mi][3], addr);
        }
        uint32_t bcur[4], bnxt[4];
        {
            uint32_t addr = bb + ((b_row * ROWE) + ks + b_koff) * 2;
            LDSM4(bcur[0], bcur[1], bcur[2], bcur[3], addr);
        }
        #pragma unroll
        for (int np = 0; np < 4; np++) {
            if (np < 3) {
                uint32_t addr = bb +
                    (((b_row + (np + 1) * 16) * ROWE) + ks + b_koff) * 2;
                LDSM4(bnxt[0], bnxt[1], bnxt[2], bnxt[3], addr);
            }
            mma_bf16(acc[0][np * 2],     afr[0], bcur[0], bcur[1]);
            mma_bf16(acc[1][np * 2],     afr[1], bcur[0], bcur[1]);
            mma_bf16(acc[0][np * 2 + 1], afr[0], bcur[2], bcur[3]);
            mma_bf16(acc[1][np * 2 + 1], afr[1], bcur[2], bcur[3]);
            #pragma unroll
            for (int j = 0; j < 4; j++) bcur[j] = bnxt[j];
        }
    }
}

// ---------------------------------------------------------------------------
// GroupNorm + transpose, single global read (+ folded weight conversion)
// ---------------------------------------------------------------------------
__global__ void gn_t_kernel(const float* __restrict__ x,
                            const float* __restrict__ gamma,
                            const float* __restrict__ beta,
                            const float* __restrict__ wq,
                            const float* __restrict__ wk,
                            const float* __restrict__ wv,
                            const float* __restrict__ wp)
{
    extern __shared__ float sd[];
    const int GSZ = 16 * HW_;
    int bg = blockIdx.x;
    int b = bg >> 5, g = bg & 31;
    long long base = (long long)bg * GSZ;
    int tid = threadIdx.x;

    {
        int idx0 = bg * 2048 + tid * 4;
        #pragma unroll
        for (int h = 0; h < 2; h++) {
            int idx = idx0 + h * 1024;
            int m = idx >> 18;
            int off = idx & 0x3FFFF;
            const float* src = (m == 0) ? wq : (m == 1) ? wk : (m == 2) ? wv : wp;
            __nv_bfloat16* dst = (m == 0) ? g_wq : (m == 1) ? g_wk : (m == 2) ? g_wv : g_wp;
            float4 v4 = *reinterpret_cast<const float4*>(&src[off]);
            __nv_bfloat162 p0(__float2bfloat16_rn(v4.x), __float2bfloat16_rn(v4.y));
            __nv_bfloat162 p1(__float2bfloat16_rn(v4.z), __float2bfloat16_rn(v4.w));
            *reinterpret_cast<__nv_bfloat162*>(&dst[off])     = p0;
            *reinterpret_cast<__nv_bfloat162*>(&dst[off + 2]) = p1;
        }
    }

    float s = 0.f, sq = 0.f;
    for (int e = tid * 4; e < GSZ; e += 256 * 4) {
        float4 v4 = *reinterpret_cast<const float4*>(&x[base + e]);
        *reinterpret_cast<float4*>(&sd[e]) = v4;
        s  += v4.x + v4.y + v4.z + v4.w;
        sq += v4.x * v4.x + v4.y * v4.y + v4.z * v4.z + v4.w * v4.w;
    }
    __shared__ float shs[8], shq[8];
    s = warp_sum(s); sq = warp_sum(sq);
    int wid = tid >> 5, lid = tid & 31;
    if (lid == 0) { shs[wid] = s; shq[wid] = sq; }
    __syncthreads();
    if (wid == 0) {
        float a = (lid < 8) ? shs[lid] : 0.f;
        float bb = (lid < 8) ? shq[lid] : 0.f;
        a = warp_sum(a); bb = warp_sum(bb);
        if (lid == 0) { shs[0] = a; shq[0] = bb; }
    }
    __syncthreads();
    float mean = shs[0] / (float)GSZ;
    float var  = shq[0] / (float)GSZ - mean * mean;
    float inv  = rsqrtf(var + 1e-6f);

    float ga[16], be[16];
    #pragma unroll
    for (int c = 0; c < 16; c++) {
        ga[c] = gamma[g * 16 + c] * inv;
        be[c] = beta[g * 16 + c] - mean * ga[c];
    }

    #pragma unroll
    for (int s0 = 0; s0 < HW_; s0 += 256) {
        int sp = s0 + tid;
        union { __nv_bfloat16 h[16]; uint4 u[2]; } o;
        #pragma unroll
        for (int c = 0; c < 16; c++)
            o.h[c] = __float2bfloat16_rn(sd[c * HW_ + sp] * ga[c] + be[c]);
        uint4* dst = reinterpret_cast<uint4*>(
            &g_xnt[((long long)b * HW_ + sp) * C_ + g * 16]);
        dst[0] = o.u[0];
        dst[1] = o.u[1];
    }
}
#define GN_SMEM (16 * HW_ * 4)

// ---------------------------------------------------------------------------
// Fused QKV GEMM (unchanged)
// ---------------------------------------------------------------------------
__global__ __launch_bounds__(256, 2) void qkv_gemm(
    const float* __restrict__ bq, const float* __restrict__ bk,
    const float* __restrict__ bv)
{
    extern __shared__ __nv_bfloat16 dsm[];

    int tid = threadIdx.x, wid = tid >> 5, lane = tid & 31;
    int g = lane >> 2, t = lane & 3;
    int wm = (wid & 3) * 32;
    int wn = (wid >> 2) * 64;

    const long long sSC = (long long)HW_ * C_;
    int zz = blockIdx.z;
    int xx = blockIdx.x;

    const __nv_bfloat16 *Ap, *Bp;
    __nv_bfloat16* Co;
    const float* bi;
    int m0, n0, Nn;
    bool bias_col;
    if (zz < 32) {
        int b = zz & 15;
        Ap = g_xnt + (long long)b * sSC;
        Bp = (zz < 16) ? g_wq : g_wk;
        Co = ((zz < 16) ? g_qt : g_kt) + (long long)b * sSC;
        bi = (zz < 16) ? bq : bk;
        m0 = (xx >> 2) * 128;
        n0 = (xx & 3) * 128;
        Nn = C_;
        bias_col = true;
    } else {
        int b = zz - 32;
        Ap = g_wv;
        Bp = g_xnt + (long long)b * sSC;
        Co = g_v + (long long)b * sSC;
        bi = bv;
        m0 = (xx >> 3) * 128;
        n0 = (xx & 7) * 128;
        Nn = HW_;
        bias_col = false;
    }

    uint32_t as_base = smem_u32(dsm);
    uint32_t bs_base = as_base + NSTAGE * STGE * 2;

    int a_row = wm + (lane & 15);
    int a_koff = (lane >> 4) * 8;
    int b_row = wn + ((lane >> 4) << 3) + (lane & 7);
    int b_koff = ((lane >> 3) & 1) * 8;

    float acc[2][8][4];
    #pragma unroll
    for (int a = 0; a < 2; a++)
        #pragma unroll
        for (int b2 = 0; b2 < 8; b2++)
            #pragma unroll
            for (int c = 0; c < 4; c++) acc[a][b2][c] = 0.f;

    const int nt = C_ / BK;

    #pragma unroll
    for (int s = 0; s < NSTAGE - 1; s++) {
        fill_stage(as_base + s * STGE * 2, bs_base + s * STGE * 2,
                   Ap, Bp, m0, n0, C_, C_, s * BK, tid);
        CPA_COMMIT();
    }
    asm volatile("cp.async.wait_group %0;" :: "n"(NSTAGE - 2) : "memory");
    __syncthreads();

    for (int tt = 0; tt < nt; tt++) {
        int fs = tt + NSTAGE - 1;
        if (fs < nt) {
            int st = fs % NSTAGE;
            fill_stage(as_base + st * STGE * 2, bs_base + st * STGE * 2,
                       Ap, Bp, m0, n0, C_, C_, fs * BK, tid);
        }
        CPA_COMMIT();

        int cs = tt % NSTAGE;
        compute_chunk(acc, as_base + cs * STGE * 2, bs_base + cs * STGE * 2,
                      a_row, a_koff, b_row, b_koff);

        asm volatile("cp.async.wait_group %0;" :: "n"(NSTAGE - 2) : "memory");
        __syncthreads();
    }

    #pragma unroll
    for (int mi = 0; mi < 2; mi++) {
        int mlo = m0 + wm + mi * 16 + g;
        int mhi = mlo + 8;
        float bmlo = bias_col ? 0.f : bi[mlo];
        float bmhi = bias_col ? 0.f : bi[mhi];
        #pragma unroll
        for (int ni = 0; ni < 8; ni++) {
            int col = n0 + wn + ni * 8 + 2 * t;
            float bn0 = bias_col ? bi[col] : 0.f;
            float bn1 = bias_col ? bi[col + 1] : 0.f;
            float v00 = acc[mi][ni][0] + bmlo + bn0;
            float v01 = acc[mi][ni][1] + bmlo + bn1;
            float v10 = acc[mi][ni][2] + bmhi + bn0;
            float v11 = acc[mi][ni][3] + bmhi + bn1;
            long long olo = (long long)mlo * Nn + col;
            long long ohi = (long long)mhi * Nn + col;
            __nv_bfloat162 plo(__float2bfloat16_rn(v00), __float2bfloat16_rn(v01));
            __nv_bfloat162 phi(__float2bfloat16_rn(v10), __float2bfloat16_rn(v11));
            *reinterpret_cast<__nv_bfloat162*>(&Co[olo]) = plo;
            *reinterpret_cast<__nv_bfloat162*>(&Co[ohi]) = phi;
        }
    }
}

// ---------------------------------------------------------------------------
// Generic bf16 GEMM.
// HAS_EXP: val = __expf(acc*alpha), out bf16, atomic row-sum into rowsum_out.
// HAS_RSC: val = acc / rowsc[m], out bf16 (ot GEMM).
// BIAS_MODE=1 + HAS_RES: fp32 out (proj GEMM).
// ---------------------------------------------------------------------------
template<int BIAS_MODE, bool HAS_RES, bool OUT_BF16, bool HAS_EXP, bool HAS_RSC>
__global__ __launch_bounds__(256, 2) void bf_gemm(
    const __nv_bfloat16* __restrict__ A, const __nv_bfloat16* __restrict__ Bm,
    void* __restrict__ Cv, const float* __restrict__ bias,
    const float* __restrict__ resid, const float* __restrict__ rowsc,
    float* __restrict__ rowsum_out,
    int K, int ldA, int ldB, int N, float alpha,
    long long sA, long long sB, long long sC, long long sR)
{
    extern __shared__ __nv_bfloat16 dsm[];

    int tid = threadIdx.x, wid = tid >> 5, lane = tid & 31;
    int g = lane >> 2, t = lane & 3;
    int wm = (wid & 3) * 32;
    int wn = (wid >> 2) * 64;
    int n0 = blockIdx.x * 128;
    int m0 = blockIdx.y * 128;
    int bz = blockIdx.z;
    const __nv_bfloat16* Ap = A  + (long long)bz * sA;
    const __nv_bfloat16* Bp = Bm + (long long)bz * sB;

    uint32_t as_base = smem_u32(dsm);
    uint32_t bs_base = as_base + NSTAGE * STGE * 2;

    int a_row = wm + (lane & 15);
    int a_koff = (lane >> 4) * 8;
    int b_row = wn + ((lane >> 4) << 3) + (lane & 7);
    int b_koff = ((lane >> 3) & 1) * 8;

    float acc[2][8][4];
    #pragma unroll
    for (int a = 0; a < 2; a++)
        #pragma unroll
        for (int b = 0; b < 8; b++)
            #pragma unroll
            for (int c = 0; c < 4; c++) acc[a][b][c] = 0.f;

    int nt = K / BK;

    #pragma unroll
    for (int s = 0; s < NSTAGE - 1; s++) {
        fill_stage(as_base + s * STGE * 2, bs_base + s * STGE * 2,
                   Ap, Bp, m0, n0, ldA, ldB, s * BK, tid);
        CPA_COMMIT();
    }
    asm volatile("cp.async.wait_group %0;" :: "n"(NSTAGE - 2) : "memory");
    __syncthreads();

    for (int tt = 0; tt < nt; tt++) {
        int fs = tt + NSTAGE - 1;
        if (fs < nt) {
            int st = fs % NSTAGE;
            fill_stage(as_base + st * STGE * 2, bs_base + st * STGE * 2,
                       Ap, Bp, m0, n0, ldA, ldB, fs * BK, tid);
        }
        CPA_COMMIT();

        int cs = tt % NSTAGE;
        compute_chunk(acc, as_base + cs * STGE * 2, bs_base + cs * STGE * 2,
                      a_row, a_koff, b_row, b_koff);

        asm volatile("cp.async.wait_group %0;" :: "n"(NSTAGE - 2) : "memory");
        __syncthreads();
    }

    const float* Rp = HAS_RES ? (resid + (long long)bz * sC) : nullptr;
    const float* Sp = HAS_RSC ? (rowsc + (long long)bz * sR) : nullptr;
    float* So = HAS_EXP ? (rowsum_out + (long long)bz * sR) : nullptr;
    float* Cf = OUT_BF16 ? nullptr : ((float*)Cv + (long long)bz * sC);
    __nv_bfloat16* Ch = OUT_BF16 ? ((__nv_bfloat16*)Cv + (long long)bz * sC) : nullptr;

    #pragma unroll
    for (int mi = 0; mi < 2; mi++) {
        int mlo = m0 + wm + mi * 16 + g;
        int mhi = mlo + 8;
        float bmlo = (BIAS_MODE == 1) ? bias[mlo] : 0.f;
        float bmhi = (BIAS_MODE == 1) ? bias[mhi] : 0.f;
        float rlo = HAS_RSC ? (1.0f / Sp[mlo]) : 1.f;
        float rhi = HAS_RSC ? (1.0f / Sp[mhi]) : 1.f;
        float slo = 0.f, shi = 0.f;
        #pragma unroll
        for (int ni = 0; ni < 8; ni++) {
            int col = n0 + wn + ni * 8 + 2 * t;
            float v00 = acc[mi][ni][0] * alpha + bmlo;
            float v01 = acc[mi][ni][1] * alpha + bmlo;
            float v10 = acc[mi][ni][2] * alpha + bmhi;
            float v11 = acc[mi][ni][3] * alpha + bmhi;
            if (HAS_EXP) {
                v00 = __expf(v00); v01 = __expf(v01);
                v10 = __expf(v10); v11 = __expf(v11);
                slo += v00 + v01;
                shi += v10 + v11;
            }
            if (HAS_RSC) {
                v00 *= rlo; v01 *= rlo;
                v10 *= rhi; v11 *= rhi;
            }
            long long olo = (long long)mlo * N + col;
            long long ohi = (long long)mhi * N + col;
            if (HAS_RES) {
                float2 r0 = *reinterpret_cast<const float2*>(&Rp[olo]);
                float2 r1 = *reinterpret_cast<const float2*>(&Rp[ohi]);
                v00 += r0.x; v01 += r0.y; v10 += r1.x; v11 += r1.y;
            }
            if (OUT_BF16) {
                __nv_bfloat162 plo(__float2bfloat16_rn(v00), __float2bfloat16_rn(v01));
                __nv_bfloat162 phi(__float2bfloat16_rn(v10), __float2bfloat16_rn(v11));
                *reinterpret_cast<__nv_bfloat162*>(&Ch[olo]) = plo;
                *reinterpret_cast<__nv_bfloat162*>(&Ch[ohi]) = phi;
            } else {
                *reinterpret_cast<float2*>(&Cf[olo]) = make_float2(v00, v01);
                *reinterpret_cast<float2*>(&Cf[ohi]) = make_float2(v10, v11);
            }
        }
        if (HAS_EXP) {
            // reduce over t lanes (same row across t=0..3), then one atomic each
            slo += __shfl_xor_sync(0xffffffffu, slo, 1);
            slo += __shfl_xor_sync(0xffffffffu, slo, 2);
            shi += __shfl_xor_sync(0xffffffffu, shi, 1);
            shi += __shfl_xor_sync(0xffffffffu, shi, 2);
            if (t == 0) {
                atomicAdd(&So[mlo], slo);
                atomicAdd(&So[mhi], shi);
            }
        }
    }
}

// ---------------------------------------------------------------------------
// Launch
// ---------------------------------------------------------------------------
extern "C" void kernel_launch(void* const* d_in, const int* in_sizes, int n_in,
                              void* d_out, int out_size)
{
    const float* x     = (const float*)d_in[0];
    const float* gamma = (const float*)d_in[1];
    const float* beta  = (const float*)d_in[2];
    const float* wq    = (const float*)d_in[3];
    const float* bq    = (const float*)d_in[4];
    const float* wk    = (const float*)d_in[5];
    const float* bk    = (const float*)d_in[6];
    const float* wv    = (const float*)d_in[7];
    const float* bv    = (const float*)d_in[8];
    const float* wp    = (const float*)d_in[9];
    const float* bp    = (const float*)d_in[10];
    float* out = (float*)d_out;

    __nv_bfloat16 *qt, *kt, *v, *at, *ot, *bwp;
    float* rsum;
    cudaGetSymbolAddress((void**)&qt,   g_qt);
    cudaGetSymbolAddress((void**)&kt,   g_kt);
    cudaGetSymbolAddress((void**)&v,    g_v);
    cudaGetSymbolAddress((void**)&at,   g_at);
    cudaGetSymbolAddress((void**)&rsum, g_s);
    cudaGetSymbolAddress((void**)&ot,   g_ot);
    cudaGetSymbolAddress((void**)&bwp,  g_wp);

    const long long sSC = (long long)HW_ * C_;
    const long long sHH = (long long)HW_ * HW_;
    const float scale = 1.0f / sqrtf((float)C_);

    cudaFuncSetAttribute(gn_t_kernel,
                         cudaFuncAttributeMaxDynamicSharedMemorySize, GN_SMEM);
    cudaFuncSetAttribute(qkv_gemm,
                         cudaFuncAttributeMaxDynamicSharedMemorySize, SMEM_BYTES);
    cudaFuncSetAttribute(bf_gemm<0, false, true, true, false>,
                         cudaFuncAttributeMaxDynamicSharedMemorySize, SMEM_BYTES);
    cudaFuncSetAttribute(bf_gemm<0, false, true, false, true>,
                         cudaFuncAttributeMaxDynamicSharedMemorySize, SMEM_BYTES);
    cudaFuncSetAttribute(bf_gemm<1, true, false, false, false>,
                         cudaFuncAttributeMaxDynamicSharedMemorySize, SMEM_BYTES);

    // 0) zero the rowsum accumulator (graph-capturable async memset)
    cudaMemsetAsync(rsum, 0, B_ * HW_ * sizeof(float));

    // 1) GroupNorm + transpose + weight conversion
    gn_t_kernel<<<B_ * NG_, 256, GN_SMEM>>>(x, gamma, beta, wq, wk, wv, wp);

    // 2) fused q_t / k_t / v
    dim3 gqkv(32, 1, 48);
    qkv_gemm<<<gqkv, 256, SMEM_BYTES>>>(bq, bk, bv);

    // 3) at[i,j] = exp(scale * q_t[i] . k_t[j]) bf16 + atomic rowsums
    dim3 ge(HW_ / 128, HW_ / 128, B_);
    bf_gemm<0, false, true, true, false><<<ge, 256, SMEM_BYTES>>>(
        qt, kt, at, nullptr, nullptr, nullptr, rsum,
        C_, C_, C_, HW_, scale, sSC, sSC, sHH, HW_);

    // 4) o_t[i,c] = (at[i] . v[c]) / rowsum[i]
    dim3 go(C_ / 128, HW_ / 128, B_);
    bf_gemm<0, false, true, false, true><<<go, 256, SMEM_BYTES>>>(
        at, v, ot, nullptr, nullptr, rsum, nullptr,
        HW_, HW_, HW_, C_, 1.0f, sHH, sSC, sSC, HW_);

    // 5) out[o,s] = wp . o_t + bp + x
    dim3 gp(HW_ / 128, C_ / 128, B_);
    bf_gemm<1, true, false, false, false><<<gp, 256, SMEM_BYTES>>>(
        bwp, ot, out, bp, x, nullptr, nullptr,
        C_, C_, C_, HW_, 1.0f, 0, sSC, sSC, 0);
}

// round 14
// speedup vs baseline: 1.2033x; 1.0092x over previous
#include <cuda_runtime.h>
#include <cuda_bf16.h>
#include <cstdint>
#include <math.h>

// ---------------------------------------------------------------------------
// Attention block, bf16 mma.sync pipeline.
// R14: R13 frozen + 512-thread GroupNorm + guarded tail commits.
// B=16, C=512, HW=1024, 32 groups, eps=1e-6
// ---------------------------------------------------------------------------

#define B_ 16
#define C_ 512
#define HW_ 1024
#define NG_ 32

__device__ __nv_bfloat16 g_xnt[(long long)B_ * HW_ * C_];
__device__ __nv_bfloat16 g_qt [(long long)B_ * HW_ * C_];
__device__ __nv_bfloat16 g_kt [(long long)B_ * HW_ * C_];
__device__ __nv_bfloat16 g_v  [(long long)B_ * C_ * HW_];
__device__ __nv_bfloat16 g_at [(long long)B_ * HW_ * HW_];   // exp(e), unnormalized
__device__ float         g_s  [B_ * HW_];                    // rowsum (atomic)
__device__ __nv_bfloat16 g_ot [(long long)B_ * HW_ * C_];
__device__ __nv_bfloat16 g_wq[C_ * C_], g_wk[C_ * C_], g_wv[C_ * C_], g_wp[C_ * C_];

__inline__ __device__ float warp_sum(float v) {
    #pragma unroll
    for (int o = 16; o > 0; o >>= 1) v += __shfl_xor_sync(0xffffffffu, v, o);
    return v;
}
__device__ __forceinline__ uint32_t smem_u32(const void* p) {
    uint32_t a;
    asm("{ .reg .u64 t; cvta.to.shared.u64 t, %1; cvt.u32.u64 %0, t; }"
        : "=r"(a) : "l"(p));
    return a;
}

#define CPA16(dst, src) \
    asm volatile("cp.async.cg.shared.global [%0], [%1], 16;" :: "r"(dst), "l"(src))
#define CPA_COMMIT() asm volatile("cp.async.commit_group;" ::: "memory")

#define LDSM4(R0, R1, R2, R3, addr) \
    asm volatile("ldmatrix.sync.aligned.m8n8.x4.shared.b16 {%0,%1,%2,%3}, [%4];" \
                 : "=r"(R0), "=r"(R1), "=r"(R2), "=r"(R3) : "r"(addr))

__device__ __forceinline__ void mma_bf16(float c[4], const uint32_t a[4],
                                         uint32_t b0, uint32_t b1) {
    asm volatile(
        "mma.sync.aligned.m16n8k16.row.col.f32.bf16.bf16.f32 "
        "{%0,%1,%2,%3}, {%4,%5,%6,%7}, {%8,%9}, {%0,%1,%2,%3};"
        : "+f"(c[0]), "+f"(c[1]), "+f"(c[2]), "+f"(c[3])
        : "r"(a[0]), "r"(a[1]), "r"(a[2]), "r"(a[3]), "r"(b0), "r"(b1));
}

// ---------------------------------------------------------------------------
// GEMM tiling constants (frozen config)
// ---------------------------------------------------------------------------
#define BK 64
#define ROWE 72
#define STGE (128 * ROWE)
#define NSTAGE 3
#define SMEM_BYTES (2 * NSTAGE * STGE * 2)

__device__ __forceinline__ void fill_stage(
    uint32_t abase, uint32_t bbase,
    const __nv_bfloat16* Ap, const __nv_bfloat16* Bp,
    int m0, int n0, int ldA, int ldB, int k0, int tid)
{
    #pragma unroll
    for (int i = 0; i < 4; i++) {
        int task = tid + i * 256;
        int row = task >> 3, kc = task & 7;
        CPA16(abase + (row * ROWE + kc * 8) * 2,
              Ap + (long long)(m0 + row) * ldA + k0 + kc * 8);
        CPA16(bbase + (row * ROWE + kc * 8) * 2,
              Bp + (long long)(n0 + row) * ldB + k0 + kc * 8);
    }
}

__device__ __forceinline__ void compute_chunk(
    float acc[2][8][4], uint32_t ab, uint32_t bb,
    int a_row, int a_koff, int b_row, int b_koff)
{
    #pragma unroll
    for (int ks = 0; ks < BK; ks += 16) {
        uint32_t afr[2][4];
        #pragma unroll
        for (int mi = 0; mi < 2; mi++) {
            uint32_t addr = ab + (((a_row + mi * 16) * ROWE) + ks + a_koff) * 2;
            LDSM4(afr[mi][0], afr[mi][1], afr[mi][2], afr[mi][3], addr);
        }
        uint32_t bcur[4], bnxt[4];
        {
            uint32_t addr = bb + ((b_row * ROWE) + ks + b_koff) * 2;
            LDSM4(bcur[0], bcur[1], bcur[2], bcur[3], addr);
        }
        #pragma unroll
        for (int np = 0; np < 4; np++) {
            if (np < 3) {
                uint32_t addr = bb +
                    (((b_row + (np + 1) * 16) * ROWE) + ks + b_koff) * 2;
                LDSM4(bnxt[0], bnxt[1], bnxt[2], bnxt[3], addr);
            }
            mma_bf16(acc[0][np * 2],     afr[0], bcur[0], bcur[1]);
            mma_bf16(acc[1][np * 2],     afr[1], bcur[0], bcur[1]);
            mma_bf16(acc[0][np * 2 + 1], afr[0], bcur[2], bcur[3]);
            mma_bf16(acc[1][np * 2 + 1], afr[1], bcur[2], bcur[3]);
            #pragma unroll
            for (int j = 0; j < 4; j++) bcur[j] = bnxt[j];
        }
    }
}

// ---------------------------------------------------------------------------
// R14 GroupNorm: 512 threads, single global read (+ folded weight conversion)
// ---------------------------------------------------------------------------
__global__ __launch_bounds__(512) void gn_t_kernel(
    const float* __restrict__ x,
    const float* __restrict__ gamma,
    const float* __restrict__ beta,
    const float* __restrict__ wq,
    const float* __restrict__ wk,
    const float* __restrict__ wv,
    const float* __restrict__ wp)
{
    extern __shared__ float sd[];       // 16384 floats = 64KB
    const int GSZ = 16 * HW_;
    int bg = blockIdx.x;
    int b = bg >> 5, g = bg & 31;
    long long base = (long long)bg * GSZ;
    int tid = threadIdx.x;

    // folded weight conversion: 512 blocks x 2048 elems covers 4 x 512x512
    {
        int idx = bg * 2048 + tid * 4;
        int m = idx >> 18;
        int off = idx & 0x3FFFF;
        const float* src = (m == 0) ? wq : (m == 1) ? wk : (m == 2) ? wv : wp;
        __nv_bfloat16* dst = (m == 0) ? g_wq : (m == 1) ? g_wk : (m == 2) ? g_wv : g_wp;
        float4 v4 = *reinterpret_cast<const float4*>(&src[off]);
        __nv_bfloat162 p0(__float2bfloat16_rn(v4.x), __float2bfloat16_rn(v4.y));
        __nv_bfloat162 p1(__float2bfloat16_rn(v4.z), __float2bfloat16_rn(v4.w));
        *reinterpret_cast<__nv_bfloat162*>(&dst[off])     = p0;
        *reinterpret_cast<__nv_bfloat162*>(&dst[off + 2]) = p1;
    }

    // single pass: global -> smem, accumulating stats (8 float4 per thread)
    float s = 0.f, sq = 0.f;
    #pragma unroll
    for (int e = tid * 4; e < GSZ; e += 512 * 4) {
        float4 v4 = *reinterpret_cast<const float4*>(&x[base + e]);
        *reinterpret_cast<float4*>(&sd[e]) = v4;
        s  += v4.x + v4.y + v4.z + v4.w;
        sq += v4.x * v4.x + v4.y * v4.y + v4.z * v4.z + v4.w * v4.w;
    }
    __shared__ float shs[16], shq[16];
    s = warp_sum(s); sq = warp_sum(sq);
    int wid = tid >> 5, lid = tid & 31;
    if (lid == 0) { shs[wid] = s; shq[wid] = sq; }
    __syncthreads();
    if (wid == 0) {
        float a = (lid < 16) ? shs[lid] : 0.f;
        float bb = (lid < 16) ? shq[lid] : 0.f;
        a = warp_sum(a); bb = warp_sum(bb);
        if (lid == 0) { shs[0] = a; shq[0] = bb; }
    }
    __syncthreads();
    float mean = shs[0] / (float)GSZ;
    float var  = shq[0] / (float)GSZ - mean * mean;
    float inv  = rsqrtf(var + 1e-6f);

    float ga[16], be[16];
    #pragma unroll
    for (int c = 0; c < 16; c++) {
        ga[c] = gamma[g * 16 + c] * inv;
        be[c] = beta[g * 16 + c] - mean * ga[c];
    }

    // normalize + transpose out of smem (2 iterations at 512 threads)
    #pragma unroll
    for (int s0 = 0; s0 < HW_; s0 += 512) {
        int sp = s0 + tid;
        union { __nv_bfloat16 h[16]; uint4 u[2]; } o;
        #pragma unroll
        for (int c = 0; c < 16; c++)
            o.h[c] = __float2bfloat16_rn(sd[c * HW_ + sp] * ga[c] + be[c]);
        uint4* dst = reinterpret_cast<uint4*>(
            &g_xnt[((long long)b * HW_ + sp) * C_ + g * 16]);
        dst[0] = o.u[0];
        dst[1] = o.u[1];
    }
}
#define GN_SMEM (16 * HW_ * 4)

// ---------------------------------------------------------------------------
// Fused QKV GEMM (guarded tail commit)
// ---------------------------------------------------------------------------
__global__ __launch_bounds__(256, 2) void qkv_gemm(
    const float* __restrict__ bq, const float* __restrict__ bk,
    const float* __restrict__ bv)
{
    extern __shared__ __nv_bfloat16 dsm[];

    int tid = threadIdx.x, wid = tid >> 5, lane = tid & 31;
    int g = lane >> 2, t = lane & 3;
    int wm = (wid & 3) * 32;
    int wn = (wid >> 2) * 64;

    const long long sSC = (long long)HW_ * C_;
    int zz = blockIdx.z;
    int xx = blockIdx.x;

    const __nv_bfloat16 *Ap, *Bp;
    __nv_bfloat16* Co;
    const float* bi;
    int m0, n0, Nn;
    bool bias_col;
    if (zz < 32) {
        int b = zz & 15;
        Ap = g_xnt + (long long)b * sSC;
        Bp = (zz < 16) ? g_wq : g_wk;
        Co = ((zz < 16) ? g_qt : g_kt) + (long long)b * sSC;
        bi = (zz < 16) ? bq : bk;
        m0 = (xx >> 2) * 128;
        n0 = (xx & 3) * 128;
        Nn = C_;
        bias_col = true;
    } else {
        int b = zz - 32;
        Ap = g_wv;
        Bp = g_xnt + (long long)b * sSC;
        Co = g_v + (long long)b * sSC;
        bi = bv;
        m0 = (xx >> 3) * 128;
        n0 = (xx & 7) * 128;
        Nn = HW_;
        bias_col = false;
    }

    uint32_t as_base = smem_u32(dsm);
    uint32_t bs_base = as_base + NSTAGE * STGE * 2;

    int a_row = wm + (lane & 15);
    int a_koff = (lane >> 4) * 8;
    int b_row = wn + ((lane >> 4) << 3) + (lane & 7);
    int b_koff = ((lane >> 3) & 1) * 8;

    float acc[2][8][4];
    #pragma unroll
    for (int a = 0; a < 2; a++)
        #pragma unroll
        for (int b2 = 0; b2 < 8; b2++)
            #pragma unroll
            for (int c = 0; c < 4; c++) acc[a][b2][c] = 0.f;

    const int nt = C_ / BK;

    #pragma unroll
    for (int s = 0; s < NSTAGE - 1; s++) {
        fill_stage(as_base + s * STGE * 2, bs_base + s * STGE * 2,
                   Ap, Bp, m0, n0, C_, C_, s * BK, tid);
        CPA_COMMIT();
    }
    asm volatile("cp.async.wait_group %0;" :: "n"(NSTAGE - 2) : "memory");
    __syncthreads();

    for (int tt = 0; tt < nt; tt++) {
        int fs = tt + NSTAGE - 1;
        if (fs < nt) {
            int st = fs % NSTAGE;
            fill_stage(as_base + st * STGE * 2, bs_base + st * STGE * 2,
                       Ap, Bp, m0, n0, C_, C_, fs * BK, tid);
            CPA_COMMIT();
        }

        int cs = tt % NSTAGE;
        compute_chunk(acc, as_base + cs * STGE * 2, bs_base + cs * STGE * 2,
                      a_row, a_koff, b_row, b_koff);

        if (fs < nt)
            asm volatile("cp.async.wait_group %0;" :: "n"(NSTAGE - 2) : "memory");
        else
            asm volatile("cp.async.wait_group 0;" ::: "memory");
        __syncthreads();
    }

    #pragma unroll
    for (int mi = 0; mi < 2; mi++) {
        int mlo = m0 + wm + mi * 16 + g;
        int mhi = mlo + 8;
        float bmlo = bias_col ? 0.f : bi[mlo];
        float bmhi = bias_col ? 0.f : bi[mhi];
        #pragma unroll
        for (int ni = 0; ni < 8; ni++) {
            int col = n0 + wn + ni * 8 + 2 * t;
            float bn0 = bias_col ? bi[col] : 0.f;
            float bn1 = bias_col ? bi[col + 1] : 0.f;
            float v00 = acc[mi][ni][0] + bmlo + bn0;
            float v01 = acc[mi][ni][1] + bmlo + bn1;
            float v10 = acc[mi][ni][2] + bmhi + bn0;
            float v11 = acc[mi][ni][3] + bmhi + bn1;
            long long olo = (long long)mlo * Nn + col;
            long long ohi = (long long)mhi * Nn + col;
            __nv_bfloat162 plo(__float2bfloat16_rn(v00), __float2bfloat16_rn(v01));
            __nv_bfloat162 phi(__float2bfloat16_rn(v10), __float2bfloat16_rn(v11));
            *reinterpret_cast<__nv_bfloat162*>(&Co[olo]) = plo;
            *reinterpret_cast<__nv_bfloat162*>(&Co[ohi]) = phi;
        }
    }
}

// ---------------------------------------------------------------------------
// Generic bf16 GEMM. HAS_EXP: exp epilogue + atomic rowsum. HAS_RSC: divide
// by rowsum. BIAS_MODE=1 + HAS_RES: fp32 out (proj).
// ---------------------------------------------------------------------------
template<int BIAS_MODE, bool HAS_RES, bool OUT_BF16, bool HAS_EXP, bool HAS_RSC>
__global__ __launch_bounds__(256, 2) void bf_gemm(
    const __nv_bfloat16* __restrict__ A, const __nv_bfloat16* __restrict__ Bm,
    void* __restrict__ Cv, const float* __restrict__ bias,
    const float* __restrict__ resid, const float* __restrict__ rowsc,
    float* __restrict__ rowsum_out,
    int K, int ldA, int ldB, int N, float alpha,
    long long sA, long long sB, long long sC, long long sR)
{
    extern __shared__ __nv_bfloat16 dsm[];

    int tid = threadIdx.x, wid = tid >> 5, lane = tid & 31;
    int g = lane >> 2, t = lane & 3;
    int wm = (wid & 3) * 32;
    int wn = (wid >> 2) * 64;
    int n0 = blockIdx.x * 128;
    int m0 = blockIdx.y * 128;
    int bz = blockIdx.z;
    const __nv_bfloat16* Ap = A  + (long long)bz * sA;
    const __nv_bfloat16* Bp = Bm + (long long)bz * sB;

    uint32_t as_base = smem_u32(dsm);
    uint32_t bs_base = as_base + NSTAGE * STGE * 2;

    int a_row = wm + (lane & 15);
    int a_koff = (lane >> 4) * 8;
    int b_row = wn + ((lane >> 4) << 3) + (lane & 7);
    int b_koff = ((lane >> 3) & 1) * 8;

    float acc[2][8][4];
    #pragma unroll
    for (int a = 0; a < 2; a++)
        #pragma unroll
        for (int b = 0; b < 8; b++)
            #pragma unroll
            for (int c = 0; c < 4; c++) acc[a][b][c] = 0.f;

    int nt = K / BK;

    #pragma unroll
    for (int s = 0; s < NSTAGE - 1; s++) {
        fill_stage(as_base + s * STGE * 2, bs_base + s * STGE * 2,
                   Ap, Bp, m0, n0, ldA, ldB, s * BK, tid);
        CPA_COMMIT();
    }
    asm volatile("cp.async.wait_group %0;" :: "n"(NSTAGE - 2) : "memory");
    __syncthreads();

    for (int tt = 0; tt < nt; tt++) {
        int fs = tt + NSTAGE - 1;
        if (fs < nt) {
            int st = fs % NSTAGE;
            fill_stage(as_base + st * STGE * 2, bs_base + st * STGE * 2,
                       Ap, Bp, m0, n0, ldA, ldB, fs * BK, tid);
            CPA_COMMIT();
        }

        int cs = tt % NSTAGE;
        compute_chunk(acc, as_base + cs * STGE * 2, bs_base + cs * STGE * 2,
                      a_row, a_koff, b_row, b_koff);

        if (fs < nt)
            asm volatile("cp.async.wait_group %0;" :: "n"(NSTAGE - 2) : "memory");
        else
            asm volatile("cp.async.wait_group 0;" ::: "memory");
        __syncthreads();
    }

    const float* Rp = HAS_RES ? (resid + (long long)bz * sC) : nullptr;
    const float* Sp = HAS_RSC ? (rowsc + (long long)bz * sR) : nullptr;
    float* So = HAS_EXP ? (rowsum_out + (long long)bz * sR) : nullptr;
    float* Cf = OUT_BF16 ? nullptr : ((float*)Cv + (long long)bz * sC);
    __nv_bfloat16* Ch = OUT_BF16 ? ((__nv_bfloat16*)Cv + (long long)bz * sC) : nullptr;

    #pragma unroll
    for (int mi = 0; mi < 2; mi++) {
        int mlo = m0 + wm + mi * 16 + g;
        int mhi = mlo + 8;
        float bmlo = (BIAS_MODE == 1) ? bias[mlo] : 0.f;
        float bmhi = (BIAS_MODE == 1) ? bias[mhi] : 0.f;
        float rlo = HAS_RSC ? (1.0f / Sp[mlo]) : 1.f;
        float rhi = HAS_RSC ? (1.0f / Sp[mhi]) : 1.f;
        float slo = 0.f, shi = 0.f;
        #pragma unroll
        for (int ni = 0; ni < 8; ni++) {
            int col = n0 + wn + ni * 8 + 2 * t;
            float v00 = acc[mi][ni][0] * alpha + bmlo;
            float v01 = acc[mi][ni][1] * alpha + bmlo;
            float v10 = acc[mi][ni][2] * alpha + bmhi;
            float v11 = acc[mi][ni][3] * alpha + bmhi;
            if (HAS_EXP) {
                v00 = __expf(v00); v01 = __expf(v01);
                v10 = __expf(v10); v11 = __expf(v11);
                slo += v00 + v01;
                shi += v10 + v11;
            }
            if (HAS_RSC) {
                v00 *= rlo; v01 *= rlo;
                v10 *= rhi; v11 *= rhi;
            }
            long long olo = (long long)mlo * N + col;
            long long ohi = (long long)mhi * N + col;
            if (HAS_RES) {
                float2 r0 = *reinterpret_cast<const float2*>(&Rp[olo]);
                float2 r1 = *reinterpret_cast<const float2*>(&Rp[ohi]);
                v00 += r0.x; v01 += r0.y; v10 += r1.x; v11 += r1.y;
            }
            if (OUT_BF16) {
                __nv_bfloat162 plo(__float2bfloat16_rn(v00), __float2bfloat16_rn(v01));
                __nv_bfloat162 phi(__float2bfloat16_rn(v10), __float2bfloat16_rn(v11));
                *reinterpret_cast<__nv_bfloat162*>(&Ch[olo]) = plo;
                *reinterpret_cast<__nv_bfloat162*>(&Ch[ohi]) = phi;
            } else {
                *reinterpret_cast<float2*>(&Cf[olo]) = make_float2(v00, v01);
                *reinterpret_cast<float2*>(&Cf[ohi]) = make_float2(v10, v11);
            }
        }
        if (HAS_EXP) {
            slo += __shfl_xor_sync(0xffffffffu, slo, 1);
            slo += __shfl_xor_sync(0xffffffffu, slo, 2);
            shi += __shfl_xor_sync(0xffffffffu, shi, 1);
            shi += __shfl_xor_sync(0xffffffffu, shi, 2);
            if (t == 0) {
                atomicAdd(&So[mlo], slo);
                atomicAdd(&So[mhi], shi);
            }
        }
    }
}

// ---------------------------------------------------------------------------
// Launch
// ---------------------------------------------------------------------------
extern "C" void kernel_launch(void* const* d_in, const int* in_sizes, int n_in,
                              void* d_out, int out_size)
{
    const float* x     = (const float*)d_in[0];
    const float* gamma = (const float*)d_in[1];
    const float* beta  = (const float*)d_in[2];
    const float* wq    = (const float*)d_in[3];
    const float* bq    = (const float*)d_in[4];
    const float* wk    = (const float*)d_in[5];
    const float* bk    = (const float*)d_in[6];
    const float* wv    = (const float*)d_in[7];
    const float* bv    = (const float*)d_in[8];
    const float* wp    = (const float*)d_in[9];
    const float* bp    = (const float*)d_in[10];
    float* out = (float*)d_out;

    __nv_bfloat16 *qt, *kt, *v, *at, *ot, *bwp;
    float* rsum;
    cudaGetSymbolAddress((void**)&qt,   g_qt);
    cudaGetSymbolAddress((void**)&kt,   g_kt);
    cudaGetSymbolAddress((void**)&v,    g_v);
    cudaGetSymbolAddress((void**)&at,   g_at);
    cudaGetSymbolAddress((void**)&rsum, g_s);
    cudaGetSymbolAddress((void**)&ot,   g_ot);
    cudaGetSymbolAddress((void**)&bwp,  g_wp);

    const long long sSC = (long long)HW_ * C_;
    const long long sHH = (long long)HW_ * HW_;
    const float scale = 1.0f / sqrtf((float)C_);

    cudaFuncSetAttribute(gn_t_kernel,
                         cudaFuncAttributeMaxDynamicSharedMemorySize, GN_SMEM);
    cudaFuncSetAttribute(qkv_gemm,
                         cudaFuncAttributeMaxDynamicSharedMemorySize, SMEM_BYTES);
    cudaFuncSetAttribute(bf_gemm<0, false, true, true, false>,
                         cudaFuncAttributeMaxDynamicSharedMemorySize, SMEM_BYTES);
    cudaFuncSetAttribute(bf_gemm<0, false, true, false, true>,
                         cudaFuncAttributeMaxDynamicSharedMemorySize, SMEM_BYTES);
    cudaFuncSetAttribute(bf_gemm<1, true, false, false, false>,
                         cudaFuncAttributeMaxDynamicSharedMemorySize, SMEM_BYTES);

    // 0) zero the rowsum accumulator (graph-capturable async memset)
    cudaMemsetAsync(rsum, 0, B_ * HW_ * sizeof(float));

    // 1) GroupNorm + transpose + weight conversion (512 threads)
    gn_t_kernel<<<B_ * NG_, 512, GN_SMEM>>>(x, gamma, beta, wq, wk, wv, wp);

    // 2) fused q_t / k_t / v
    dim3 gqkv(32, 1, 48);
    qkv_gemm<<<gqkv, 256, SMEM_BYTES>>>(bq, bk, bv);

    // 3) at[i,j] = exp(scale * q_t[i] . k_t[j]) bf16 + atomic rowsums
    dim3 ge(HW_ / 128, HW_ / 128, B_);
    bf_gemm<0, false, true, true, false><<<ge, 256, SMEM_BYTES>>>(
        qt, kt, at, nullptr, nullptr, nullptr, rsum,
        C_, C_, C_, HW_, scale, sSC, sSC, sHH, HW_);

    // 4) o_t[i,c] = (at[i] . v[c]) / rowsum[i]
    dim3 go(C_ / 128, HW_ / 128, B_);
    bf_gemm<0, false, true, false, true><<<go, 256, SMEM_BYTES>>>(
        at, v, ot, nullptr, nullptr, rsum, nullptr,
        HW_, HW_, HW_, C_, 1.0f, sHH, sSC, sSC, HW_);

    // 5) out[o,s] = wp . o_t + bp + x
    dim3 gp(HW_ / 128, C_ / 128, B_);
    bf_gemm<1, true, false, false, false><<<gp, 256, SMEM_BYTES>>>(
        bwp, ot, out, bp, x, nullptr, nullptr,
        C_, C_, C_, HW_, 1.0f, 0, sSC, sSC, 0);
}

// round 15
// speedup vs baseline: 1.2290x; 1.0214x over previous
#include <cuda_runtime.h>
#include <cuda_bf16.h>
#include <cstdint>
#include <math.h>

// ---------------------------------------------------------------------------
// Attention block, bf16 mma.sync pipeline.
// R15: R14 frozen + programmatic dependent launch (PDL) across the chain.
// B=16, C=512, HW=1024, 32 groups, eps=1e-6
// ---------------------------------------------------------------------------

#define B_ 16
#define C_ 512
#define HW_ 1024
#define NG_ 32

__device__ __nv_bfloat16 g_xnt[(long long)B_ * HW_ * C_];
__device__ __nv_bfloat16 g_qt [(long long)B_ * HW_ * C_];
__device__ __nv_bfloat16 g_kt [(long long)B_ * HW_ * C_];
__device__ __nv_bfloat16 g_v  [(long long)B_ * C_ * HW_];
__device__ __nv_bfloat16 g_at [(long long)B_ * HW_ * HW_];   // exp(e), unnormalized
__device__ float         g_s  [B_ * HW_];                    // rowsum (atomic)
__device__ __nv_bfloat16 g_ot [(long long)B_ * HW_ * C_];
__device__ __nv_bfloat16 g_wq[C_ * C_], g_wk[C_ * C_], g_wv[C_ * C_], g_wp[C_ * C_];

__inline__ __device__ float warp_sum(float v) {
    #pragma unroll
    for (int o = 16; o > 0; o >>= 1) v += __shfl_xor_sync(0xffffffffu, v, o);
    return v;
}
__device__ __forceinline__ uint32_t smem_u32(const void* p) {
    uint32_t a;
    asm("{ .reg .u64 t; cvta.to.shared.u64 t, %1; cvt.u32.u64 %0, t; }"
        : "=r"(a) : "l"(p));
    return a;
}
// PDL primitives
__device__ __forceinline__ void gdc_launch() {
    asm volatile("griddepcontrol.launch_dependents;");
}
__device__ __forceinline__ void gdc_wait() {
    asm volatile("griddepcontrol.wait;" ::: "memory");
}

#define CPA16(dst, src) \
    asm volatile("cp.async.cg.shared.global [%0], [%1], 16;" :: "r"(dst), "l"(src))
#define CPA_COMMIT() asm volatile("cp.async.commit_group;" ::: "memory")

#define LDSM4(R0, R1, R2, R3, addr) \
    asm volatile("ldmatrix.sync.aligned.m8n8.x4.shared.b16 {%0,%1,%2,%3}, [%4];" \
                 : "=r"(R0), "=r"(R1), "=r"(R2), "=r"(R3) : "r"(addr))

__device__ __forceinline__ void mma_bf16(float c[4], const uint32_t a[4],
                                         uint32_t b0, uint32_t b1) {
    asm volatile(
        "mma.sync.aligned.m16n8k16.row.col.f32.bf16.bf16.f32 "
        "{%0,%1,%2,%3}, {%4,%5,%6,%7}, {%8,%9}, {%0,%1,%2,%3};"
        : "+f"(c[0]), "+f"(c[1]), "+f"(c[2]), "+f"(c[3])
        : "r"(a[0]), "r"(a[1]), "r"(a[2]), "r"(a[3]), "r"(b0), "r"(b1));
}

// ---------------------------------------------------------------------------
// GEMM tiling constants (frozen config)
// ---------------------------------------------------------------------------
#define BK 64
#define ROWE 72
#define STGE (128 * ROWE)
#define NSTAGE 3
#define SMEM_BYTES (2 * NSTAGE * STGE * 2)

__device__ __forceinline__ void fill_stage(
    uint32_t abase, uint32_t bbase,
    const __nv_bfloat16* Ap, const __nv_bfloat16* Bp,
    int m0, int n0, int ldA, int ldB, int k0, int tid)
{
    #pragma unroll
    for (int i = 0; i < 4; i++) {
        int task = tid + i * 256;
        int row = task >> 3, kc = task & 7;
        CPA16(abase + (row * ROWE + kc * 8) * 2,
              Ap + (long long)(m0 + row) * ldA + k0 + kc * 8);
        CPA16(bbase + (row * ROWE + kc * 8) * 2,
              Bp + (long long)(n0 + row) * ldB + k0 + kc * 8);
    }
}

__device__ __forceinline__ void compute_chunk(
    float acc[2][8][4], uint32_t ab, uint32_t bb,
    int a_row, int a_koff, int b_row, int b_koff)
{
    #pragma unroll
    for (int ks = 0; ks < BK; ks += 16) {
        uint32_t afr[2][4];
        #pragma unroll
        for (int mi = 0; mi < 2; mi++) {
            uint32_t addr = ab + (((a_row + mi * 16) * ROWE) + ks + a_koff) * 2;
            LDSM4(afr[mi][0], afr[mi][1], afr[mi][2], afr[mi][3], addr);
        }
        uint32_t bcur[4], bnxt[4];
        {
            uint32_t addr = bb + ((b_row * ROWE) + ks + b_koff) * 2;
            LDSM4(bcur[0], bcur[1], bcur[2], bcur[3], addr);
        }
        #pragma unroll
        for (int np = 0; np < 4; np++) {
            if (np < 3) {
                uint32_t addr = bb +
                    (((b_row + (np + 1) * 16) * ROWE) + ks + b_koff) * 2;
                LDSM4(bnxt[0], bnxt[1], bnxt[2], bnxt[3], addr);
            }
            mma_bf16(acc[0][np * 2],     afr[0], bcur[0], bcur[1]);
            mma_bf16(acc[1][np * 2],     afr[1], bcur[0], bcur[1]);
            mma_bf16(acc[0][np * 2 + 1], afr[0], bcur[2], bcur[3]);
            mma_bf16(acc[1][np * 2 + 1], afr[1], bcur[2], bcur[3]);
            #pragma unroll
            for (int j = 0; j < 4; j++) bcur[j] = bnxt[j];
        }
    }
}

// ---------------------------------------------------------------------------
// GroupNorm: 512 threads, single global read (+ folded weight conversion)
// ---------------------------------------------------------------------------
__global__ __launch_bounds__(512) void gn_t_kernel(
    const float* __restrict__ x,
    const float* __restrict__ gamma,
    const float* __restrict__ beta,
    const float* __restrict__ wq,
    const float* __restrict__ wk,
    const float* __restrict__ wv,
    const float* __restrict__ wp)
{
    extern __shared__ float sd[];
    const int GSZ = 16 * HW_;
    int bg = blockIdx.x;
    int b = bg >> 5, g = bg & 31;
    long long base = (long long)bg * GSZ;
    int tid = threadIdx.x;

    gdc_launch();
    gdc_wait();   // predecessor: rsum memset (untouched here; trivial)

    {
        int idx = bg * 2048 + tid * 4;
        int m = idx >> 18;
        int off = idx & 0x3FFFF;
        const float* src = (m == 0) ? wq : (m == 1) ? wk : (m == 2) ? wv : wp;
        __nv_bfloat16* dst = (m == 0) ? g_wq : (m == 1) ? g_wk : (m == 2) ? g_wv : g_wp;
        float4 v4 = *reinterpret_cast<const float4*>(&src[off]);
        __nv_bfloat162 p0(__float2bfloat16_rn(v4.x), __float2bfloat16_rn(v4.y));
        __nv_bfloat162 p1(__float2bfloat16_rn(v4.z), __float2bfloat16_rn(v4.w));
        *reinterpret_cast<__nv_bfloat162*>(&dst[off])     = p0;
        *reinterpret_cast<__nv_bfloat162*>(&dst[off + 2]) = p1;
    }

    float s = 0.f, sq = 0.f;
    #pragma unroll
    for (int e = tid * 4; e < GSZ; e += 512 * 4) {
        float4 v4 = *reinterpret_cast<const float4*>(&x[base + e]);
        *reinterpret_cast<float4*>(&sd[e]) = v4;
        s  += v4.x + v4.y + v4.z + v4.w;
        sq += v4.x * v4.x + v4.y * v4.y + v4.z * v4.z + v4.w * v4.w;
    }
    __shared__ float shs[16], shq[16];
    s = warp_sum(s); sq = warp_sum(sq);
    int wid = tid >> 5, lid = tid & 31;
    if (lid == 0) { shs[wid] = s; shq[wid] = sq; }
    __syncthreads();
    if (wid == 0) {
        float a = (lid < 16) ? shs[lid] : 0.f;
        float bb = (lid < 16) ? shq[lid] : 0.f;
        a = warp_sum(a); bb = warp_sum(bb);
        if (lid == 0) { shs[0] = a; shq[0] = bb; }
    }
    __syncthreads();
    float mean = shs[0] / (float)GSZ;
    float var  = shq[0] / (float)GSZ - mean * mean;
    float inv  = rsqrtf(var + 1e-6f);

    float ga[16], be[16];
    #pragma unroll
    for (int c = 0; c < 16; c++) {
        ga[c] = gamma[g * 16 + c] * inv;
        be[c] = beta[g * 16 + c] - mean * ga[c];
    }

    #pragma unroll
    for (int s0 = 0; s0 < HW_; s0 += 512) {
        int sp = s0 + tid;
        union { __nv_bfloat16 h[16]; uint4 u[2]; } o;
        #pragma unroll
        for (int c = 0; c < 16; c++)
            o.h[c] = __float2bfloat16_rn(sd[c * HW_ + sp] * ga[c] + be[c]);
        uint4* dst = reinterpret_cast<uint4*>(
            &g_xnt[((long long)b * HW_ + sp) * C_ + g * 16]);
        dst[0] = o.u[0];
        dst[1] = o.u[1];
    }
}
#define GN_SMEM (16 * HW_ * 4)

// ---------------------------------------------------------------------------
// Fused QKV GEMM
// ---------------------------------------------------------------------------
__global__ __launch_bounds__(256, 2) void qkv_gemm(
    const float* __restrict__ bq, const float* __restrict__ bk,
    const float* __restrict__ bv)
{
    extern __shared__ __nv_bfloat16 dsm[];

    int tid = threadIdx.x, wid = tid >> 5, lane = tid & 31;
    int g = lane >> 2, t = lane & 3;
    int wm = (wid & 3) * 32;
    int wn = (wid >> 2) * 64;

    const long long sSC = (long long)HW_ * C_;
    int zz = blockIdx.z;
    int xx = blockIdx.x;

    gdc_launch();

    const __nv_bfloat16 *Ap, *Bp;
    __nv_bfloat16* Co;
    const float* bi;
    int m0, n0, Nn;
    bool bias_col;
    if (zz < 32) {
        int b = zz & 15;
        Ap = g_xnt + (long long)b * sSC;
        Bp = (zz < 16) ? g_wq : g_wk;
        Co = ((zz < 16) ? g_qt : g_kt) + (long long)b * sSC;
        bi = (zz < 16) ? bq : bk;
        m0 = (xx >> 2) * 128;
        n0 = (xx & 3) * 128;
        Nn = C_;
        bias_col = true;
    } else {
        int b = zz - 32;
        Ap = g_wv;
        Bp = g_xnt + (long long)b * sSC;
        Co = g_v + (long long)b * sSC;
        bi = bv;
        m0 = (xx >> 3) * 128;
        n0 = (xx & 7) * 128;
        Nn = HW_;
        bias_col = false;
    }

    uint32_t as_base = smem_u32(dsm);
    uint32_t bs_base = as_base + NSTAGE * STGE * 2;

    int a_row = wm + (lane & 15);
    int a_koff = (lane >> 4) * 8;
    int b_row = wn + ((lane >> 4) << 3) + (lane & 7);
    int b_koff = ((lane >> 3) & 1) * 8;

    float acc[2][8][4];
    #pragma unroll
    for (int a = 0; a < 2; a++)
        #pragma unroll
        for (int b2 = 0; b2 < 8; b2++)
            #pragma unroll
            for (int c = 0; c < 4; c++) acc[a][b2][c] = 0.f;

    const int nt = C_ / BK;

    gdc_wait();   // xnt / converted weights must be visible

    #pragma unroll
    for (int s = 0; s < NSTAGE - 1; s++) {
        fill_stage(as_base + s * STGE * 2, bs_base + s * STGE * 2,
                   Ap, Bp, m0, n0, C_, C_, s * BK, tid);
        CPA_COMMIT();
    }
    asm volatile("cp.async.wait_group %0;" :: "n"(NSTAGE - 2) : "memory");
    __syncthreads();

    for (int tt = 0; tt < nt; tt++) {
        int fs = tt + NSTAGE - 1;
        if (fs < nt) {
            int st = fs % NSTAGE;
            fill_stage(as_base + st * STGE * 2, bs_base + st * STGE * 2,
                       Ap, Bp, m0, n0, C_, C_, fs * BK, tid);
            CPA_COMMIT();
        }

        int cs = tt % NSTAGE;
        compute_chunk(acc, as_base + cs * STGE * 2, bs_base + cs * STGE * 2,
                      a_row, a_koff, b_row, b_koff);

        if (fs < nt)
            asm volatile("cp.async.wait_group %0;" :: "n"(NSTAGE - 2) : "memory");
        else
            asm volatile("cp.async.wait_group 0;" ::: "memory");
        __syncthreads();
    }

    #pragma unroll
    for (int mi = 0; mi < 2; mi++) {
        int mlo = m0 + wm + mi * 16 + g;
        int mhi = mlo + 8;
        float bmlo = bias_col ? 0.f : bi[mlo];
        float bmhi = bias_col ? 0.f : bi[mhi];
        #pragma unroll
        for (int ni = 0; ni < 8; ni++) {
            int col = n0 + wn + ni * 8 + 2 * t;
            float bn0 = bias_col ? bi[col] : 0.f;
            float bn1 = bias_col ? bi[col + 1] : 0.f;
            float v00 = acc[mi][ni][0] + bmlo + bn0;
            float v01 = acc[mi][ni][1] + bmlo + bn1;
            float v10 = acc[mi][ni][2] + bmhi + bn0;
            float v11 = acc[mi][ni][3] + bmhi + bn1;
            long long olo = (long long)mlo * Nn + col;
            long long ohi = (long long)mhi * Nn + col;
            __nv_bfloat162 plo(__float2bfloat16_rn(v00), __float2bfloat16_rn(v01));
            __nv_bfloat162 phi(__float2bfloat16_rn(v10), __float2bfloat16_rn(v11));
            *reinterpret_cast<__nv_bfloat162*>(&Co[olo]) = plo;
            *reinterpret_cast<__nv_bfloat162*>(&Co[ohi]) = phi;
        }
    }
}

// ---------------------------------------------------------------------------
// Generic bf16 GEMM. HAS_EXP: exp epilogue + atomic rowsum. HAS_RSC: divide
// by rowsum. BIAS_MODE=1 + HAS_RES: fp32 out (proj).
// ---------------------------------------------------------------------------
template<int BIAS_MODE, bool HAS_RES, bool OUT_BF16, bool HAS_EXP, bool HAS_RSC>
__global__ __launch_bounds__(256, 2) void bf_gemm(
    const __nv_bfloat16* __restrict__ A, const __nv_bfloat16* __restrict__ Bm,
    void* __restrict__ Cv, const float* __restrict__ bias,
    const float* __restrict__ resid, const float* __restrict__ rowsc,
    float* __restrict__ rowsum_out,
    int K, int ldA, int ldB, int N, float alpha,
    long long sA, long long sB, long long sC, long long sR)
{
    extern __shared__ __nv_bfloat16 dsm[];

    int tid = threadIdx.x, wid = tid >> 5, lane = tid & 31;
    int g = lane >> 2, t = lane & 3;
    int wm = (wid & 3) * 32;
    int wn = (wid >> 2) * 64;
    int n0 = blockIdx.x * 128;
    int m0 = blockIdx.y * 128;
    int bz = blockIdx.z;

    gdc_launch();

    const __nv_bfloat16* Ap = A  + (long long)bz * sA;
    const __nv_bfloat16* Bp = Bm + (long long)bz * sB;

    uint32_t as_base = smem_u32(dsm);
    uint32_t bs_base = as_base + NSTAGE * STGE * 2;

    int a_row = wm + (lane & 15);
    int a_koff = (lane >> 4) * 8;
    int b_row = wn + ((lane >> 4) << 3) + (lane & 7);
    int b_koff = ((lane >> 3) & 1) * 8;

    float acc[2][8][4];
    #pragma unroll
    for (int a = 0; a < 2; a++)
        #pragma unroll
        for (int b = 0; b < 8; b++)
            #pragma unroll
            for (int c = 0; c < 4; c++) acc[a][b][c] = 0.f;

    int nt = K / BK;

    gdc_wait();   // producer outputs must be visible

    #pragma unroll
    for (int s = 0; s < NSTAGE - 1; s++) {
        fill_stage(as_base + s * STGE * 2, bs_base + s * STGE * 2,
                   Ap, Bp, m0, n0, ldA, ldB, s * BK, tid);
        CPA_COMMIT();
    }
    asm volatile("cp.async.wait_group %0;" :: "n"(NSTAGE - 2) : "memory");
    __syncthreads();

    for (int tt = 0; tt < nt; tt++) {
        int fs = tt + NSTAGE - 1;
        if (fs < nt) {
            int st = fs % NSTAGE;
            fill_stage(as_base + st * STGE * 2, bs_base + st * STGE * 2,
                       Ap, Bp, m0, n0, ldA, ldB, fs * BK, tid);
            CPA_COMMIT();
        }

        int cs = tt % NSTAGE;
        compute_chunk(acc, as_base + cs * STGE * 2, bs_base + cs * STGE * 2,
                      a_row, a_koff, b_row, b_koff);

        if (fs < nt)
            asm volatile("cp.async.wait_group %0;" :: "n"(NSTAGE - 2) : "memory");
        else
            asm volatile("cp.async.wait_group 0;" ::: "memory");
        __syncthreads();
    }

    const float* Rp = HAS_RES ? (resid + (long long)bz * sC) : nullptr;
    const float* Sp = HAS_RSC ? (rowsc + (long long)bz * sR) : nullptr;
    float* So = HAS_EXP ? (rowsum_out + (long long)bz * sR) : nullptr;
    float* Cf = OUT_BF16 ? nullptr : ((float*)Cv + (long long)bz * sC);
    __nv_bfloat16* Ch = OUT_BF16 ? ((__nv_bfloat16*)Cv + (long long)bz * sC) : nullptr;

    #pragma unroll
    for (int mi = 0; mi < 2; mi++) {
        int mlo = m0 + wm + mi * 16 + g;
        int mhi = mlo + 8;
        float bmlo = (BIAS_MODE == 1) ? bias[mlo] : 0.f;
        float bmhi = (BIAS_MODE == 1) ? bias[mhi] : 0.f;
        float rlo = HAS_RSC ? (1.0f / Sp[mlo]) : 1.f;
        float rhi = HAS_RSC ? (1.0f / Sp[mhi]) : 1.f;
        float slo = 0.f, shi = 0.f;
        #pragma unroll
        for (int ni = 0; ni < 8; ni++) {
            int col = n0 + wn + ni * 8 + 2 * t;
            float v00 = acc[mi][ni][0] * alpha + bmlo;
            float v01 = acc[mi][ni][1] * alpha + bmlo;
            float v10 = acc[mi][ni][2] * alpha + bmhi;
            float v11 = acc[mi][ni][3] * alpha + bmhi;
            if (HAS_EXP) {
                v00 = __expf(v00); v01 = __expf(v01);
                v10 = __expf(v10); v11 = __expf(v11);
                slo += v00 + v01;
                shi += v10 + v11;
            }
            if (HAS_RSC) {
                v00 *= rlo; v01 *= rlo;
                v10 *= rhi; v11 *= rhi;
            }
            long long olo = (long long)mlo * N + col;
            long long ohi = (long long)mhi * N + col;
            if (HAS_RES) {
                float2 r0 = *reinterpret_cast<const float2*>(&Rp[olo]);
                float2 r1 = *reinterpret_cast<const float2*>(&Rp[ohi]);
                v00 += r0.x; v01 += r0.y; v10 += r1.x; v11 += r1.y;
            }
            if (OUT_BF16) {
                __nv_bfloat162 plo(__float2bfloat16_rn(v00), __float2bfloat16_rn(v01));
                __nv_bfloat162 phi(__float2bfloat16_rn(v10), __float2bfloat16_rn(v11));
                *reinterpret_cast<__nv_bfloat162*>(&Ch[olo]) = plo;
                *reinterpret_cast<__nv_bfloat162*>(&Ch[ohi]) = phi;
            } else {
                *reinterpret_cast<float2*>(&Cf[olo]) = make_float2(v00, v01);
                *reinterpret_cast<float2*>(&Cf[ohi]) = make_float2(v10, v11);
            }
        }
        if (HAS_EXP) {
            slo += __shfl_xor_sync(0xffffffffu, slo, 1);
            slo += __shfl_xor_sync(0xffffffffu, slo, 2);
            shi += __shfl_xor_sync(0xffffffffu, shi, 1);
            shi += __shfl_xor_sync(0xffffffffu, shi, 2);
            if (t == 0) {
                atomicAdd(&So[mlo], slo);
                atomicAdd(&So[mhi], shi);
            }
        }
    }
}

// ---------------------------------------------------------------------------
// Launch (PDL-attributed launches via cudaLaunchKernelEx)
// ---------------------------------------------------------------------------
extern "C" void kernel_launch(void* const* d_in, const int* in_sizes, int n_in,
                              void* d_out, int out_size)
{
    const float* x     = (const float*)d_in[0];
    const float* gamma = (const float*)d_in[1];
    const float* beta  = (const float*)d_in[2];
    const float* wq    = (const float*)d_in[3];
    const float* bq    = (const float*)d_in[4];
    const float* wk    = (const float*)d_in[5];
    const float* bk    = (const float*)d_in[6];
    const float* wv    = (const float*)d_in[7];
    const float* bv    = (const float*)d_in[8];
    const float* wp    = (const float*)d_in[9];
    const float* bp    = (const float*)d_in[10];
    float* out = (float*)d_out;

    __nv_bfloat16 *qt, *kt, *v, *at, *ot, *bwp;
    float* rsum;
    cudaGetSymbolAddress((void**)&qt,   g_qt);
    cudaGetSymbolAddress((void**)&kt,   g_kt);
    cudaGetSymbolAddress((void**)&v,    g_v);
    cudaGetSymbolAddress((void**)&at,   g_at);
    cudaGetSymbolAddress((void**)&rsum, g_s);
    cudaGetSymbolAddress((void**)&ot,   g_ot);
    cudaGetSymbolAddress((void**)&bwp,  g_wp);

    const long long sSC = (long long)HW_ * C_;
    const long long sHH = (long long)HW_ * HW_;
    const float scale = 1.0f / sqrtf((float)C_);

    cudaFuncSetAttribute(gn_t_kernel,
                         cudaFuncAttributeMaxDynamicSharedMemorySize, GN_SMEM);
    cudaFuncSetAttribute(qkv_gemm,
                         cudaFuncAttributeMaxDynamicSharedMemorySize, SMEM_BYTES);
    cudaFuncSetAttribute(bf_gemm<0, false, true, true, false>,
                         cudaFuncAttributeMaxDynamicSharedMemorySize, SMEM_BYTES);
    cudaFuncSetAttribute(bf_gemm<0, false, true, false, true>,
                         cudaFuncAttributeMaxDynamicSharedMemorySize, SMEM_BYTES);
    cudaFuncSetAttribute(bf_gemm<1, true, false, false, false>,
                         cudaFuncAttributeMaxDynamicSharedMemorySize, SMEM_BYTES);

    cudaLaunchAttribute pdl[1];
    pdl[0].id = cudaLaunchAttributeProgrammaticStreamSerialization;
    pdl[0].val.programmaticStreamSerializationAllowed = 1;

    // 0) zero the rowsum accumulator
    cudaMemsetAsync(rsum, 0, B_ * HW_ * sizeof(float));

    // 1) GroupNorm + transpose + weight conversion
    {
        cudaLaunchConfig_t cfg = {};
        cfg.gridDim = dim3(B_ * NG_); cfg.blockDim = dim3(512);
        cfg.dynamicSmemBytes = GN_SMEM; cfg.attrs = pdl; cfg.numAttrs = 1;
        cudaLaunchKernelEx(&cfg, gn_t_kernel, x, gamma, beta, wq, wk, wv, wp);
    }

    // 2) fused q_t / k_t / v
    {
        cudaLaunchConfig_t cfg = {};
        cfg.gridDim = dim3(32, 1, 48); cfg.blockDim = dim3(256);
        cfg.dynamicSmemBytes = SMEM_BYTES; cfg.attrs = pdl; cfg.numAttrs = 1;
        cudaLaunchKernelEx(&cfg, qkv_gemm, bq, bk, bv);
    }

    // 3) at = exp(scale * qt . kt) + atomic rowsums
    {
        cudaLaunchConfig_t cfg = {};
        cfg.gridDim = dim3(HW_ / 128, HW_ / 128, B_); cfg.blockDim = dim3(256);
        cfg.dynamicSmemBytes = SMEM_BYTES; cfg.attrs = pdl; cfg.numAttrs = 1;
        cudaLaunchKernelEx(&cfg, bf_gemm<0, false, true, true, false>,
                           (const __nv_bfloat16*)qt, (const __nv_bfloat16*)kt,
                           (void*)at, (const float*)nullptr, (const float*)nullptr,
                           (const float*)nullptr, rsum,
                           C_, C_, C_, HW_, scale, sSC, sSC, sHH, (long long)HW_);
    }

    // 4) ot = (at . v) / rowsum
    {
        cudaLaunchConfig_t cfg = {};
        cfg.gridDim = dim3(C_ / 128, HW_ / 128, B_); cfg.blockDim = dim3(256);
        cfg.dynamicSmemBytes = SMEM_BYTES; cfg.attrs = pdl; cfg.numAttrs = 1;
        cudaLaunchKernelEx(&cfg, bf_gemm<0, false, true, false, true>,
                           (const __nv_bfloat16*)at, (const __nv_bfloat16*)v,
                           (void*)ot, (const float*)nullptr, (const float*)nullptr,
                           (const float*)rsum, (float*)nullptr,
                           HW_, HW_, HW_, C_, 1.0f, sHH, sSC, sSC, (long long)HW_);
    }

    // 5) out = wp . ot + bp + x
    {
        cudaLaunchConfig_t cfg = {};
        cfg.gridDim = dim3(HW_ / 128, C_ / 128, B_); cfg.blockDim = dim3(256);
        cfg.dynamicSmemBytes = SMEM_BYTES; cfg.attrs = pdl; cfg.numAttrs = 1;
        cudaLaunchKernelEx(&cfg, bf_gemm<1, true, false, false, false>,
                           (const __nv_bfloat16*)bwp, (const __nv_bfloat16*)ot,
                           (void*)out, bp, x,
                           (const float*)nullptr, (float*)nullptr,
                           C_, C_, C_, HW_, 1.0f, 0LL, sSC, sSC, 0LL);
    }
}